// round 9
// baseline (speedup 1.0000x reference)
#include <cuda_runtime.h>
#include <cuda_bf16.h>
#include <cstdint>
#include <cmath>

// ---------------------------------------------------------------------------
// Problem constants (fixed shapes)
// ---------------------------------------------------------------------------
#define BB 2
#define TT 2048
#define NE 2048          // N_EMBED
#define NH 16            // N_HEAD
#define NKV 4            // N_KV_HEAD
#define HD 128           // HEAD_DIM
#define MROWS (BB*TT)    // 4096
#define KVDIM (NKV*HD)   // 512
#define NQKV (NE + 2*KVDIM)   // 3072

// ---------------------------------------------------------------------------
// Scratch (static device globals; no allocations allowed)
// ---------------------------------------------------------------------------
__device__ __nv_bfloat16 g_qr[(size_t)BB * NH * TT * HD];   // rope(q) bf16 [B,H,T,D]
__device__ __nv_bfloat16 g_kr[(size_t)BB * NKV * TT * HD];  // rope(k) bf16 [B,KV,T,D]
__device__ __nv_bfloat16 g_vh[(size_t)BB * NKV * TT * HD];  // v hi bf16 [B,KV,T,D]
__device__ __nv_bfloat16 g_vl[(size_t)BB * NKV * TT * HD];  // v lo bf16 [B,KV,T,D]
__device__ float g_cos[TT * (HD/2)];
__device__ float g_sin[TT * (HD/2)];

// split-bf16 operands for tensor-core GEMMs
__device__ __nv_bfloat16 g_xh[(size_t)MROWS * NE];
__device__ __nv_bfloat16 g_xl[(size_t)MROWS * NE];
__device__ __nv_bfloat16 g_oh[(size_t)MROWS * NE];   // attn out hi
__device__ __nv_bfloat16 g_ol[(size_t)MROWS * NE];   // attn out lo
// packed transposed weights [N][K] hi/lo: rows 0..2047 Wq^T, 2048..2559 Wk^T, 2560..3071 Wv^T
__device__ __nv_bfloat16 g_wqkvh[(size_t)NQKV * NE];
__device__ __nv_bfloat16 g_wqkvl[(size_t)NQKV * NE];
__device__ __nv_bfloat16 g_woh[(size_t)NE * NE];
__device__ __nv_bfloat16 g_wol[(size_t)NE * NE];

// ---------------------------------------------------------------------------
// Helpers (baseline PTX only — no sm_103a-suffixed features)
// ---------------------------------------------------------------------------
__device__ __forceinline__ uint32_t smem_u32(const void* p) {
    uint32_t a;
    asm("{ .reg .u64 t; cvta.to.shared.u64 t, %1; cvt.u32.u64 %0, t; }" : "=r"(a) : "l"(p));
    return a;
}
__device__ __forceinline__ uint32_t sw128(uint32_t off) {
    return off ^ ((off >> 3) & 0x70);
}
__device__ __forceinline__ void cp16(uint32_t dst, const void* src) {
    asm volatile("cp.async.cg.shared.global [%0], [%1], 16;" :: "r"(dst), "l"(src) : "memory");
}
__device__ __forceinline__ void ldsm4(uint32_t* r, uint32_t addr) {
    asm volatile("ldmatrix.sync.aligned.m8n8.x4.shared.b16 {%0,%1,%2,%3}, [%4];"
                 : "=r"(r[0]), "=r"(r[1]), "=r"(r[2]), "=r"(r[3]) : "r"(addr));
}
__device__ __forceinline__ void ldsm4t(uint32_t* r, uint32_t addr) {
    asm volatile("ldmatrix.sync.aligned.m8n8.x4.trans.shared.b16 {%0,%1,%2,%3}, [%4];"
                 : "=r"(r[0]), "=r"(r[1]), "=r"(r[2]), "=r"(r[3]) : "r"(addr));
}
__device__ __forceinline__ void mma16816(float* c, const uint32_t* a, const uint32_t* b) {
    asm volatile(
        "mma.sync.aligned.m16n8k16.row.col.f32.bf16.bf16.f32 "
        "{%0,%1,%2,%3}, {%4,%5,%6,%7}, {%8,%9}, {%0,%1,%2,%3};"
        : "+f"(c[0]), "+f"(c[1]), "+f"(c[2]), "+f"(c[3])
        : "r"(a[0]), "r"(a[1]), "r"(a[2]), "r"(a[3]), "r"(b[0]), "r"(b[1]));
}
__device__ __forceinline__ uint32_t packbf2(__nv_bfloat16 lo, __nv_bfloat16 hi) {
    return ((uint32_t)__bfloat16_as_ushort(hi) << 16) | (uint32_t)__bfloat16_as_ushort(lo);
}

// ---------------------------------------------------------------------------
// Prep kernels
// ---------------------------------------------------------------------------
__global__ void __launch_bounds__(256)
split_kernel(const float* __restrict__ x, __nv_bfloat16* __restrict__ xh,
             __nv_bfloat16* __restrict__ xl, int n8)
{
    int i = blockIdx.x * 256 + threadIdx.x;
    if (i >= n8) return;
    size_t base = (size_t)i * 8;
    float4 v0 = *(const float4*)(x + base);
    float4 v1 = *(const float4*)(x + base + 4);
    float vv[8] = {v0.x, v0.y, v0.z, v0.w, v1.x, v1.y, v1.z, v1.w};
    union { __nv_bfloat16 b[8]; uint4 u; } ph, pl;
    #pragma unroll
    for (int j = 0; j < 8; j++) {
        __nv_bfloat16 h = __float2bfloat16(vv[j]);
        ph.b[j] = h;
        pl.b[j] = __float2bfloat16(vv[j] - __bfloat162float(h));
    }
    *(uint4*)(xh + base) = ph.u;
    *(uint4*)(xl + base) = pl.u;
}

// All four weight transposes fused: W[K][N] row-major -> T[N][K] hi/lo bf16
__global__ void __launch_bounds__(256)
tsplit_all_kernel(const float* __restrict__ Wq, const float* __restrict__ Wk,
                  const float* __restrict__ Wv, const float* __restrict__ Wo,
                  __nv_bfloat16* __restrict__ wqkvh, __nv_bfloat16* __restrict__ wqkvl,
                  __nv_bfloat16* __restrict__ woh, __nv_bfloat16* __restrict__ wol)
{
    __shared__ float t[32][33];
    int id = blockIdx.x;
    const float* W;
    __nv_bfloat16 *Th, *Tl;
    int N;
    if (id < 4096)      { W = Wq; Th = wqkvh;                            Tl = wqkvl;                            N = NE;    }
    else if (id < 5120) { W = Wk; Th = wqkvh + (size_t)NE * NE;          Tl = wqkvl + (size_t)NE * NE;          N = KVDIM; id -= 4096; }
    else if (id < 6144) { W = Wv; Th = wqkvh + (size_t)(NE + KVDIM) * NE; Tl = wqkvl + (size_t)(NE + KVDIM) * NE; N = KVDIM; id -= 5120; }
    else                { W = Wo; Th = woh;                              Tl = wol;                              N = NE;    id -= 6144; }
    const int ntiles = N / 32;
    const int n0 = (id % ntiles) * 32;
    const int k0 = (id / ntiles) * 32;
    const int tx = threadIdx.x & 31, ty = threadIdx.x >> 5;   // 32x8
    #pragma unroll
    for (int i = 0; i < 4; i++)
        t[ty + i * 8][tx] = W[(size_t)(k0 + ty + i * 8) * N + n0 + tx];
    __syncthreads();
    #pragma unroll
    for (int i = 0; i < 4; i++) {
        int n = n0 + ty + i * 8, k = k0 + tx;
        float v = t[tx][ty + i * 8];
        __nv_bfloat16 h = __float2bfloat16(v);
        Th[(size_t)n * NE + k] = h;
        Tl[(size_t)n * NE + k] = __float2bfloat16(v - __bfloat162float(h));
    }
}

// RoPE table: angle = fp32(t) * fp32(double-precision freq)
__global__ void __launch_bounds__(256)
rope_table_kernel(float* __restrict__ ct, float* __restrict__ st)
{
    int idx = blockIdx.x * 256 + threadIdx.x;
    if (idx >= TT * (HD/2)) return;
    int t = idx >> 6;
    int i = idx & 63;
    double fr = exp(-((double)(2 * i) / (double)NE) * log(10000.0));
    float ff = (float)fr;
    float ang = __fmul_rn((float)t, ff);
    float s, c;
    sincosf(ang, &s, &c);
    ct[idx] = c;
    st[idx] = s;
}

// ---------------------------------------------------------------------------
// GEMM core: split-bf16 C = Ah@Bh^T + Ah@Bl^T + Al@Bh^T
// BM=256, BN=128, BK=64, 256 threads (4m x 2n warps, warp tile 64x64),
// 2-stage cp.async pipeline. TERM-MAJOR MMA ordering (RAW distance 32).
// Stage layout: Ah@0(32K) | Al@32K | Bh@64K(16K) | Bl@80K  (rows 128B, SW128)
// ---------------------------------------------------------------------------
#define STG_BYTES 98304
#define GEMM_SMEM (2*STG_BYTES + 1024)

__device__ __forceinline__ void gemm_core(
    const __nv_bfloat16* __restrict__ Ah, const __nv_bfloat16* __restrict__ Al,
    const __nv_bfloat16* __restrict__ BTh, const __nv_bfloat16* __restrict__ BTl,
    int K, int m0, int n0, uint32_t sb, int tid, float c[4][8][4])
{
    const int lane = tid & 31;
    const int wm   = (tid >> 5) >> 1;   // 0..3 (64 rows each)
    const int wn   = (tid >> 5) & 1;    // 0..1 (64 cols each)
    const int nstage = K / 64;

    #pragma unroll
    for (int im = 0; im < 4; im++)
        #pragma unroll
        for (int in = 0; in < 8; in++)
            #pragma unroll
            for (int j = 0; j < 4; j++) c[im][in][j] = 0.f;

    auto load_stage = [&](int s) {
        const int k0 = s * 64;
        const uint32_t stg = sb + (uint32_t)(s & 1) * STG_BYTES;
        #pragma unroll
        for (int i = 0; i < 24; i++) {
            int idx = tid + (i << 8);           // 0..6143
            if (idx < 4096) {
                int mat = idx >> 11;
                int row = (idx >> 3) & 255;
                int q   = idx & 7;
                const __nv_bfloat16* src =
                    (mat ? Al : Ah) + (size_t)(m0 + row) * K + k0 + q * 8;
                cp16(stg + mat * 32768 + sw128((uint32_t)(row * 128 + q * 16)), src);
            } else {
                int rel = idx - 4096;
                int mat = rel >> 10;
                int row = (rel >> 3) & 127;
                int q   = rel & 7;
                const __nv_bfloat16* src =
                    (mat ? BTl : BTh) + (size_t)(n0 + row) * K + k0 + q * 8;
                cp16(stg + 65536 + mat * 16384 + sw128((uint32_t)(row * 128 + q * 16)), src);
            }
        }
    };

    load_stage(0);
    asm volatile("cp.async.commit_group;" ::: "memory");

    const int aRow  = (lane & 15);
    const int aKoff = (lane >> 4) << 4;
    const int bRow  = (lane & 7) + ((lane >> 4) << 3);
    const int bKoff = ((lane >> 3) & 1) << 4;

    for (int s = 0; s < nstage; s++) {
        if (s + 1 < nstage) {
            load_stage(s + 1);
            asm volatile("cp.async.commit_group;" ::: "memory");
            asm volatile("cp.async.wait_group 1;" ::: "memory");
        } else {
            asm volatile("cp.async.wait_group 0;" ::: "memory");
        }
        __syncthreads();

        const uint32_t ab = sb + (uint32_t)(s & 1) * STG_BYTES;

        #pragma unroll
        for (int kk = 0; kk < 4; kk++) {
            const int kb = kk * 32;
            uint32_t a_h[4][4], a_l[4][4];
            #pragma unroll
            for (int im = 0; im < 4; im++) {
                uint32_t off = sw128((uint32_t)((wm * 64 + im * 16 + aRow) * 128 + kb + aKoff));
                ldsm4(a_h[im], ab + off);
                ldsm4(a_l[im], ab + 32768 + off);
            }
            uint32_t b_h[16], b_l[16];
            #pragma unroll
            for (int ib = 0; ib < 4; ib++) {
                uint32_t off = sw128((uint32_t)((wn * 64 + ib * 16 + bRow) * 128 + kb + bKoff));
                ldsm4(&b_h[ib * 4], ab + 65536 + off);
                ldsm4(&b_l[ib * 4], ab + 81920 + off);
            }
            // term-major: all Ah*Bh, then all Al*Bh, then all Ah*Bl.
            // Per-accumulator order preserved -> numerics identical; RAW distance 32.
            #pragma unroll
            for (int im = 0; im < 4; im++)
                #pragma unroll
                for (int in = 0; in < 8; in++)
                    mma16816(c[im][in], a_h[im], &b_h[(in >> 1) * 4 + (in & 1) * 2]);
            #pragma unroll
            for (int im = 0; im < 4; im++)
                #pragma unroll
                for (int in = 0; in < 8; in++)
                    mma16816(c[im][in], a_l[im], &b_h[(in >> 1) * 4 + (in & 1) * 2]);
            #pragma unroll
            for (int im = 0; im < 4; im++)
                #pragma unroll
                for (int in = 0; in < 8; in++)
                    mma16816(c[im][in], a_h[im], &b_l[(in >> 1) * 4 + (in & 1) * 2]);
        }
        __syncthreads();
    }
}

// ---------------------------------------------------------------------------
// QKV GEMM: fused projections with RoPE / v-split epilogue.
// N = 3072 columns: [0,2048) Q, [2048,2560) K, [2560,3072) V.
// ---------------------------------------------------------------------------
__global__ void __launch_bounds__(256, 1)
gemm_qkv_kernel(const __nv_bfloat16* __restrict__ Ah, const __nv_bfloat16* __restrict__ Al,
                const __nv_bfloat16* __restrict__ BTh, const __nv_bfloat16* __restrict__ BTl,
                const float* __restrict__ bq, const float* __restrict__ bk,
                const float* __restrict__ bv,
                const float* __restrict__ ct, const float* __restrict__ st,
                __nv_bfloat16* __restrict__ qr, __nv_bfloat16* __restrict__ kr,
                __nv_bfloat16* __restrict__ vh, __nv_bfloat16* __restrict__ vl)
{
    extern __shared__ char dsm[];
    char* smbase = (char*)(((uintptr_t)dsm + 1023) & ~(uintptr_t)1023);
    const uint32_t sb = smem_u32(smbase);
    const int tid  = threadIdx.x;
    const int lane = tid & 31;
    const int wm   = (tid >> 5) >> 1;
    const int wn   = (tid >> 5) & 1;
    const int m0   = blockIdx.y * 256;
    const int n0   = blockIdx.x * 128;

    float c[4][8][4];
    gemm_core(Ah, Al, BTh, BTl, NE, m0, n0, sb, tid, c);

    const int region = (n0 >= NE + KVDIM) ? 2 : (n0 >= NE ? 1 : 0);

    #pragma unroll
    for (int im = 0; im < 4; im++) {
        const int r0 = m0 + wm * 64 + im * 16 + (lane >> 2);
        const int b  = r0 >> 11;
        const int t  = r0 & 2047;
        #pragma unroll
        for (int in = 0; in < 8; in++) {
            const int cc = n0 + wn * 64 + in * 8 + ((lane & 3) << 1);
            float b0, b1;
            if (region == 0)      { b0 = bq[cc];          b1 = bq[cc + 1]; }
            else if (region == 1) { b0 = bk[cc - NE];     b1 = bk[cc - NE + 1]; }
            else                  { b0 = bv[cc - NE - KVDIM]; b1 = bv[cc - NE - KVDIM + 1]; }
            float v0 = c[im][in][0] + b0, v1 = c[im][in][1] + b1;   // row t
            float v2 = c[im][in][2] + b0, v3 = c[im][in][3] + b1;   // row t+8
            const int dloc = cc & 127;
            if (region <= 1) {
                const int i  = dloc >> 1;
                float c0 = ct[t * 64 + i],       s0 = st[t * 64 + i];
                float c2 = ct[(t + 8) * 64 + i], s2 = st[(t + 8) * 64 + i];
                uint32_t p0 = packbf2(__float2bfloat16(v0 * c0 - v1 * s0),
                                      __float2bfloat16(v0 * s0 + v1 * c0));
                uint32_t p2 = packbf2(__float2bfloat16(v2 * c2 - v3 * s2),
                                      __float2bfloat16(v2 * s2 + v3 * c2));
                if (region == 0) {
                    const int h = cc >> 7;
                    size_t dst = ((size_t)((b * NH + h) * TT + t)) * HD + dloc;
                    *(uint32_t*)(qr + dst)          = p0;
                    *(uint32_t*)(qr + dst + 8 * HD) = p2;
                } else {
                    const int h = (cc - NE) >> 7;
                    size_t dst = ((size_t)((b * NKV + h) * TT + t)) * HD + dloc;
                    *(uint32_t*)(kr + dst)          = p0;
                    *(uint32_t*)(kr + dst + 8 * HD) = p2;
                }
            } else {
                const int h = (cc - NE - KVDIM) >> 7;
                size_t dst = ((size_t)((b * NKV + h) * TT + t)) * HD + dloc;
                __nv_bfloat16 h0 = __float2bfloat16(v0);
                __nv_bfloat16 h1 = __float2bfloat16(v1);
                __nv_bfloat16 h2 = __float2bfloat16(v2);
                __nv_bfloat16 h3 = __float2bfloat16(v3);
                *(uint32_t*)(vh + dst) = packbf2(h0, h1);
                *(uint32_t*)(vl + dst) = packbf2(__float2bfloat16(v0 - __bfloat162float(h0)),
                                                 __float2bfloat16(v1 - __bfloat162float(h1)));
                *(uint32_t*)(vh + dst + 8 * HD) = packbf2(h2, h3);
                *(uint32_t*)(vl + dst + 8 * HD) = packbf2(__float2bfloat16(v2 - __bfloat162float(h2)),
                                                          __float2bfloat16(v3 - __bfloat162float(h3)));
            }
        }
    }
}

// ---------------------------------------------------------------------------
// Output projection GEMM: plain bias epilogue -> fp32 out
// ---------------------------------------------------------------------------
__global__ void __launch_bounds__(256, 1)
gemm_out_kernel(const __nv_bfloat16* __restrict__ Ah, const __nv_bfloat16* __restrict__ Al,
                const __nv_bfloat16* __restrict__ BTh, const __nv_bfloat16* __restrict__ BTl,
                const float* __restrict__ bias, float* __restrict__ C)
{
    extern __shared__ char dsm[];
    char* smbase = (char*)(((uintptr_t)dsm + 1023) & ~(uintptr_t)1023);
    const uint32_t sb = smem_u32(smbase);
    const int tid  = threadIdx.x;
    const int lane = tid & 31;
    const int wm   = (tid >> 5) >> 1;
    const int wn   = (tid >> 5) & 1;
    const int m0   = blockIdx.y * 256;
    const int n0   = blockIdx.x * 128;

    float c[4][8][4];
    gemm_core(Ah, Al, BTh, BTl, NE, m0, n0, sb, tid, c);

    #pragma unroll
    for (int im = 0; im < 4; im++) {
        const int r0 = m0 + wm * 64 + im * 16 + (lane >> 2);
        #pragma unroll
        for (int in = 0; in < 8; in++) {
            const int cc = n0 + wn * 64 + in * 8 + ((lane & 3) << 1);
            float2 bb = *(const float2*)&bias[cc];
            float2 o0, o1;
            o0.x = c[im][in][0] + bb.x;  o0.y = c[im][in][1] + bb.y;
            o1.x = c[im][in][2] + bb.x;  o1.y = c[im][in][3] + bb.y;
            *(float2*)&C[(size_t)r0 * NE + cc]       = o0;
            *(float2*)&C[(size_t)(r0 + 8) * NE + cc] = o1;
        }
    }
}

// ---------------------------------------------------------------------------
// Flash attention (causal, GQA) on mma.sync. BM=128, BN=64, 256 threads/8 warps.
// Epilogue writes split-bf16 oh/ol directly (feeds O-projection GEMM).
// smem: Q(128 rows) | {K,Vh,Vl} x 2 buffers (64 rows each), rows 272B.
// ---------------------------------------------------------------------------
#define AT_RS 272
#define AT_T64 (64 * AT_RS)
#define AT_QSZ (128 * AT_RS)
#define ATT_SMEM (AT_QSZ + 6 * AT_T64 + 1024)

__global__ void __launch_bounds__(256, 1)
attn_mma_kernel(const __nv_bfloat16* __restrict__ qr, const __nv_bfloat16* __restrict__ kr,
                const __nv_bfloat16* __restrict__ vh, const __nv_bfloat16* __restrict__ vl,
                __nv_bfloat16* __restrict__ oh, __nv_bfloat16* __restrict__ ol)
{
    extern __shared__ char dsm2[];
    char* smb = (char*)(((uintptr_t)dsm2 + 1023) & ~(uintptr_t)1023);
    const uint32_t sb = smem_u32(smb);

    const int tid  = threadIdx.x;
    const int lane = tid & 31;
    const int w    = tid >> 5;                              // 0..7
    const int mtb  = (int)gridDim.x - 1 - (int)blockIdx.x;  // heavy blocks first
    const int h    = blockIdx.y, b = blockIdx.z;
    const int m0   = mtb * 128;
    const int kv   = h >> 2;
    const int ntile = 2 * mtb + 2;

    const __nv_bfloat16* qg  = qr + ((size_t)(b * NH + h) * TT + m0) * HD;
    const __nv_bfloat16* kg  = kr + ((size_t)(b * NKV + kv) * TT) * HD;
    const __nv_bfloat16* vhg = vh + ((size_t)(b * NKV + kv) * TT) * HD;
    const __nv_bfloat16* vlg = vl + ((size_t)(b * NKV + kv) * TT) * HD;

    const uint32_t Q0 = sb;
    auto toff = [&](int buf, int which) -> uint32_t {
        return sb + AT_QSZ + (uint32_t)AT_T64 * (buf * 3 + which);
    };
    auto load64 = [&](uint32_t dst, const __nv_bfloat16* src) {
        #pragma unroll
        for (int i = 0; i < 4; i++) {
            int idx = tid + i * 256;
            int row = idx >> 4, cq = idx & 15;
            cp16(dst + (uint32_t)(row * AT_RS + cq * 16), src + (size_t)row * HD + cq * 8);
        }
    };

    // Q: 128 rows
    #pragma unroll
    for (int i = 0; i < 8; i++) {
        int idx = tid + i * 256;
        int row = idx >> 4, cq = idx & 15;
        cp16(Q0 + (uint32_t)(row * AT_RS + cq * 16), qg + (size_t)row * HD + cq * 8);
    }
    load64(toff(0, 0), kg);
    load64(toff(0, 1), vhg);
    load64(toff(0, 2), vlg);
    asm volatile("cp.async.commit_group;" ::: "memory");

    uint32_t qf[8][4];
    float ov[16][4];
    #pragma unroll
    for (int n = 0; n < 16; n++) { ov[n][0] = ov[n][1] = ov[n][2] = ov[n][3] = 0.f; }
    float m_lo = -1e30f, m_hi = -1e30f, l_lo = 0.f, l_hi = 0.f;

    const int aRow = lane & 15;
    const int aK   = (lane >> 4) << 4;
    const int bRow = (lane & 7) + ((lane >> 4) << 3);
    const int bK   = ((lane >> 3) & 1) << 4;
    const int vRow = (lane & 7) + (((lane >> 3) & 1) << 3);
    const int vC   = (lane >> 4) << 4;

    for (int jt = 0; jt < ntile; jt++) {
        if (jt + 1 < ntile) {
            int nb = (jt + 1) & 1;
            load64(toff(nb, 0), kg  + (size_t)(jt + 1) * 64 * HD);
            load64(toff(nb, 1), vhg + (size_t)(jt + 1) * 64 * HD);
            load64(toff(nb, 2), vlg + (size_t)(jt + 1) * 64 * HD);
            asm volatile("cp.async.commit_group;" ::: "memory");
            asm volatile("cp.async.wait_group 1;" ::: "memory");
        } else {
            asm volatile("cp.async.wait_group 0;" ::: "memory");
        }
        __syncthreads();

        if (jt == 0) {
            #pragma unroll
            for (int kt = 0; kt < 8; kt++)
                ldsm4(qf[kt], Q0 + (uint32_t)((w * 16 + aRow) * AT_RS + kt * 32 + aK));
        }

        const uint32_t kb  = toff(jt & 1, 0);
        const uint32_t vhb = toff(jt & 1, 1);
        const uint32_t vlb = toff(jt & 1, 2);

        // ---- S = Q @ K^T ----
        float sc[8][4];
        #pragma unroll
        for (int j = 0; j < 8; j++) { sc[j][0] = sc[j][1] = sc[j][2] = sc[j][3] = 0.f; }

        #pragma unroll
        for (int kt = 0; kt < 8; kt++) {
            #pragma unroll
            for (int ib = 0; ib < 4; ib++) {
                uint32_t bf[4];
                ldsm4(bf, kb + (uint32_t)((ib * 16 + bRow) * AT_RS + kt * 32 + bK));
                mma16816(sc[2 * ib],     qf[kt], bf);
                mma16816(sc[2 * ib + 1], qf[kt], bf + 2);
            }
        }

        // ---- causal mask (last two tiles only) ----
        if (jt >= ntile - 2) {
            const int rl = m0 + w * 16 + (lane >> 2);
            #pragma unroll
            for (int j = 0; j < 8; j++) {
                int gn = jt * 64 + j * 8 + ((lane & 3) << 1);
                if (gn     > rl)     sc[j][0] = -1e30f;
                if (gn + 1 > rl)     sc[j][1] = -1e30f;
                if (gn     > rl + 8) sc[j][2] = -1e30f;
                if (gn + 1 > rl + 8) sc[j][3] = -1e30f;
            }
        }

        // ---- online softmax ----
        float vlo = -1e30f, vhi = -1e30f;
        #pragma unroll
        for (int j = 0; j < 8; j++) {
            vlo = fmaxf(vlo, fmaxf(sc[j][0], sc[j][1]));
            vhi = fmaxf(vhi, fmaxf(sc[j][2], sc[j][3]));
        }
        vlo = fmaxf(vlo, __shfl_xor_sync(0xffffffffu, vlo, 1));
        vlo = fmaxf(vlo, __shfl_xor_sync(0xffffffffu, vlo, 2));
        vhi = fmaxf(vhi, __shfl_xor_sync(0xffffffffu, vhi, 1));
        vhi = fmaxf(vhi, __shfl_xor_sync(0xffffffffu, vhi, 2));
        float mn_lo = fmaxf(m_lo, vlo), mn_hi = fmaxf(m_hi, vhi);
        float al_lo = __expf(m_lo - mn_lo), al_hi = __expf(m_hi - mn_hi);
        m_lo = mn_lo; m_hi = mn_hi;
        l_lo *= al_lo; l_hi *= al_hi;
        #pragma unroll
        for (int n = 0; n < 16; n++) {
            ov[n][0] *= al_lo; ov[n][1] *= al_lo;
            ov[n][2] *= al_hi; ov[n][3] *= al_hi;
        }

        uint32_t ph[8][2], pl[8][2];
        #pragma unroll
        for (int j = 0; j < 8; j++) {
            float p0 = __expf(sc[j][0] - m_lo), p1 = __expf(sc[j][1] - m_lo);
            float p2 = __expf(sc[j][2] - m_hi), p3 = __expf(sc[j][3] - m_hi);
            l_lo += p0 + p1;  l_hi += p2 + p3;
            __nv_bfloat16 h0 = __float2bfloat16(p0), h1 = __float2bfloat16(p1);
            __nv_bfloat16 h2 = __float2bfloat16(p2), h3 = __float2bfloat16(p3);
            ph[j][0] = packbf2(h0, h1);
            ph[j][1] = packbf2(h2, h3);
            pl[j][0] = packbf2(__float2bfloat16(p0 - __bfloat162float(h0)),
                               __float2bfloat16(p1 - __bfloat162float(h1)));
            pl[j][1] = packbf2(__float2bfloat16(p2 - __bfloat162float(h2)),
                               __float2bfloat16(p3 - __bfloat162float(h3)));
        }

        // ---- O += P @ V  (3-term split) ----
        #pragma unroll
        for (int kt = 0; kt < 4; kt++) {
            uint32_t ah[4] = { ph[2*kt][0], ph[2*kt][1], ph[2*kt+1][0], ph[2*kt+1][1] };
            uint32_t am[4] = { pl[2*kt][0], pl[2*kt][1], pl[2*kt+1][0], pl[2*kt+1][1] };
            #pragma unroll
            for (int np = 0; np < 4; np++) {
                uint32_t base = (uint32_t)((kt * 16 + vRow) * AT_RS + np * 64 + vC);
                uint32_t bh0[4], bh1[4], bl0[4], bl1[4];
                ldsm4t(bh0, vhb + base);
                ldsm4t(bh1, vhb + base + 32);
                ldsm4t(bl0, vlb + base);
                ldsm4t(bl1, vlb + base + 32);
                mma16816(ov[np*4+0], ah, bh0);
                mma16816(ov[np*4+1], ah, bh0 + 2);
                mma16816(ov[np*4+2], ah, bh1);
                mma16816(ov[np*4+3], ah, bh1 + 2);
                mma16816(ov[np*4+0], am, bh0);
                mma16816(ov[np*4+1], am, bh0 + 2);
                mma16816(ov[np*4+2], am, bh1);
                mma16816(ov[np*4+3], am, bh1 + 2);
                mma16816(ov[np*4+0], ah, bl0);
                mma16816(ov[np*4+1], ah, bl0 + 2);
                mma16816(ov[np*4+2], ah, bl1);
                mma16816(ov[np*4+3], ah, bl1 + 2);
            }
        }
        __syncthreads();
    }

    // ---- epilogue: normalize, split-bf16, write oh/ol ----
    l_lo += __shfl_xor_sync(0xffffffffu, l_lo, 1);
    l_lo += __shfl_xor_sync(0xffffffffu, l_lo, 2);
    l_hi += __shfl_xor_sync(0xffffffffu, l_hi, 1);
    l_hi += __shfl_xor_sync(0xffffffffu, l_hi, 2);
    const float inv_lo = 0.022097086912079608f / l_lo;
    const float inv_hi = 0.022097086912079608f / l_hi;
    const int rlo = m0 + w * 16 + (lane >> 2);
    size_t base = ((size_t)(b * TT) + rlo) * NE + h * HD;
    #pragma unroll
    for (int n = 0; n < 16; n++) {
        int d = n * 8 + ((lane & 3) << 1);
        float o0 = ov[n][0] * inv_lo, o1 = ov[n][1] * inv_lo;
        float o2 = ov[n][2] * inv_hi, o3 = ov[n][3] * inv_hi;
        __nv_bfloat16 h0 = __float2bfloat16(o0), h1 = __float2bfloat16(o1);
        __nv_bfloat16 h2 = __float2bfloat16(o2), h3 = __float2bfloat16(o3);
        *(uint32_t*)(oh + base + d) = packbf2(h0, h1);
        *(uint32_t*)(ol + base + d) = packbf2(__float2bfloat16(o0 - __bfloat162float(h0)),
                                              __float2bfloat16(o1 - __bfloat162float(h1)));
        *(uint32_t*)(oh + base + 8 * NE + d) = packbf2(h2, h3);
        *(uint32_t*)(ol + base + 8 * NE + d) = packbf2(__float2bfloat16(o2 - __bfloat162float(h2)),
                                                       __float2bfloat16(o3 - __bfloat162float(h3)));
    }
}

// ---------------------------------------------------------------------------
// launch
// ---------------------------------------------------------------------------
extern "C" void kernel_launch(void* const* d_in, const int* in_sizes, int n_in,
                              void* d_out, int out_size)
{
    const float* x  = (const float*)d_in[0];
    const float* Wq = (const float*)d_in[1];
    const float* bq = (const float*)d_in[2];
    const float* Wk = (const float*)d_in[3];
    const float* bk = (const float*)d_in[4];
    const float* Wv = (const float*)d_in[5];
    const float* bv = (const float*)d_in[6];
    const float* Wo = (const float*)d_in[7];
    const float* bo = (const float*)d_in[8];
    float* out = (float*)d_out;

    float *ct, *st;
    __nv_bfloat16 *qr, *kr, *vhp, *vlp;
    __nv_bfloat16 *xh, *xl, *oh, *ol;
    __nv_bfloat16 *wqkvh, *wqkvl, *woh, *wol;
    cudaGetSymbolAddress((void**)&ct, g_cos);
    cudaGetSymbolAddress((void**)&st, g_sin);
    cudaGetSymbolAddress((void**)&qr, g_qr);
    cudaGetSymbolAddress((void**)&kr, g_kr);
    cudaGetSymbolAddress((void**)&vhp, g_vh);
    cudaGetSymbolAddress((void**)&vlp, g_vl);
    cudaGetSymbolAddress((void**)&xh, g_xh);
    cudaGetSymbolAddress((void**)&xl, g_xl);
    cudaGetSymbolAddress((void**)&oh, g_oh);
    cudaGetSymbolAddress((void**)&ol, g_ol);
    cudaGetSymbolAddress((void**)&wqkvh, g_wqkvh);
    cudaGetSymbolAddress((void**)&wqkvl, g_wqkvl);
    cudaGetSymbolAddress((void**)&woh, g_woh);
    cudaGetSymbolAddress((void**)&wol, g_wol);

    cudaFuncSetAttribute(gemm_qkv_kernel, cudaFuncAttributeMaxDynamicSharedMemorySize, GEMM_SMEM);
    cudaFuncSetAttribute(gemm_out_kernel, cudaFuncAttributeMaxDynamicSharedMemorySize, GEMM_SMEM);
    cudaFuncSetAttribute(attn_mma_kernel, cudaFuncAttributeMaxDynamicSharedMemorySize, ATT_SMEM);

    // prep (3 launches)
    tsplit_all_kernel<<<10240, 256>>>(Wq, Wk, Wv, Wo, wqkvh, wqkvl, woh, wol);
    split_kernel<<<(MROWS * NE / 8 + 255) / 256, 256>>>(x, xh, xl, MROWS * NE / 8);
    rope_table_kernel<<<(TT * 64 + 255) / 256, 256>>>(ct, st);

    // fused QKV projection (rope + v-split epilogue)
    gemm_qkv_kernel<<<dim3(NQKV / 128, MROWS / 256), 256, GEMM_SMEM>>>(
        xh, xl, wqkvh, wqkvl, bq, bk, bv, ct, st, qr, kr, vhp, vlp);

    // attention (writes split-bf16 oh/ol)
    {
        dim3 grid(TT / 128, NH, BB);
        attn_mma_kernel<<<grid, 256, ATT_SMEM>>>(qr, kr, vhp, vlp, oh, ol);
    }

    // output projection
    gemm_out_kernel<<<dim3(NE / 128, MROWS / 256), 256, GEMM_SMEM>>>(
        oh, ol, woh, wol, bo, out);
}

// round 10
// speedup vs baseline: 1.5697x; 1.5697x over previous
#include <cuda_runtime.h>
#include <cuda_bf16.h>
#include <cstdint>
#include <cmath>

// ---------------------------------------------------------------------------
// Problem constants (fixed shapes)
// ---------------------------------------------------------------------------
#define BB 2
#define TT 2048
#define NE 2048          // N_EMBED
#define NH 16            // N_HEAD
#define NKV 4            // N_KV_HEAD
#define HD 128           // HEAD_DIM
#define MROWS (BB*TT)    // 4096
#define KVDIM (NKV*HD)   // 512
#define NQKV (NE + 2*KVDIM)   // 3072

// ---------------------------------------------------------------------------
// Scratch (static device globals; no allocations allowed)
// ---------------------------------------------------------------------------
__device__ __nv_bfloat16 g_qr[(size_t)BB * NH * TT * HD];   // rope(q) bf16 [B,H,T,D]
__device__ __nv_bfloat16 g_kr[(size_t)BB * NKV * TT * HD];  // rope(k) bf16 [B,KV,T,D]
__device__ __nv_bfloat16 g_vh[(size_t)BB * NKV * TT * HD];  // v hi bf16 [B,KV,T,D]
__device__ __nv_bfloat16 g_vl[(size_t)BB * NKV * TT * HD];  // v lo bf16 [B,KV,T,D]
__device__ float g_cos[TT * (HD/2)];
__device__ float g_sin[TT * (HD/2)];

// split-bf16 operands for tensor-core GEMMs
__device__ __nv_bfloat16 g_xh[(size_t)MROWS * NE];
__device__ __nv_bfloat16 g_xl[(size_t)MROWS * NE];
__device__ __nv_bfloat16 g_oh[(size_t)MROWS * NE];   // attn out hi
__device__ __nv_bfloat16 g_ol[(size_t)MROWS * NE];   // attn out lo
// packed transposed weights [N][K] hi/lo: rows 0..2047 Wq^T, 2048..2559 Wk^T, 2560..3071 Wv^T
__device__ __nv_bfloat16 g_wqkvh[(size_t)NQKV * NE];
__device__ __nv_bfloat16 g_wqkvl[(size_t)NQKV * NE];
__device__ __nv_bfloat16 g_woh[(size_t)NE * NE];
__device__ __nv_bfloat16 g_wol[(size_t)NE * NE];

// ---------------------------------------------------------------------------
// Helpers (baseline PTX only — no sm_103a-suffixed features)
// ---------------------------------------------------------------------------
__device__ __forceinline__ uint32_t smem_u32(const void* p) {
    uint32_t a;
    asm("{ .reg .u64 t; cvta.to.shared.u64 t, %1; cvt.u32.u64 %0, t; }" : "=r"(a) : "l"(p));
    return a;
}
__device__ __forceinline__ uint32_t sw128(uint32_t off) {
    return off ^ ((off >> 3) & 0x70);
}
__device__ __forceinline__ void cp16(uint32_t dst, const void* src) {
    asm volatile("cp.async.cg.shared.global [%0], [%1], 16;" :: "r"(dst), "l"(src) : "memory");
}
__device__ __forceinline__ void ldsm4(uint32_t* r, uint32_t addr) {
    asm volatile("ldmatrix.sync.aligned.m8n8.x4.shared.b16 {%0,%1,%2,%3}, [%4];"
                 : "=r"(r[0]), "=r"(r[1]), "=r"(r[2]), "=r"(r[3]) : "r"(addr));
}
__device__ __forceinline__ void ldsm4t(uint32_t* r, uint32_t addr) {
    asm volatile("ldmatrix.sync.aligned.m8n8.x4.trans.shared.b16 {%0,%1,%2,%3}, [%4];"
                 : "=r"(r[0]), "=r"(r[1]), "=r"(r[2]), "=r"(r[3]) : "r"(addr));
}
__device__ __forceinline__ void mma16816(float* c, const uint32_t* a, const uint32_t* b) {
    asm volatile(
        "mma.sync.aligned.m16n8k16.row.col.f32.bf16.bf16.f32 "
        "{%0,%1,%2,%3}, {%4,%5,%6,%7}, {%8,%9}, {%0,%1,%2,%3};"
        : "+f"(c[0]), "+f"(c[1]), "+f"(c[2]), "+f"(c[3])
        : "r"(a[0]), "r"(a[1]), "r"(a[2]), "r"(a[3]), "r"(b[0]), "r"(b[1]));
}
__device__ __forceinline__ uint32_t packbf2(__nv_bfloat16 lo, __nv_bfloat16 hi) {
    return ((uint32_t)__bfloat16_as_ushort(hi) << 16) | (uint32_t)__bfloat16_as_ushort(lo);
}

// ---------------------------------------------------------------------------
// Prep kernels
// ---------------------------------------------------------------------------
__global__ void __launch_bounds__(256)
split_kernel(const float* __restrict__ x, __nv_bfloat16* __restrict__ xh,
             __nv_bfloat16* __restrict__ xl, int n8)
{
    int i = blockIdx.x * 256 + threadIdx.x;
    if (i >= n8) return;
    size_t base = (size_t)i * 8;
    float4 v0 = *(const float4*)(x + base);
    float4 v1 = *(const float4*)(x + base + 4);
    float vv[8] = {v0.x, v0.y, v0.z, v0.w, v1.x, v1.y, v1.z, v1.w};
    union { __nv_bfloat16 b[8]; uint4 u; } ph, pl;
    #pragma unroll
    for (int j = 0; j < 8; j++) {
        __nv_bfloat16 h = __float2bfloat16(vv[j]);
        ph.b[j] = h;
        pl.b[j] = __float2bfloat16(vv[j] - __bfloat162float(h));
    }
    *(uint4*)(xh + base) = ph.u;
    *(uint4*)(xl + base) = pl.u;
}

// All four weight transposes fused: W[K][N] row-major -> T[N][K] hi/lo bf16
__global__ void __launch_bounds__(256)
tsplit_all_kernel(const float* __restrict__ Wq, const float* __restrict__ Wk,
                  const float* __restrict__ Wv, const float* __restrict__ Wo,
                  __nv_bfloat16* __restrict__ wqkvh, __nv_bfloat16* __restrict__ wqkvl,
                  __nv_bfloat16* __restrict__ woh, __nv_bfloat16* __restrict__ wol)
{
    __shared__ float t[32][33];
    int id = blockIdx.x;
    const float* W;
    __nv_bfloat16 *Th, *Tl;
    int N;
    if (id < 4096)      { W = Wq; Th = wqkvh;                            Tl = wqkvl;                            N = NE;    }
    else if (id < 5120) { W = Wk; Th = wqkvh + (size_t)NE * NE;          Tl = wqkvl + (size_t)NE * NE;          N = KVDIM; id -= 4096; }
    else if (id < 6144) { W = Wv; Th = wqkvh + (size_t)(NE + KVDIM) * NE; Tl = wqkvl + (size_t)(NE + KVDIM) * NE; N = KVDIM; id -= 5120; }
    else                { W = Wo; Th = woh;                              Tl = wol;                              N = NE;    id -= 6144; }
    const int ntiles = N / 32;
    const int n0 = (id % ntiles) * 32;
    const int k0 = (id / ntiles) * 32;
    const int tx = threadIdx.x & 31, ty = threadIdx.x >> 5;   // 32x8
    #pragma unroll
    for (int i = 0; i < 4; i++)
        t[ty + i * 8][tx] = W[(size_t)(k0 + ty + i * 8) * N + n0 + tx];
    __syncthreads();
    #pragma unroll
    for (int i = 0; i < 4; i++) {
        int n = n0 + ty + i * 8, k = k0 + tx;
        float v = t[tx][ty + i * 8];
        __nv_bfloat16 h = __float2bfloat16(v);
        Th[(size_t)n * NE + k] = h;
        Tl[(size_t)n * NE + k] = __float2bfloat16(v - __bfloat162float(h));
    }
}

// RoPE table: angle = fp32(t) * fp32(double-precision freq)
__global__ void __launch_bounds__(256)
rope_table_kernel(float* __restrict__ ct, float* __restrict__ st)
{
    int idx = blockIdx.x * 256 + threadIdx.x;
    if (idx >= TT * (HD/2)) return;
    int t = idx >> 6;
    int i = idx & 63;
    double fr = exp(-((double)(2 * i) / (double)NE) * log(10000.0));
    float ff = (float)fr;
    float ang = __fmul_rn((float)t, ff);
    float s, c;
    sincosf(ang, &s, &c);
    ct[idx] = c;
    st[idx] = s;
}

// ---------------------------------------------------------------------------
// GEMM core: split-bf16 C = Ah@Bh^T + Ah@Bl^T + Al@Bh^T
// BM=256, BN=128, BK=64, 256 threads (4m x 2n warps, warp tile 64x64),
// 2-stage cp.async pipeline. Per-accumulator MMA grouping (R8-proven).
// Stage layout: Ah@0(32K) | Al@32K | Bh@64K(16K) | Bl@80K  (rows 128B, SW128)
// ---------------------------------------------------------------------------
#define STG_BYTES 98304
#define GEMM_SMEM (2*STG_BYTES + 1024)

__device__ __forceinline__ void gemm_core(
    const __nv_bfloat16* __restrict__ Ah, const __nv_bfloat16* __restrict__ Al,
    const __nv_bfloat16* __restrict__ BTh, const __nv_bfloat16* __restrict__ BTl,
    int K, int m0, int n0, uint32_t sb, int tid, float c[4][8][4])
{
    const int lane = tid & 31;
    const int wm   = (tid >> 5) >> 1;   // 0..3 (64 rows each)
    const int wn   = (tid >> 5) & 1;    // 0..1 (64 cols each)
    const int nstage = K / 64;

    #pragma unroll
    for (int im = 0; im < 4; im++)
        #pragma unroll
        for (int in = 0; in < 8; in++)
            #pragma unroll
            for (int j = 0; j < 4; j++) c[im][in][j] = 0.f;

    auto load_stage = [&](int s) {
        const int k0 = s * 64;
        const uint32_t stg = sb + (uint32_t)(s & 1) * STG_BYTES;
        #pragma unroll
        for (int i = 0; i < 24; i++) {
            int idx = tid + (i << 8);           // 0..6143
            if (idx < 4096) {
                int mat = idx >> 11;
                int row = (idx >> 3) & 255;
                int q   = idx & 7;
                const __nv_bfloat16* src =
                    (mat ? Al : Ah) + (size_t)(m0 + row) * K + k0 + q * 8;
                cp16(stg + mat * 32768 + sw128((uint32_t)(row * 128 + q * 16)), src);
            } else {
                int rel = idx - 4096;
                int mat = rel >> 10;
                int row = (rel >> 3) & 127;
                int q   = rel & 7;
                const __nv_bfloat16* src =
                    (mat ? BTl : BTh) + (size_t)(n0 + row) * K + k0 + q * 8;
                cp16(stg + 65536 + mat * 16384 + sw128((uint32_t)(row * 128 + q * 16)), src);
            }
        }
    };

    load_stage(0);
    asm volatile("cp.async.commit_group;" ::: "memory");

    const int aRow  = (lane & 15);
    const int aKoff = (lane >> 4) << 4;
    const int bRow  = (lane & 7) + ((lane >> 4) << 3);
    const int bKoff = ((lane >> 3) & 1) << 4;

    for (int s = 0; s < nstage; s++) {
        if (s + 1 < nstage) {
            load_stage(s + 1);
            asm volatile("cp.async.commit_group;" ::: "memory");
            asm volatile("cp.async.wait_group 1;" ::: "memory");
        } else {
            asm volatile("cp.async.wait_group 0;" ::: "memory");
        }
        __syncthreads();

        const uint32_t ab = sb + (uint32_t)(s & 1) * STG_BYTES;

        #pragma unroll
        for (int kk = 0; kk < 4; kk++) {
            const int kb = kk * 32;
            uint32_t a_h[4][4], a_l[4][4];
            #pragma unroll
            for (int im = 0; im < 4; im++) {
                uint32_t off = sw128((uint32_t)((wm * 64 + im * 16 + aRow) * 128 + kb + aKoff));
                ldsm4(a_h[im], ab + off);
                ldsm4(a_l[im], ab + 32768 + off);
            }
            uint32_t b_h[16], b_l[16];
            #pragma unroll
            for (int ib = 0; ib < 4; ib++) {
                uint32_t off = sw128((uint32_t)((wn * 64 + ib * 16 + bRow) * 128 + kb + bKoff));
                ldsm4(&b_h[ib * 4], ab + 65536 + off);
                ldsm4(&b_l[ib * 4], ab + 81920 + off);
            }
            #pragma unroll
            for (int im = 0; im < 4; im++) {
                #pragma unroll
                for (int in = 0; in < 8; in++) {
                    const uint32_t* bh = &b_h[(in >> 1) * 4 + (in & 1) * 2];
                    const uint32_t* bl = &b_l[(in >> 1) * 4 + (in & 1) * 2];
                    mma16816(c[im][in], a_h[im], bh);
                    mma16816(c[im][in], a_l[im], bh);
                    mma16816(c[im][in], a_h[im], bl);
                }
            }
        }
        __syncthreads();
    }
}

// ---------------------------------------------------------------------------
// QKV GEMM: fused projections with RoPE / v-split epilogue.
// N = 3072 columns: [0,2048) Q, [2048,2560) K, [2560,3072) V.
// ---------------------------------------------------------------------------
__global__ void __launch_bounds__(256, 1)
gemm_qkv_kernel(const __nv_bfloat16* __restrict__ Ah, const __nv_bfloat16* __restrict__ Al,
                const __nv_bfloat16* __restrict__ BTh, const __nv_bfloat16* __restrict__ BTl,
                const float* __restrict__ bq, const float* __restrict__ bk,
                const float* __restrict__ bv,
                const float* __restrict__ ct, const float* __restrict__ st,
                __nv_bfloat16* __restrict__ qr, __nv_bfloat16* __restrict__ kr,
                __nv_bfloat16* __restrict__ vh, __nv_bfloat16* __restrict__ vl)
{
    extern __shared__ char dsm[];
    char* smbase = (char*)(((uintptr_t)dsm + 1023) & ~(uintptr_t)1023);
    const uint32_t sb = smem_u32(smbase);
    const int tid  = threadIdx.x;
    const int lane = tid & 31;
    const int wm   = (tid >> 5) >> 1;
    const int wn   = (tid >> 5) & 1;
    const int m0   = blockIdx.y * 256;
    const int n0   = blockIdx.x * 128;

    float c[4][8][4];
    gemm_core(Ah, Al, BTh, BTl, NE, m0, n0, sb, tid, c);

    const int region = (n0 >= NE + KVDIM) ? 2 : (n0 >= NE ? 1 : 0);

    #pragma unroll
    for (int im = 0; im < 4; im++) {
        const int r0 = m0 + wm * 64 + im * 16 + (lane >> 2);
        const int b  = r0 >> 11;
        const int t  = r0 & 2047;
        #pragma unroll
        for (int in = 0; in < 8; in++) {
            const int cc = n0 + wn * 64 + in * 8 + ((lane & 3) << 1);
            float b0, b1;
            if (region == 0)      { b0 = bq[cc];          b1 = bq[cc + 1]; }
            else if (region == 1) { b0 = bk[cc - NE];     b1 = bk[cc - NE + 1]; }
            else                  { b0 = bv[cc - NE - KVDIM]; b1 = bv[cc - NE - KVDIM + 1]; }
            float v0 = c[im][in][0] + b0, v1 = c[im][in][1] + b1;   // row t
            float v2 = c[im][in][2] + b0, v3 = c[im][in][3] + b1;   // row t+8
            const int dloc = cc & 127;
            if (region <= 1) {
                const int i  = dloc >> 1;
                float c0 = ct[t * 64 + i],       s0 = st[t * 64 + i];
                float c2 = ct[(t + 8) * 64 + i], s2 = st[(t + 8) * 64 + i];
                uint32_t p0 = packbf2(__float2bfloat16(v0 * c0 - v1 * s0),
                                      __float2bfloat16(v0 * s0 + v1 * c0));
                uint32_t p2 = packbf2(__float2bfloat16(v2 * c2 - v3 * s2),
                                      __float2bfloat16(v2 * s2 + v3 * c2));
                if (region == 0) {
                    const int h = cc >> 7;
                    size_t dst = ((size_t)((b * NH + h) * TT + t)) * HD + dloc;
                    *(uint32_t*)(qr + dst)          = p0;
                    *(uint32_t*)(qr + dst + 8 * HD) = p2;
                } else {
                    const int h = (cc - NE) >> 7;
                    size_t dst = ((size_t)((b * NKV + h) * TT + t)) * HD + dloc;
                    *(uint32_t*)(kr + dst)          = p0;
                    *(uint32_t*)(kr + dst + 8 * HD) = p2;
                }
            } else {
                const int h = (cc - NE - KVDIM) >> 7;
                size_t dst = ((size_t)((b * NKV + h) * TT + t)) * HD + dloc;
                __nv_bfloat16 h0 = __float2bfloat16(v0);
                __nv_bfloat16 h1 = __float2bfloat16(v1);
                __nv_bfloat16 h2 = __float2bfloat16(v2);
                __nv_bfloat16 h3 = __float2bfloat16(v3);
                *(uint32_t*)(vh + dst) = packbf2(h0, h1);
                *(uint32_t*)(vl + dst) = packbf2(__float2bfloat16(v0 - __bfloat162float(h0)),
                                                 __float2bfloat16(v1 - __bfloat162float(h1)));
                *(uint32_t*)(vh + dst + 8 * HD) = packbf2(h2, h3);
                *(uint32_t*)(vl + dst + 8 * HD) = packbf2(__float2bfloat16(v2 - __bfloat162float(h2)),
                                                          __float2bfloat16(v3 - __bfloat162float(h3)));
            }
        }
    }
}

// ---------------------------------------------------------------------------
// Output projection GEMM: plain bias epilogue -> fp32 out
// ---------------------------------------------------------------------------
__global__ void __launch_bounds__(256, 1)
gemm_out_kernel(const __nv_bfloat16* __restrict__ Ah, const __nv_bfloat16* __restrict__ Al,
                const __nv_bfloat16* __restrict__ BTh, const __nv_bfloat16* __restrict__ BTl,
                const float* __restrict__ bias, float* __restrict__ C)
{
    extern __shared__ char dsm[];
    char* smbase = (char*)(((uintptr_t)dsm + 1023) & ~(uintptr_t)1023);
    const uint32_t sb = smem_u32(smbase);
    const int tid  = threadIdx.x;
    const int lane = tid & 31;
    const int wm   = (tid >> 5) >> 1;
    const int wn   = (tid >> 5) & 1;
    const int m0   = blockIdx.y * 256;
    const int n0   = blockIdx.x * 128;

    float c[4][8][4];
    gemm_core(Ah, Al, BTh, BTl, NE, m0, n0, sb, tid, c);

    #pragma unroll
    for (int im = 0; im < 4; im++) {
        const int r0 = m0 + wm * 64 + im * 16 + (lane >> 2);
        #pragma unroll
        for (int in = 0; in < 8; in++) {
            const int cc = n0 + wn * 64 + in * 8 + ((lane & 3) << 1);
            float2 bb = *(const float2*)&bias[cc];
            float2 o0, o1;
            o0.x = c[im][in][0] + bb.x;  o0.y = c[im][in][1] + bb.y;
            o1.x = c[im][in][2] + bb.x;  o1.y = c[im][in][3] + bb.y;
            *(float2*)&C[(size_t)r0 * NE + cc]       = o0;
            *(float2*)&C[(size_t)(r0 + 8) * NE + cc] = o1;
        }
    }
}

// ---------------------------------------------------------------------------
// Flash attention (causal, GQA) on mma.sync. BM=128, BN=64, 256 threads/8 warps.
// 3-buffer cp.async ring, ONE __syncthreads per tile (warp skew < 1 tile).
// Epilogue writes split-bf16 oh/ol directly (feeds O-projection GEMM).
// smem: Q(128 rows) | {K,Vh,Vl} x 3 buffers (64 rows each), rows 272B.
// ---------------------------------------------------------------------------
#define AT_RS 272
#define AT_T64 (64 * AT_RS)
#define AT_QSZ (128 * AT_RS)
#define ATT_SMEM (AT_QSZ + 9 * AT_T64 + 1024)

__global__ void __launch_bounds__(256, 1)
attn_mma_kernel(const __nv_bfloat16* __restrict__ qr, const __nv_bfloat16* __restrict__ kr,
                const __nv_bfloat16* __restrict__ vh, const __nv_bfloat16* __restrict__ vl,
                __nv_bfloat16* __restrict__ oh, __nv_bfloat16* __restrict__ ol)
{
    extern __shared__ char dsm2[];
    char* smb = (char*)(((uintptr_t)dsm2 + 1023) & ~(uintptr_t)1023);
    const uint32_t sb = smem_u32(smb);

    const int tid  = threadIdx.x;
    const int lane = tid & 31;
    const int w    = tid >> 5;                              // 0..7
    const int mtb  = (int)gridDim.x - 1 - (int)blockIdx.x;  // heavy blocks first
    const int h    = blockIdx.y, b = blockIdx.z;
    const int m0   = mtb * 128;
    const int kv   = h >> 2;
    const int ntile = 2 * mtb + 2;

    const __nv_bfloat16* qg  = qr + ((size_t)(b * NH + h) * TT + m0) * HD;
    const __nv_bfloat16* kg  = kr + ((size_t)(b * NKV + kv) * TT) * HD;
    const __nv_bfloat16* vhg = vh + ((size_t)(b * NKV + kv) * TT) * HD;
    const __nv_bfloat16* vlg = vl + ((size_t)(b * NKV + kv) * TT) * HD;

    const uint32_t Q0 = sb;
    auto toff = [&](int buf, int which) -> uint32_t {
        return sb + AT_QSZ + (uint32_t)AT_T64 * (buf * 3 + which);
    };
    auto load64 = [&](uint32_t dst, const __nv_bfloat16* src) {
        #pragma unroll
        for (int i = 0; i < 4; i++) {
            int idx = tid + i * 256;
            int row = idx >> 4, cq = idx & 15;
            cp16(dst + (uint32_t)(row * AT_RS + cq * 16), src + (size_t)row * HD + cq * 8);
        }
    };

    // Q: 128 rows (group 0, together with tile 0's K/V)
    #pragma unroll
    for (int i = 0; i < 8; i++) {
        int idx = tid + i * 256;
        int row = idx >> 4, cq = idx & 15;
        cp16(Q0 + (uint32_t)(row * AT_RS + cq * 16), qg + (size_t)row * HD + cq * 8);
    }
    load64(toff(0, 0), kg);
    load64(toff(0, 1), vhg);
    load64(toff(0, 2), vlg);
    asm volatile("cp.async.commit_group;" ::: "memory");

    uint32_t qf[8][4];
    float ov[16][4];
    #pragma unroll
    for (int n = 0; n < 16; n++) { ov[n][0] = ov[n][1] = ov[n][2] = ov[n][3] = 0.f; }
    float m_lo = -1e30f, m_hi = -1e30f, l_lo = 0.f, l_hi = 0.f;

    const int aRow = lane & 15;
    const int aK   = (lane >> 4) << 4;
    const int bRow = (lane & 7) + ((lane >> 4) << 3);
    const int bK   = ((lane >> 3) & 1) << 4;
    const int vRow = (lane & 7) + (((lane >> 3) & 1) << 3);
    const int vC   = (lane >> 4) << 4;

    for (int jt = 0; jt < ntile; jt++) {
        // prefetch tile jt+1 into ring buffer (jt+1)%3; last read at tile jt-2,
        // and the single per-tile sync bounds warp skew to <1 tile -> safe.
        if (jt + 1 < ntile) {
            int nb = (jt + 1) % 3;
            load64(toff(nb, 0), kg  + (size_t)(jt + 1) * 64 * HD);
            load64(toff(nb, 1), vhg + (size_t)(jt + 1) * 64 * HD);
            load64(toff(nb, 2), vlg + (size_t)(jt + 1) * 64 * HD);
            asm volatile("cp.async.commit_group;" ::: "memory");
            asm volatile("cp.async.wait_group 1;" ::: "memory");
        } else {
            asm volatile("cp.async.wait_group 0;" ::: "memory");
        }
        __syncthreads();   // the only sync per tile

        if (jt == 0) {
            #pragma unroll
            for (int kt = 0; kt < 8; kt++)
                ldsm4(qf[kt], Q0 + (uint32_t)((w * 16 + aRow) * AT_RS + kt * 32 + aK));
        }

        const int cbuf = jt % 3;
        const uint32_t kb  = toff(cbuf, 0);
        const uint32_t vhb = toff(cbuf, 1);
        const uint32_t vlb = toff(cbuf, 2);

        // ---- S = Q @ K^T ----
        float sc[8][4];
        #pragma unroll
        for (int j = 0; j < 8; j++) { sc[j][0] = sc[j][1] = sc[j][2] = sc[j][3] = 0.f; }

        #pragma unroll
        for (int kt = 0; kt < 8; kt++) {
            #pragma unroll
            for (int ib = 0; ib < 4; ib++) {
                uint32_t bf[4];
                ldsm4(bf, kb + (uint32_t)((ib * 16 + bRow) * AT_RS + kt * 32 + bK));
                mma16816(sc[2 * ib],     qf[kt], bf);
                mma16816(sc[2 * ib + 1], qf[kt], bf + 2);
            }
        }

        // ---- causal mask (last two tiles only) ----
        if (jt >= ntile - 2) {
            const int rl = m0 + w * 16 + (lane >> 2);
            #pragma unroll
            for (int j = 0; j < 8; j++) {
                int gn = jt * 64 + j * 8 + ((lane & 3) << 1);
                if (gn     > rl)     sc[j][0] = -1e30f;
                if (gn + 1 > rl)     sc[j][1] = -1e30f;
                if (gn     > rl + 8) sc[j][2] = -1e30f;
                if (gn + 1 > rl + 8) sc[j][3] = -1e30f;
            }
        }

        // ---- online softmax ----
        float vlo = -1e30f, vhi = -1e30f;
        #pragma unroll
        for (int j = 0; j < 8; j++) {
            vlo = fmaxf(vlo, fmaxf(sc[j][0], sc[j][1]));
            vhi = fmaxf(vhi, fmaxf(sc[j][2], sc[j][3]));
        }
        vlo = fmaxf(vlo, __shfl_xor_sync(0xffffffffu, vlo, 1));
        vlo = fmaxf(vlo, __shfl_xor_sync(0xffffffffu, vlo, 2));
        vhi = fmaxf(vhi, __shfl_xor_sync(0xffffffffu, vhi, 1));
        vhi = fmaxf(vhi, __shfl_xor_sync(0xffffffffu, vhi, 2));
        float mn_lo = fmaxf(m_lo, vlo), mn_hi = fmaxf(m_hi, vhi);
        float al_lo = __expf(m_lo - mn_lo), al_hi = __expf(m_hi - mn_hi);
        m_lo = mn_lo; m_hi = mn_hi;
        l_lo *= al_lo; l_hi *= al_hi;
        #pragma unroll
        for (int n = 0; n < 16; n++) {
            ov[n][0] *= al_lo; ov[n][1] *= al_lo;
            ov[n][2] *= al_hi; ov[n][3] *= al_hi;
        }

        uint32_t ph[8][2], pl[8][2];
        #pragma unroll
        for (int j = 0; j < 8; j++) {
            float p0 = __expf(sc[j][0] - m_lo), p1 = __expf(sc[j][1] - m_lo);
            float p2 = __expf(sc[j][2] - m_hi), p3 = __expf(sc[j][3] - m_hi);
            l_lo += p0 + p1;  l_hi += p2 + p3;
            __nv_bfloat16 h0 = __float2bfloat16(p0), h1 = __float2bfloat16(p1);
            __nv_bfloat16 h2 = __float2bfloat16(p2), h3 = __float2bfloat16(p3);
            ph[j][0] = packbf2(h0, h1);
            ph[j][1] = packbf2(h2, h3);
            pl[j][0] = packbf2(__float2bfloat16(p0 - __bfloat162float(h0)),
                               __float2bfloat16(p1 - __bfloat162float(h1)));
            pl[j][1] = packbf2(__float2bfloat16(p2 - __bfloat162float(h2)),
                               __float2bfloat16(p3 - __bfloat162float(h3)));
        }

        // ---- O += P @ V  (3-term split) ----
        #pragma unroll
        for (int kt = 0; kt < 4; kt++) {
            uint32_t ah[4] = { ph[2*kt][0], ph[2*kt][1], ph[2*kt+1][0], ph[2*kt+1][1] };
            uint32_t am[4] = { pl[2*kt][0], pl[2*kt][1], pl[2*kt+1][0], pl[2*kt+1][1] };
            #pragma unroll
            for (int np = 0; np < 4; np++) {
                uint32_t base = (uint32_t)((kt * 16 + vRow) * AT_RS + np * 64 + vC);
                uint32_t bh0[4], bh1[4], bl0[4], bl1[4];
                ldsm4t(bh0, vhb + base);
                ldsm4t(bh1, vhb + base + 32);
                ldsm4t(bl0, vlb + base);
                ldsm4t(bl1, vlb + base + 32);
                mma16816(ov[np*4+0], ah, bh0);
                mma16816(ov[np*4+1], ah, bh0 + 2);
                mma16816(ov[np*4+2], ah, bh1);
                mma16816(ov[np*4+3], ah, bh1 + 2);
                mma16816(ov[np*4+0], am, bh0);
                mma16816(ov[np*4+1], am, bh0 + 2);
                mma16816(ov[np*4+2], am, bh1);
                mma16816(ov[np*4+3], am, bh1 + 2);
                mma16816(ov[np*4+0], ah, bl0);
                mma16816(ov[np*4+1], ah, bl0 + 2);
                mma16816(ov[np*4+2], ah, bl1);
                mma16816(ov[np*4+3], ah, bl1 + 2);
            }
        }
        // no trailing sync: next iteration's loads target a buffer last read
        // two tiles ago, and the per-tile sync bounds skew to <1 tile.
    }

    // ---- epilogue: normalize, split-bf16, write oh/ol ----
    l_lo += __shfl_xor_sync(0xffffffffu, l_lo, 1);
    l_lo += __shfl_xor_sync(0xffffffffu, l_lo, 2);
    l_hi += __shfl_xor_sync(0xffffffffu, l_hi, 1);
    l_hi += __shfl_xor_sync(0xffffffffu, l_hi, 2);
    const float inv_lo = 0.022097086912079608f / l_lo;
    const float inv_hi = 0.022097086912079608f / l_hi;
    const int rlo = m0 + w * 16 + (lane >> 2);
    size_t base = ((size_t)(b * TT) + rlo) * NE + h * HD;
    #pragma unroll
    for (int n = 0; n < 16; n++) {
        int d = n * 8 + ((lane & 3) << 1);
        float o0 = ov[n][0] * inv_lo, o1 = ov[n][1] * inv_lo;
        float o2 = ov[n][2] * inv_hi, o3 = ov[n][3] * inv_hi;
        __nv_bfloat16 h0 = __float2bfloat16(o0), h1 = __float2bfloat16(o1);
        __nv_bfloat16 h2 = __float2bfloat16(o2), h3 = __float2bfloat16(o3);
        *(uint32_t*)(oh + base + d) = packbf2(h0, h1);
        *(uint32_t*)(ol + base + d) = packbf2(__float2bfloat16(o0 - __bfloat162float(h0)),
                                              __float2bfloat16(o1 - __bfloat162float(h1)));
        *(uint32_t*)(oh + base + 8 * NE + d) = packbf2(h2, h3);
        *(uint32_t*)(ol + base + 8 * NE + d) = packbf2(__float2bfloat16(o2 - __bfloat162float(h2)),
                                                       __float2bfloat16(o3 - __bfloat162float(h3)));
    }
}

// ---------------------------------------------------------------------------
// launch
// ---------------------------------------------------------------------------
extern "C" void kernel_launch(void* const* d_in, const int* in_sizes, int n_in,
                              void* d_out, int out_size)
{
    const float* x  = (const float*)d_in[0];
    const float* Wq = (const float*)d_in[1];
    const float* bq = (const float*)d_in[2];
    const float* Wk = (const float*)d_in[3];
    const float* bk = (const float*)d_in[4];
    const float* Wv = (const float*)d_in[5];
    const float* bv = (const float*)d_in[6];
    const float* Wo = (const float*)d_in[7];
    const float* bo = (const float*)d_in[8];
    float* out = (float*)d_out;

    float *ct, *st;
    __nv_bfloat16 *qr, *kr, *vhp, *vlp;
    __nv_bfloat16 *xh, *xl, *oh, *ol;
    __nv_bfloat16 *wqkvh, *wqkvl, *woh, *wol;
    cudaGetSymbolAddress((void**)&ct, g_cos);
    cudaGetSymbolAddress((void**)&st, g_sin);
    cudaGetSymbolAddress((void**)&qr, g_qr);
    cudaGetSymbolAddress((void**)&kr, g_kr);
    cudaGetSymbolAddress((void**)&vhp, g_vh);
    cudaGetSymbolAddress((void**)&vlp, g_vl);
    cudaGetSymbolAddress((void**)&xh, g_xh);
    cudaGetSymbolAddress((void**)&xl, g_xl);
    cudaGetSymbolAddress((void**)&oh, g_oh);
    cudaGetSymbolAddress((void**)&ol, g_ol);
    cudaGetSymbolAddress((void**)&wqkvh, g_wqkvh);
    cudaGetSymbolAddress((void**)&wqkvl, g_wqkvl);
    cudaGetSymbolAddress((void**)&woh, g_woh);
    cudaGetSymbolAddress((void**)&wol, g_wol);

    cudaFuncSetAttribute(gemm_qkv_kernel, cudaFuncAttributeMaxDynamicSharedMemorySize, GEMM_SMEM);
    cudaFuncSetAttribute(gemm_out_kernel, cudaFuncAttributeMaxDynamicSharedMemorySize, GEMM_SMEM);
    cudaFuncSetAttribute(attn_mma_kernel, cudaFuncAttributeMaxDynamicSharedMemorySize, ATT_SMEM);

    // prep (3 launches)
    tsplit_all_kernel<<<10240, 256>>>(Wq, Wk, Wv, Wo, wqkvh, wqkvl, woh, wol);
    split_kernel<<<(MROWS * NE / 8 + 255) / 256, 256>>>(x, xh, xl, MROWS * NE / 8);
    rope_table_kernel<<<(TT * 64 + 255) / 256, 256>>>(ct, st);

    // fused QKV projection (rope + v-split epilogue)
    gemm_qkv_kernel<<<dim3(NQKV / 128, MROWS / 256), 256, GEMM_SMEM>>>(
        xh, xl, wqkvh, wqkvl, bq, bk, bv, ct, st, qr, kr, vhp, vlp);

    // attention (writes split-bf16 oh/ol)
    {
        dim3 grid(TT / 128, NH, BB);
        attn_mma_kernel<<<grid, 256, ATT_SMEM>>>(qr, kr, vhp, vlp, oh, ol);
    }

    // output projection
    gemm_out_kernel<<<dim3(NE / 128, MROWS / 256), 256, GEMM_SMEM>>>(
        oh, ol, woh, wol, bo, out);
}

// round 11
// speedup vs baseline: 1.6018x; 1.0204x over previous
#include <cuda_runtime.h>
#include <cuda_bf16.h>
#include <cstdint>
#include <cmath>

// ---------------------------------------------------------------------------
// Problem constants (fixed shapes)
// ---------------------------------------------------------------------------
#define BB 2
#define TT 2048
#define NE 2048          // N_EMBED
#define NH 16            // N_HEAD
#define NKV 4            // N_KV_HEAD
#define HD 128           // HEAD_DIM
#define MROWS (BB*TT)    // 4096
#define KVDIM (NKV*HD)   // 512
#define NQKV (NE + 2*KVDIM)   // 3072

// ---------------------------------------------------------------------------
// Scratch (static device globals; no allocations allowed)
// ---------------------------------------------------------------------------
__device__ __nv_bfloat16 g_qr[(size_t)BB * NH * TT * HD];   // rope(q) bf16 [B,H,T,D]
__device__ __nv_bfloat16 g_kr[(size_t)BB * NKV * TT * HD];  // rope(k) bf16 [B,KV,T,D]
__device__ __nv_bfloat16 g_vh[(size_t)BB * NKV * TT * HD];  // v hi bf16 [B,KV,T,D]
__device__ __nv_bfloat16 g_vl[(size_t)BB * NKV * TT * HD];  // v lo bf16 [B,KV,T,D]
__device__ float g_cos[TT * (HD/2)];
__device__ float g_sin[TT * (HD/2)];

// split-bf16 operands for tensor-core GEMMs
__device__ __nv_bfloat16 g_xh[(size_t)MROWS * NE];
__device__ __nv_bfloat16 g_xl[(size_t)MROWS * NE];
__device__ __nv_bfloat16 g_oh[(size_t)MROWS * NE];   // attn out hi
__device__ __nv_bfloat16 g_ol[(size_t)MROWS * NE];   // attn out lo
// packed transposed weights [N][K] hi/lo: rows 0..2047 Wq^T, 2048..2559 Wk^T, 2560..3071 Wv^T
__device__ __nv_bfloat16 g_wqkvh[(size_t)NQKV * NE];
__device__ __nv_bfloat16 g_wqkvl[(size_t)NQKV * NE];
__device__ __nv_bfloat16 g_woh[(size_t)NE * NE];
__device__ __nv_bfloat16 g_wol[(size_t)NE * NE];

// ---------------------------------------------------------------------------
// Helpers (baseline PTX only — no sm_103a-suffixed features)
// ---------------------------------------------------------------------------
__device__ __forceinline__ uint32_t smem_u32(const void* p) {
    uint32_t a;
    asm("{ .reg .u64 t; cvta.to.shared.u64 t, %1; cvt.u32.u64 %0, t; }" : "=r"(a) : "l"(p));
    return a;
}
__device__ __forceinline__ uint32_t sw128(uint32_t off) {
    return off ^ ((off >> 3) & 0x70);
}
__device__ __forceinline__ void cp16(uint32_t dst, const void* src) {
    asm volatile("cp.async.cg.shared.global [%0], [%1], 16;" :: "r"(dst), "l"(src) : "memory");
}
__device__ __forceinline__ void ldsm4(uint32_t* r, uint32_t addr) {
    asm volatile("ldmatrix.sync.aligned.m8n8.x4.shared.b16 {%0,%1,%2,%3}, [%4];"
                 : "=r"(r[0]), "=r"(r[1]), "=r"(r[2]), "=r"(r[3]) : "r"(addr));
}
__device__ __forceinline__ void ldsm4t(uint32_t* r, uint32_t addr) {
    asm volatile("ldmatrix.sync.aligned.m8n8.x4.trans.shared.b16 {%0,%1,%2,%3}, [%4];"
                 : "=r"(r[0]), "=r"(r[1]), "=r"(r[2]), "=r"(r[3]) : "r"(addr));
}
__device__ __forceinline__ void mma16816(float* c, const uint32_t* a, const uint32_t* b) {
    asm volatile(
        "mma.sync.aligned.m16n8k16.row.col.f32.bf16.bf16.f32 "
        "{%0,%1,%2,%3}, {%4,%5,%6,%7}, {%8,%9}, {%0,%1,%2,%3};"
        : "+f"(c[0]), "+f"(c[1]), "+f"(c[2]), "+f"(c[3])
        : "r"(a[0]), "r"(a[1]), "r"(a[2]), "r"(a[3]), "r"(b[0]), "r"(b[1]));
}
__device__ __forceinline__ uint32_t packbf2(__nv_bfloat16 lo, __nv_bfloat16 hi) {
    return ((uint32_t)__bfloat16_as_ushort(hi) << 16) | (uint32_t)__bfloat16_as_ushort(lo);
}

// ---------------------------------------------------------------------------
// Prep kernels
// ---------------------------------------------------------------------------
__global__ void __launch_bounds__(256)
split_kernel(const float* __restrict__ x, __nv_bfloat16* __restrict__ xh,
             __nv_bfloat16* __restrict__ xl, int n8)
{
    int i = blockIdx.x * 256 + threadIdx.x;
    if (i >= n8) return;
    size_t base = (size_t)i * 8;
    float4 v0 = *(const float4*)(x + base);
    float4 v1 = *(const float4*)(x + base + 4);
    float vv[8] = {v0.x, v0.y, v0.z, v0.w, v1.x, v1.y, v1.z, v1.w};
    union { __nv_bfloat16 b[8]; uint4 u; } ph, pl;
    #pragma unroll
    for (int j = 0; j < 8; j++) {
        __nv_bfloat16 h = __float2bfloat16(vv[j]);
        ph.b[j] = h;
        pl.b[j] = __float2bfloat16(vv[j] - __bfloat162float(h));
    }
    *(uint4*)(xh + base) = ph.u;
    *(uint4*)(xl + base) = pl.u;
}

// All four weight transposes fused: W[K][N] row-major -> T[N][K] hi/lo bf16
__global__ void __launch_bounds__(256)
tsplit_all_kernel(const float* __restrict__ Wq, const float* __restrict__ Wk,
                  const float* __restrict__ Wv, const float* __restrict__ Wo,
                  __nv_bfloat16* __restrict__ wqkvh, __nv_bfloat16* __restrict__ wqkvl,
                  __nv_bfloat16* __restrict__ woh, __nv_bfloat16* __restrict__ wol)
{
    __shared__ float t[32][33];
    int id = blockIdx.x;
    const float* W;
    __nv_bfloat16 *Th, *Tl;
    int N;
    if (id < 4096)      { W = Wq; Th = wqkvh;                            Tl = wqkvl;                            N = NE;    }
    else if (id < 5120) { W = Wk; Th = wqkvh + (size_t)NE * NE;          Tl = wqkvl + (size_t)NE * NE;          N = KVDIM; id -= 4096; }
    else if (id < 6144) { W = Wv; Th = wqkvh + (size_t)(NE + KVDIM) * NE; Tl = wqkvl + (size_t)(NE + KVDIM) * NE; N = KVDIM; id -= 5120; }
    else                { W = Wo; Th = woh;                              Tl = wol;                              N = NE;    id -= 6144; }
    const int ntiles = N / 32;
    const int n0 = (id % ntiles) * 32;
    const int k0 = (id / ntiles) * 32;
    const int tx = threadIdx.x & 31, ty = threadIdx.x >> 5;   // 32x8
    #pragma unroll
    for (int i = 0; i < 4; i++)
        t[ty + i * 8][tx] = W[(size_t)(k0 + ty + i * 8) * N + n0 + tx];
    __syncthreads();
    #pragma unroll
    for (int i = 0; i < 4; i++) {
        int n = n0 + ty + i * 8, k = k0 + tx;
        float v = t[tx][ty + i * 8];
        __nv_bfloat16 h = __float2bfloat16(v);
        Th[(size_t)n * NE + k] = h;
        Tl[(size_t)n * NE + k] = __float2bfloat16(v - __bfloat162float(h));
    }
}

// RoPE table: angle = fp32(t) * fp32(double-precision freq)
__global__ void __launch_bounds__(256)
rope_table_kernel(float* __restrict__ ct, float* __restrict__ st)
{
    int idx = blockIdx.x * 256 + threadIdx.x;
    if (idx >= TT * (HD/2)) return;
    int t = idx >> 6;
    int i = idx & 63;
    double fr = exp(-((double)(2 * i) / (double)NE) * log(10000.0));
    float ff = (float)fr;
    float ang = __fmul_rn((float)t, ff);
    float s, c;
    sincosf(ang, &s, &c);
    ct[idx] = c;
    st[idx] = s;
}

// ---------------------------------------------------------------------------
// GEMM core: split-bf16 C = Ah@Bh^T + Ah@Bl^T + Al@Bh^T
// BM=256, BN=128, BK=64, 512 threads (4m x 4n warps, warp tile 64x32),
// 2-stage cp.async pipeline, ONE __syncthreads per stage.
// Stage layout: Ah@0(32K) | Al@32K | Bh@64K(16K) | Bl@80K  (rows 128B, SW128)
// ---------------------------------------------------------------------------
#define STG_BYTES 98304
#define GEMM_SMEM (2*STG_BYTES + 1024)

__device__ __forceinline__ void gemm_core(
    const __nv_bfloat16* __restrict__ Ah, const __nv_bfloat16* __restrict__ Al,
    const __nv_bfloat16* __restrict__ BTh, const __nv_bfloat16* __restrict__ BTl,
    int K, int m0, int n0, uint32_t sb, int tid, float c[4][4][4])
{
    const int lane = tid & 31;
    const int wm   = (tid >> 5) >> 2;   // 0..3 (64 rows each)
    const int wn   = (tid >> 5) & 3;    // 0..3 (32 cols each)
    const int nstage = K / 64;

    #pragma unroll
    for (int im = 0; im < 4; im++)
        #pragma unroll
        for (int in = 0; in < 4; in++)
            #pragma unroll
            for (int j = 0; j < 4; j++) c[im][in][j] = 0.f;

    auto load_stage = [&](int s) {
        const int k0 = s * 64;
        const uint32_t stg = sb + (uint32_t)(s & 1) * STG_BYTES;
        #pragma unroll
        for (int i = 0; i < 12; i++) {
            int idx = tid + (i << 9);           // 0..6143 (512 stride)
            if (idx < 4096) {
                int mat = idx >> 11;
                int row = (idx >> 3) & 255;
                int q   = idx & 7;
                const __nv_bfloat16* src =
                    (mat ? Al : Ah) + (size_t)(m0 + row) * K + k0 + q * 8;
                cp16(stg + mat * 32768 + sw128((uint32_t)(row * 128 + q * 16)), src);
            } else {
                int rel = idx - 4096;
                int mat = rel >> 10;
                int row = (rel >> 3) & 127;
                int q   = rel & 7;
                const __nv_bfloat16* src =
                    (mat ? BTl : BTh) + (size_t)(n0 + row) * K + k0 + q * 8;
                cp16(stg + 65536 + mat * 16384 + sw128((uint32_t)(row * 128 + q * 16)), src);
            }
        }
    };

    load_stage(0);
    asm volatile("cp.async.commit_group;" ::: "memory");

    const int aRow  = (lane & 15);
    const int aKoff = (lane >> 4) << 4;
    const int bRow  = (lane & 7) + ((lane >> 4) << 3);
    const int bKoff = ((lane >> 3) & 1) << 4;

    for (int s = 0; s < nstage; s++) {
        asm volatile("cp.async.wait_group 0;" ::: "memory");
        __syncthreads();   // all warps done with compute(s-1); buffer (s+1)&1 free
        if (s + 1 < nstage) {
            load_stage(s + 1);
            asm volatile("cp.async.commit_group;" ::: "memory");
        }

        const uint32_t ab = sb + (uint32_t)(s & 1) * STG_BYTES;

        #pragma unroll
        for (int kk = 0; kk < 4; kk++) {
            const int kb = kk * 32;
            // B fragments for this warp's 32 columns (hi+lo): 4 ldsm
            uint32_t b_h[8], b_l[8];
            #pragma unroll
            for (int ib = 0; ib < 2; ib++) {
                uint32_t off = sw128((uint32_t)((wn * 32 + ib * 16 + bRow) * 128 + kb + bKoff));
                ldsm4(&b_h[ib * 4], ab + 65536 + off);
                ldsm4(&b_l[ib * 4], ab + 81920 + off);
            }
            #pragma unroll
            for (int im = 0; im < 4; im++) {
                uint32_t a_h[4], a_l[4];
                uint32_t off = sw128((uint32_t)((wm * 64 + im * 16 + aRow) * 128 + kb + aKoff));
                ldsm4(a_h, ab + off);
                ldsm4(a_l, ab + 32768 + off);
                #pragma unroll
                for (int in = 0; in < 4; in++) {
                    const uint32_t* bh = &b_h[(in >> 1) * 4 + (in & 1) * 2];
                    const uint32_t* bl = &b_l[(in >> 1) * 4 + (in & 1) * 2];
                    mma16816(c[im][in], a_h, bh);
                    mma16816(c[im][in], a_l, bh);
                    mma16816(c[im][in], a_h, bl);
                }
            }
        }
    }
    __syncthreads();
}

// ---------------------------------------------------------------------------
// QKV GEMM: fused projections with RoPE / v-split epilogue.
// N = 3072 columns: [0,2048) Q, [2048,2560) K, [2560,3072) V.
// ---------------------------------------------------------------------------
__global__ void __launch_bounds__(512, 1)
gemm_qkv_kernel(const __nv_bfloat16* __restrict__ Ah, const __nv_bfloat16* __restrict__ Al,
                const __nv_bfloat16* __restrict__ BTh, const __nv_bfloat16* __restrict__ BTl,
                const float* __restrict__ bq, const float* __restrict__ bk,
                const float* __restrict__ bv,
                const float* __restrict__ ct, const float* __restrict__ st,
                __nv_bfloat16* __restrict__ qr, __nv_bfloat16* __restrict__ kr,
                __nv_bfloat16* __restrict__ vh, __nv_bfloat16* __restrict__ vl)
{
    extern __shared__ char dsm[];
    char* smbase = (char*)(((uintptr_t)dsm + 1023) & ~(uintptr_t)1023);
    const uint32_t sb = smem_u32(smbase);
    const int tid  = threadIdx.x;
    const int lane = tid & 31;
    const int wm   = (tid >> 5) >> 2;
    const int wn   = (tid >> 5) & 3;
    const int m0   = blockIdx.y * 256;
    const int n0   = blockIdx.x * 128;

    float c[4][4][4];
    gemm_core(Ah, Al, BTh, BTl, NE, m0, n0, sb, tid, c);

    const int region = (n0 >= NE + KVDIM) ? 2 : (n0 >= NE ? 1 : 0);

    #pragma unroll
    for (int im = 0; im < 4; im++) {
        const int r0 = m0 + wm * 64 + im * 16 + (lane >> 2);
        const int b  = r0 >> 11;
        const int t  = r0 & 2047;
        #pragma unroll
        for (int in = 0; in < 4; in++) {
            const int cc = n0 + wn * 32 + in * 8 + ((lane & 3) << 1);
            float b0, b1;
            if (region == 0)      { b0 = bq[cc];          b1 = bq[cc + 1]; }
            else if (region == 1) { b0 = bk[cc - NE];     b1 = bk[cc - NE + 1]; }
            else                  { b0 = bv[cc - NE - KVDIM]; b1 = bv[cc - NE - KVDIM + 1]; }
            float v0 = c[im][in][0] + b0, v1 = c[im][in][1] + b1;   // row t
            float v2 = c[im][in][2] + b0, v3 = c[im][in][3] + b1;   // row t+8
            const int dloc = cc & 127;
            if (region <= 1) {
                const int i  = dloc >> 1;
                float c0 = ct[t * 64 + i],       s0 = st[t * 64 + i];
                float c2 = ct[(t + 8) * 64 + i], s2 = st[(t + 8) * 64 + i];
                uint32_t p0 = packbf2(__float2bfloat16(v0 * c0 - v1 * s0),
                                      __float2bfloat16(v0 * s0 + v1 * c0));
                uint32_t p2 = packbf2(__float2bfloat16(v2 * c2 - v3 * s2),
                                      __float2bfloat16(v2 * s2 + v3 * c2));
                if (region == 0) {
                    const int h = cc >> 7;
                    size_t dst = ((size_t)((b * NH + h) * TT + t)) * HD + dloc;
                    *(uint32_t*)(qr + dst)          = p0;
                    *(uint32_t*)(qr + dst + 8 * HD) = p2;
                } else {
                    const int h = (cc - NE) >> 7;
                    size_t dst = ((size_t)((b * NKV + h) * TT + t)) * HD + dloc;
                    *(uint32_t*)(kr + dst)          = p0;
                    *(uint32_t*)(kr + dst + 8 * HD) = p2;
                }
            } else {
                const int h = (cc - NE - KVDIM) >> 7;
                size_t dst = ((size_t)((b * NKV + h) * TT + t)) * HD + dloc;
                __nv_bfloat16 h0 = __float2bfloat16(v0);
                __nv_bfloat16 h1 = __float2bfloat16(v1);
                __nv_bfloat16 h2 = __float2bfloat16(v2);
                __nv_bfloat16 h3 = __float2bfloat16(v3);
                *(uint32_t*)(vh + dst) = packbf2(h0, h1);
                *(uint32_t*)(vl + dst) = packbf2(__float2bfloat16(v0 - __bfloat162float(h0)),
                                                 __float2bfloat16(v1 - __bfloat162float(h1)));
                *(uint32_t*)(vh + dst + 8 * HD) = packbf2(h2, h3);
                *(uint32_t*)(vl + dst + 8 * HD) = packbf2(__float2bfloat16(v2 - __bfloat162float(h2)),
                                                          __float2bfloat16(v3 - __bfloat162float(h3)));
            }
        }
    }
}

// ---------------------------------------------------------------------------
// Output projection GEMM: plain bias epilogue -> fp32 out
// ---------------------------------------------------------------------------
__global__ void __launch_bounds__(512, 1)
gemm_out_kernel(const __nv_bfloat16* __restrict__ Ah, const __nv_bfloat16* __restrict__ Al,
                const __nv_bfloat16* __restrict__ BTh, const __nv_bfloat16* __restrict__ BTl,
                const float* __restrict__ bias, float* __restrict__ C)
{
    extern __shared__ char dsm[];
    char* smbase = (char*)(((uintptr_t)dsm + 1023) & ~(uintptr_t)1023);
    const uint32_t sb = smem_u32(smbase);
    const int tid  = threadIdx.x;
    const int lane = tid & 31;
    const int wm   = (tid >> 5) >> 2;
    const int wn   = (tid >> 5) & 3;
    const int m0   = blockIdx.y * 256;
    const int n0   = blockIdx.x * 128;

    float c[4][4][4];
    gemm_core(Ah, Al, BTh, BTl, NE, m0, n0, sb, tid, c);

    #pragma unroll
    for (int im = 0; im < 4; im++) {
        const int r0 = m0 + wm * 64 + im * 16 + (lane >> 2);
        #pragma unroll
        for (int in = 0; in < 4; in++) {
            const int cc = n0 + wn * 32 + in * 8 + ((lane & 3) << 1);
            float2 bb = *(const float2*)&bias[cc];
            float2 o0, o1;
            o0.x = c[im][in][0] + bb.x;  o0.y = c[im][in][1] + bb.y;
            o1.x = c[im][in][2] + bb.x;  o1.y = c[im][in][3] + bb.y;
            *(float2*)&C[(size_t)r0 * NE + cc]       = o0;
            *(float2*)&C[(size_t)(r0 + 8) * NE + cc] = o1;
        }
    }
}

// ---------------------------------------------------------------------------
// Flash attention (causal, GQA) on mma.sync. BM=128, BN=64, 256 threads/8 warps.
// 3-buffer cp.async ring, ONE __syncthreads per tile (warp skew < 1 tile).
// Epilogue writes split-bf16 oh/ol directly (feeds O-projection GEMM).
// smem: Q(128 rows) | {K,Vh,Vl} x 3 buffers (64 rows each), rows 272B.
// ---------------------------------------------------------------------------
#define AT_RS 272
#define AT_T64 (64 * AT_RS)
#define AT_QSZ (128 * AT_RS)
#define ATT_SMEM (AT_QSZ + 9 * AT_T64 + 1024)

__global__ void __launch_bounds__(256, 1)
attn_mma_kernel(const __nv_bfloat16* __restrict__ qr, const __nv_bfloat16* __restrict__ kr,
                const __nv_bfloat16* __restrict__ vh, const __nv_bfloat16* __restrict__ vl,
                __nv_bfloat16* __restrict__ oh, __nv_bfloat16* __restrict__ ol)
{
    extern __shared__ char dsm2[];
    char* smb = (char*)(((uintptr_t)dsm2 + 1023) & ~(uintptr_t)1023);
    const uint32_t sb = smem_u32(smb);

    const int tid  = threadIdx.x;
    const int lane = tid & 31;
    const int w    = tid >> 5;                              // 0..7
    const int mtb  = (int)gridDim.x - 1 - (int)blockIdx.x;  // heavy blocks first
    const int h    = blockIdx.y, b = blockIdx.z;
    const int m0   = mtb * 128;
    const int kv   = h >> 2;
    const int ntile = 2 * mtb + 2;

    const __nv_bfloat16* qg  = qr + ((size_t)(b * NH + h) * TT + m0) * HD;
    const __nv_bfloat16* kg  = kr + ((size_t)(b * NKV + kv) * TT) * HD;
    const __nv_bfloat16* vhg = vh + ((size_t)(b * NKV + kv) * TT) * HD;
    const __nv_bfloat16* vlg = vl + ((size_t)(b * NKV + kv) * TT) * HD;

    const uint32_t Q0 = sb;
    auto toff = [&](int buf, int which) -> uint32_t {
        return sb + AT_QSZ + (uint32_t)AT_T64 * (buf * 3 + which);
    };
    auto load64 = [&](uint32_t dst, const __nv_bfloat16* src) {
        #pragma unroll
        for (int i = 0; i < 4; i++) {
            int idx = tid + i * 256;
            int row = idx >> 4, cq = idx & 15;
            cp16(dst + (uint32_t)(row * AT_RS + cq * 16), src + (size_t)row * HD + cq * 8);
        }
    };

    // Q: 128 rows (group 0, together with tile 0's K/V)
    #pragma unroll
    for (int i = 0; i < 8; i++) {
        int idx = tid + i * 256;
        int row = idx >> 4, cq = idx & 15;
        cp16(Q0 + (uint32_t)(row * AT_RS + cq * 16), qg + (size_t)row * HD + cq * 8);
    }
    load64(toff(0, 0), kg);
    load64(toff(0, 1), vhg);
    load64(toff(0, 2), vlg);
    asm volatile("cp.async.commit_group;" ::: "memory");

    uint32_t qf[8][4];
    float ov[16][4];
    #pragma unroll
    for (int n = 0; n < 16; n++) { ov[n][0] = ov[n][1] = ov[n][2] = ov[n][3] = 0.f; }
    float m_lo = -1e30f, m_hi = -1e30f, l_lo = 0.f, l_hi = 0.f;

    const int aRow = lane & 15;
    const int aK   = (lane >> 4) << 4;
    const int bRow = (lane & 7) + ((lane >> 4) << 3);
    const int bK   = ((lane >> 3) & 1) << 4;
    const int vRow = (lane & 7) + (((lane >> 3) & 1) << 3);
    const int vC   = (lane >> 4) << 4;

    for (int jt = 0; jt < ntile; jt++) {
        // prefetch tile jt+1 into ring buffer (jt+1)%3; last read at tile jt-2,
        // and the single per-tile sync bounds warp skew to <1 tile -> safe.
        if (jt + 1 < ntile) {
            int nb = (jt + 1) % 3;
            load64(toff(nb, 0), kg  + (size_t)(jt + 1) * 64 * HD);
            load64(toff(nb, 1), vhg + (size_t)(jt + 1) * 64 * HD);
            load64(toff(nb, 2), vlg + (size_t)(jt + 1) * 64 * HD);
            asm volatile("cp.async.commit_group;" ::: "memory");
            asm volatile("cp.async.wait_group 1;" ::: "memory");
        } else {
            asm volatile("cp.async.wait_group 0;" ::: "memory");
        }
        __syncthreads();   // the only sync per tile

        if (jt == 0) {
            #pragma unroll
            for (int kt = 0; kt < 8; kt++)
                ldsm4(qf[kt], Q0 + (uint32_t)((w * 16 + aRow) * AT_RS + kt * 32 + aK));
        }

        const int cbuf = jt % 3;
        const uint32_t kb  = toff(cbuf, 0);
        const uint32_t vhb = toff(cbuf, 1);
        const uint32_t vlb = toff(cbuf, 2);

        // ---- S = Q @ K^T ----
        float sc[8][4];
        #pragma unroll
        for (int j = 0; j < 8; j++) { sc[j][0] = sc[j][1] = sc[j][2] = sc[j][3] = 0.f; }

        #pragma unroll
        for (int kt = 0; kt < 8; kt++) {
            #pragma unroll
            for (int ib = 0; ib < 4; ib++) {
                uint32_t bf[4];
                ldsm4(bf, kb + (uint32_t)((ib * 16 + bRow) * AT_RS + kt * 32 + bK));
                mma16816(sc[2 * ib],     qf[kt], bf);
                mma16816(sc[2 * ib + 1], qf[kt], bf + 2);
            }
        }

        // ---- causal mask (last two tiles only) ----
        if (jt >= ntile - 2) {
            const int rl = m0 + w * 16 + (lane >> 2);
            #pragma unroll
            for (int j = 0; j < 8; j++) {
                int gn = jt * 64 + j * 8 + ((lane & 3) << 1);
                if (gn     > rl)     sc[j][0] = -1e30f;
                if (gn + 1 > rl)     sc[j][1] = -1e30f;
                if (gn     > rl + 8) sc[j][2] = -1e30f;
                if (gn + 1 > rl + 8) sc[j][3] = -1e30f;
            }
        }

        // ---- online softmax ----
        float vlo = -1e30f, vhi = -1e30f;
        #pragma unroll
        for (int j = 0; j < 8; j++) {
            vlo = fmaxf(vlo, fmaxf(sc[j][0], sc[j][1]));
            vhi = fmaxf(vhi, fmaxf(sc[j][2], sc[j][3]));
        }
        vlo = fmaxf(vlo, __shfl_xor_sync(0xffffffffu, vlo, 1));
        vlo = fmaxf(vlo, __shfl_xor_sync(0xffffffffu, vlo, 2));
        vhi = fmaxf(vhi, __shfl_xor_sync(0xffffffffu, vhi, 1));
        vhi = fmaxf(vhi, __shfl_xor_sync(0xffffffffu, vhi, 2));
        float mn_lo = fmaxf(m_lo, vlo), mn_hi = fmaxf(m_hi, vhi);
        float al_lo = __expf(m_lo - mn_lo), al_hi = __expf(m_hi - mn_hi);
        m_lo = mn_lo; m_hi = mn_hi;
        l_lo *= al_lo; l_hi *= al_hi;
        #pragma unroll
        for (int n = 0; n < 16; n++) {
            ov[n][0] *= al_lo; ov[n][1] *= al_lo;
            ov[n][2] *= al_hi; ov[n][3] *= al_hi;
        }

        uint32_t ph[8][2], pl[8][2];
        #pragma unroll
        for (int j = 0; j < 8; j++) {
            float p0 = __expf(sc[j][0] - m_lo), p1 = __expf(sc[j][1] - m_lo);
            float p2 = __expf(sc[j][2] - m_hi), p3 = __expf(sc[j][3] - m_hi);
            l_lo += p0 + p1;  l_hi += p2 + p3;
            __nv_bfloat16 h0 = __float2bfloat16(p0), h1 = __float2bfloat16(p1);
            __nv_bfloat16 h2 = __float2bfloat16(p2), h3 = __float2bfloat16(p3);
            ph[j][0] = packbf2(h0, h1);
            ph[j][1] = packbf2(h2, h3);
            pl[j][0] = packbf2(__float2bfloat16(p0 - __bfloat162float(h0)),
                               __float2bfloat16(p1 - __bfloat162float(h1)));
            pl[j][1] = packbf2(__float2bfloat16(p2 - __bfloat162float(h2)),
                               __float2bfloat16(p3 - __bfloat162float(h3)));
        }

        // ---- O += P @ V  (3-term split) ----
        #pragma unroll
        for (int kt = 0; kt < 4; kt++) {
            uint32_t ah[4] = { ph[2*kt][0], ph[2*kt][1], ph[2*kt+1][0], ph[2*kt+1][1] };
            uint32_t am[4] = { pl[2*kt][0], pl[2*kt][1], pl[2*kt+1][0], pl[2*kt+1][1] };
            #pragma unroll
            for (int np = 0; np < 4; np++) {
                uint32_t base = (uint32_t)((kt * 16 + vRow) * AT_RS + np * 64 + vC);
                uint32_t bh0[4], bh1[4], bl0[4], bl1[4];
                ldsm4t(bh0, vhb + base);
                ldsm4t(bh1, vhb + base + 32);
                ldsm4t(bl0, vlb + base);
                ldsm4t(bl1, vlb + base + 32);
                mma16816(ov[np*4+0], ah, bh0);
                mma16816(ov[np*4+1], ah, bh0 + 2);
                mma16816(ov[np*4+2], ah, bh1);
                mma16816(ov[np*4+3], ah, bh1 + 2);
                mma16816(ov[np*4+0], am, bh0);
                mma16816(ov[np*4+1], am, bh0 + 2);
                mma16816(ov[np*4+2], am, bh1);
                mma16816(ov[np*4+3], am, bh1 + 2);
                mma16816(ov[np*4+0], ah, bl0);
                mma16816(ov[np*4+1], ah, bl0 + 2);
                mma16816(ov[np*4+2], ah, bl1);
                mma16816(ov[np*4+3], ah, bl1 + 2);
            }
        }
        // no trailing sync: next iteration's loads target a buffer last read
        // two tiles ago, and the per-tile sync bounds skew to <1 tile.
    }

    // ---- epilogue: normalize, split-bf16, write oh/ol ----
    l_lo += __shfl_xor_sync(0xffffffffu, l_lo, 1);
    l_lo += __shfl_xor_sync(0xffffffffu, l_lo, 2);
    l_hi += __shfl_xor_sync(0xffffffffu, l_hi, 1);
    l_hi += __shfl_xor_sync(0xffffffffu, l_hi, 2);
    const float inv_lo = 0.022097086912079608f / l_lo;
    const float inv_hi = 0.022097086912079608f / l_hi;
    const int rlo = m0 + w * 16 + (lane >> 2);
    size_t base = ((size_t)(b * TT) + rlo) * NE + h * HD;
    #pragma unroll
    for (int n = 0; n < 16; n++) {
        int d = n * 8 + ((lane & 3) << 1);
        float o0 = ov[n][0] * inv_lo, o1 = ov[n][1] * inv_lo;
        float o2 = ov[n][2] * inv_hi, o3 = ov[n][3] * inv_hi;
        __nv_bfloat16 h0 = __float2bfloat16(o0), h1 = __float2bfloat16(o1);
        __nv_bfloat16 h2 = __float2bfloat16(o2), h3 = __float2bfloat16(o3);
        *(uint32_t*)(oh + base + d) = packbf2(h0, h1);
        *(uint32_t*)(ol + base + d) = packbf2(__float2bfloat16(o0 - __bfloat162float(h0)),
                                              __float2bfloat16(o1 - __bfloat162float(h1)));
        *(uint32_t*)(oh + base + 8 * NE + d) = packbf2(h2, h3);
        *(uint32_t*)(ol + base + 8 * NE + d) = packbf2(__float2bfloat16(o2 - __bfloat162float(h2)),
                                                       __float2bfloat16(o3 - __bfloat162float(h3)));
    }
}

// ---------------------------------------------------------------------------
// launch
// ---------------------------------------------------------------------------
extern "C" void kernel_launch(void* const* d_in, const int* in_sizes, int n_in,
                              void* d_out, int out_size)
{
    const float* x  = (const float*)d_in[0];
    const float* Wq = (const float*)d_in[1];
    const float* bq = (const float*)d_in[2];
    const float* Wk = (const float*)d_in[3];
    const float* bk = (const float*)d_in[4];
    const float* Wv = (const float*)d_in[5];
    const float* bv = (const float*)d_in[6];
    const float* Wo = (const float*)d_in[7];
    const float* bo = (const float*)d_in[8];
    float* out = (float*)d_out;

    float *ct, *st;
    __nv_bfloat16 *qr, *kr, *vhp, *vlp;
    __nv_bfloat16 *xh, *xl, *oh, *ol;
    __nv_bfloat16 *wqkvh, *wqkvl, *woh, *wol;
    cudaGetSymbolAddress((void**)&ct, g_cos);
    cudaGetSymbolAddress((void**)&st, g_sin);
    cudaGetSymbolAddress((void**)&qr, g_qr);
    cudaGetSymbolAddress((void**)&kr, g_kr);
    cudaGetSymbolAddress((void**)&vhp, g_vh);
    cudaGetSymbolAddress((void**)&vlp, g_vl);
    cudaGetSymbolAddress((void**)&xh, g_xh);
    cudaGetSymbolAddress((void**)&xl, g_xl);
    cudaGetSymbolAddress((void**)&oh, g_oh);
    cudaGetSymbolAddress((void**)&ol, g_ol);
    cudaGetSymbolAddress((void**)&wqkvh, g_wqkvh);
    cudaGetSymbolAddress((void**)&wqkvl, g_wqkvl);
    cudaGetSymbolAddress((void**)&woh, g_woh);
    cudaGetSymbolAddress((void**)&wol, g_wol);

    cudaFuncSetAttribute(gemm_qkv_kernel, cudaFuncAttributeMaxDynamicSharedMemorySize, GEMM_SMEM);
    cudaFuncSetAttribute(gemm_out_kernel, cudaFuncAttributeMaxDynamicSharedMemorySize, GEMM_SMEM);
    cudaFuncSetAttribute(attn_mma_kernel, cudaFuncAttributeMaxDynamicSharedMemorySize, ATT_SMEM);

    // prep (3 launches)
    tsplit_all_kernel<<<10240, 256>>>(Wq, Wk, Wv, Wo, wqkvh, wqkvl, woh, wol);
    split_kernel<<<(MROWS * NE / 8 + 255) / 256, 256>>>(x, xh, xl, MROWS * NE / 8);
    rope_table_kernel<<<(TT * 64 + 255) / 256, 256>>>(ct, st);

    // fused QKV projection (rope + v-split epilogue)
    gemm_qkv_kernel<<<dim3(NQKV / 128, MROWS / 256), 512, GEMM_SMEM>>>(
        xh, xl, wqkvh, wqkvl, bq, bk, bv, ct, st, qr, kr, vhp, vlp);

    // attention (writes split-bf16 oh/ol)
    {
        dim3 grid(TT / 128, NH, BB);
        attn_mma_kernel<<<grid, 256, ATT_SMEM>>>(qr, kr, vhp, vlp, oh, ol);
    }

    // output projection
    gemm_out_kernel<<<dim3(NE / 128, MROWS / 256), 512, GEMM_SMEM>>>(
        oh, ol, woh, wol, bo, out);
}

// round 12
// speedup vs baseline: 1.6403x; 1.0240x over previous
#include <cuda_runtime.h>
#include <cuda_bf16.h>
#include <cstdint>
#include <cmath>

// ---------------------------------------------------------------------------
// Problem constants (fixed shapes)
// ---------------------------------------------------------------------------
#define BB 2
#define TT 2048
#define NE 2048          // N_EMBED
#define NH 16            // N_HEAD
#define NKV 4            // N_KV_HEAD
#define HD 128           // HEAD_DIM
#define MROWS (BB*TT)    // 4096
#define KVDIM (NKV*HD)   // 512
#define NQKV (NE + 2*KVDIM)   // 3072

// ---------------------------------------------------------------------------
// Scratch (static device globals; no allocations allowed)
// ---------------------------------------------------------------------------
__device__ __nv_bfloat16 g_qr[(size_t)BB * NH * TT * HD];   // rope(q) bf16 [B,H,T,D]
__device__ __nv_bfloat16 g_kr[(size_t)BB * NKV * TT * HD];  // rope(k) bf16 [B,KV,T,D]
__device__ __nv_bfloat16 g_vh[(size_t)BB * NKV * TT * HD];  // v hi bf16 [B,KV,T,D]
__device__ __nv_bfloat16 g_vl[(size_t)BB * NKV * TT * HD];  // v lo bf16 [B,KV,T,D]
__device__ float g_cos[TT * (HD/2)];
__device__ float g_sin[TT * (HD/2)];

// split-bf16 operands for tensor-core GEMMs
__device__ __nv_bfloat16 g_xh[(size_t)MROWS * NE];
__device__ __nv_bfloat16 g_xl[(size_t)MROWS * NE];
__device__ __nv_bfloat16 g_oh[(size_t)MROWS * NE];   // attn out hi
__device__ __nv_bfloat16 g_ol[(size_t)MROWS * NE];   // attn out lo
// packed transposed weights [N][K] hi/lo: rows 0..2047 Wq^T, 2048..2559 Wk^T, 2560..3071 Wv^T
__device__ __nv_bfloat16 g_wqkvh[(size_t)NQKV * NE];
__device__ __nv_bfloat16 g_wqkvl[(size_t)NQKV * NE];
__device__ __nv_bfloat16 g_woh[(size_t)NE * NE];
__device__ __nv_bfloat16 g_wol[(size_t)NE * NE];

// ---------------------------------------------------------------------------
// Helpers (baseline PTX only — no sm_103a-suffixed features)
// ---------------------------------------------------------------------------
__device__ __forceinline__ uint32_t smem_u32(const void* p) {
    uint32_t a;
    asm("{ .reg .u64 t; cvta.to.shared.u64 t, %1; cvt.u32.u64 %0, t; }" : "=r"(a) : "l"(p));
    return a;
}
__device__ __forceinline__ uint32_t sw128(uint32_t off) {
    return off ^ ((off >> 3) & 0x70);
}
__device__ __forceinline__ void cp16(uint32_t dst, const void* src) {
    asm volatile("cp.async.cg.shared.global [%0], [%1], 16;" :: "r"(dst), "l"(src) : "memory");
}
__device__ __forceinline__ void ldsm4(uint32_t* r, uint32_t addr) {
    asm volatile("ldmatrix.sync.aligned.m8n8.x4.shared.b16 {%0,%1,%2,%3}, [%4];"
                 : "=r"(r[0]), "=r"(r[1]), "=r"(r[2]), "=r"(r[3]) : "r"(addr));
}
__device__ __forceinline__ void ldsm4t(uint32_t* r, uint32_t addr) {
    asm volatile("ldmatrix.sync.aligned.m8n8.x4.trans.shared.b16 {%0,%1,%2,%3}, [%4];"
                 : "=r"(r[0]), "=r"(r[1]), "=r"(r[2]), "=r"(r[3]) : "r"(addr));
}
__device__ __forceinline__ void mma16816(float* c, const uint32_t* a, const uint32_t* b) {
    asm volatile(
        "mma.sync.aligned.m16n8k16.row.col.f32.bf16.bf16.f32 "
        "{%0,%1,%2,%3}, {%4,%5,%6,%7}, {%8,%9}, {%0,%1,%2,%3};"
        : "+f"(c[0]), "+f"(c[1]), "+f"(c[2]), "+f"(c[3])
        : "r"(a[0]), "r"(a[1]), "r"(a[2]), "r"(a[3]), "r"(b[0]), "r"(b[1]));
}
// pack two f32 -> bf16x2 (lo -> low half, hi -> high half), round-to-nearest-even
__device__ __forceinline__ uint32_t cvtpack(float lo, float hi) {
    uint32_t r;
    asm("cvt.rn.bf16x2.f32 %0, %1, %2;" : "=r"(r) : "f"(hi), "f"(lo));
    return r;
}
__device__ __forceinline__ float lo_f(uint32_t p) { return __uint_as_float(p << 16); }
__device__ __forceinline__ float hi_f(uint32_t p) { return __uint_as_float(p & 0xffff0000u); }

// ---------------------------------------------------------------------------
// Fused prep kernel: weight transposes+split | x split | rope table
// blocks [0,10240) tsplit, [10240,14336) xsplit, [14336,14848) rope table
// ---------------------------------------------------------------------------
__global__ void __launch_bounds__(256)
prep_kernel(const float* __restrict__ Wq, const float* __restrict__ Wk,
            const float* __restrict__ Wv, const float* __restrict__ Wo,
            const float* __restrict__ x,
            __nv_bfloat16* __restrict__ wqkvh, __nv_bfloat16* __restrict__ wqkvl,
            __nv_bfloat16* __restrict__ woh, __nv_bfloat16* __restrict__ wol,
            __nv_bfloat16* __restrict__ xh, __nv_bfloat16* __restrict__ xl,
            float* __restrict__ ct, float* __restrict__ st)
{
    int bid = blockIdx.x;
    if (bid < 10240) {
        // ---- weight transpose+split ----
        __shared__ float t[32][33];
        int id = bid;
        const float* W;
        __nv_bfloat16 *Th, *Tl;
        int N;
        if (id < 4096)      { W = Wq; Th = wqkvh;                             Tl = wqkvl;                             N = NE;    }
        else if (id < 5120) { W = Wk; Th = wqkvh + (size_t)NE * NE;           Tl = wqkvl + (size_t)NE * NE;           N = KVDIM; id -= 4096; }
        else if (id < 6144) { W = Wv; Th = wqkvh + (size_t)(NE + KVDIM) * NE; Tl = wqkvl + (size_t)(NE + KVDIM) * NE; N = KVDIM; id -= 5120; }
        else                { W = Wo; Th = woh;                               Tl = wol;                               N = NE;    id -= 6144; }
        const int ntiles = N / 32;
        const int n0 = (id % ntiles) * 32;
        const int k0 = (id / ntiles) * 32;
        const int tx = threadIdx.x & 31, ty = threadIdx.x >> 5;
        #pragma unroll
        for (int i = 0; i < 4; i++)
            t[ty + i * 8][tx] = W[(size_t)(k0 + ty + i * 8) * N + n0 + tx];
        __syncthreads();
        #pragma unroll
        for (int i = 0; i < 4; i++) {
            int n = n0 + ty + i * 8, k = k0 + tx;
            float v = t[tx][ty + i * 8];
            __nv_bfloat16 h = __float2bfloat16(v);
            Th[(size_t)n * NE + k] = h;
            Tl[(size_t)n * NE + k] = __float2bfloat16(v - __bfloat162float(h));
        }
    } else if (bid < 14336) {
        // ---- x split ----
        int i = (bid - 10240) * 256 + threadIdx.x;
        size_t base = (size_t)i * 8;
        float4 v0 = *(const float4*)(x + base);
        float4 v1 = *(const float4*)(x + base + 4);
        float vv[8] = {v0.x, v0.y, v0.z, v0.w, v1.x, v1.y, v1.z, v1.w};
        uint4 uh, ul;
        uint32_t* ph = (uint32_t*)&uh;
        uint32_t* pl = (uint32_t*)&ul;
        #pragma unroll
        for (int j = 0; j < 4; j++) {
            uint32_t h = cvtpack(vv[2*j], vv[2*j+1]);
            ph[j] = h;
            pl[j] = cvtpack(vv[2*j] - lo_f(h), vv[2*j+1] - hi_f(h));
        }
        *(uint4*)(xh + base) = uh;
        *(uint4*)(xl + base) = ul;
    } else {
        // ---- rope table ----
        int idx = (bid - 14336) * 256 + threadIdx.x;
        int t = idx >> 6;
        int i = idx & 63;
        double fr = exp(-((double)(2 * i) / (double)NE) * log(10000.0));
        float ff = (float)fr;
        float ang = __fmul_rn((float)t, ff);
        float s, c;
        sincosf(ang, &s, &c);
        ct[idx] = c;
        st[idx] = s;
    }
}

// ---------------------------------------------------------------------------
// GEMM core: split-bf16 C = Ah@Bh^T + Ah@Bl^T + Al@Bh^T
// BM=256, BN=128, BK=64, 512 threads (4m x 4n warps, warp tile 64x32),
// 2-stage cp.async pipeline, ONE __syncthreads per stage. (R11-proven)
// ---------------------------------------------------------------------------
#define STG_BYTES 98304
#define GEMM_SMEM (2*STG_BYTES + 1024)

__device__ __forceinline__ void gemm_core(
    const __nv_bfloat16* __restrict__ Ah, const __nv_bfloat16* __restrict__ Al,
    const __nv_bfloat16* __restrict__ BTh, const __nv_bfloat16* __restrict__ BTl,
    int K, int m0, int n0, uint32_t sb, int tid, float c[4][4][4])
{
    const int lane = tid & 31;
    const int wm   = (tid >> 5) >> 2;
    const int wn   = (tid >> 5) & 3;
    const int nstage = K / 64;

    #pragma unroll
    for (int im = 0; im < 4; im++)
        #pragma unroll
        for (int in = 0; in < 4; in++)
            #pragma unroll
            for (int j = 0; j < 4; j++) c[im][in][j] = 0.f;

    auto load_stage = [&](int s) {
        const int k0 = s * 64;
        const uint32_t stg = sb + (uint32_t)(s & 1) * STG_BYTES;
        #pragma unroll
        for (int i = 0; i < 12; i++) {
            int idx = tid + (i << 9);
            if (idx < 4096) {
                int mat = idx >> 11;
                int row = (idx >> 3) & 255;
                int q   = idx & 7;
                const __nv_bfloat16* src =
                    (mat ? Al : Ah) + (size_t)(m0 + row) * K + k0 + q * 8;
                cp16(stg + mat * 32768 + sw128((uint32_t)(row * 128 + q * 16)), src);
            } else {
                int rel = idx - 4096;
                int mat = rel >> 10;
                int row = (rel >> 3) & 127;
                int q   = rel & 7;
                const __nv_bfloat16* src =
                    (mat ? BTl : BTh) + (size_t)(n0 + row) * K + k0 + q * 8;
                cp16(stg + 65536 + mat * 16384 + sw128((uint32_t)(row * 128 + q * 16)), src);
            }
        }
    };

    load_stage(0);
    asm volatile("cp.async.commit_group;" ::: "memory");

    const int aRow  = (lane & 15);
    const int aKoff = (lane >> 4) << 4;
    const int bRow  = (lane & 7) + ((lane >> 4) << 3);
    const int bKoff = ((lane >> 3) & 1) << 4;

    for (int s = 0; s < nstage; s++) {
        asm volatile("cp.async.wait_group 0;" ::: "memory");
        __syncthreads();
        if (s + 1 < nstage) {
            load_stage(s + 1);
            asm volatile("cp.async.commit_group;" ::: "memory");
        }

        const uint32_t ab = sb + (uint32_t)(s & 1) * STG_BYTES;

        #pragma unroll
        for (int kk = 0; kk < 4; kk++) {
            const int kb = kk * 32;
            uint32_t b_h[8], b_l[8];
            #pragma unroll
            for (int ib = 0; ib < 2; ib++) {
                uint32_t off = sw128((uint32_t)((wn * 32 + ib * 16 + bRow) * 128 + kb + bKoff));
                ldsm4(&b_h[ib * 4], ab + 65536 + off);
                ldsm4(&b_l[ib * 4], ab + 81920 + off);
            }
            #pragma unroll
            for (int im = 0; im < 4; im++) {
                uint32_t a_h[4], a_l[4];
                uint32_t off = sw128((uint32_t)((wm * 64 + im * 16 + aRow) * 128 + kb + aKoff));
                ldsm4(a_h, ab + off);
                ldsm4(a_l, ab + 32768 + off);
                #pragma unroll
                for (int in = 0; in < 4; in++) {
                    const uint32_t* bh = &b_h[(in >> 1) * 4 + (in & 1) * 2];
                    const uint32_t* bl = &b_l[(in >> 1) * 4 + (in & 1) * 2];
                    mma16816(c[im][in], a_h, bh);
                    mma16816(c[im][in], a_l, bh);
                    mma16816(c[im][in], a_h, bl);
                }
            }
        }
    }
    __syncthreads();
}

// ---------------------------------------------------------------------------
// QKV GEMM: fused projections with RoPE / v-split epilogue.
// ---------------------------------------------------------------------------
__global__ void __launch_bounds__(512, 1)
gemm_qkv_kernel(const __nv_bfloat16* __restrict__ Ah, const __nv_bfloat16* __restrict__ Al,
                const __nv_bfloat16* __restrict__ BTh, const __nv_bfloat16* __restrict__ BTl,
                const float* __restrict__ bq, const float* __restrict__ bk,
                const float* __restrict__ bv,
                const float* __restrict__ ct, const float* __restrict__ st,
                __nv_bfloat16* __restrict__ qr, __nv_bfloat16* __restrict__ kr,
                __nv_bfloat16* __restrict__ vh, __nv_bfloat16* __restrict__ vl)
{
    extern __shared__ char dsm[];
    char* smbase = (char*)(((uintptr_t)dsm + 1023) & ~(uintptr_t)1023);
    const uint32_t sb = smem_u32(smbase);
    const int tid  = threadIdx.x;
    const int lane = tid & 31;
    const int wm   = (tid >> 5) >> 2;
    const int wn   = (tid >> 5) & 3;
    const int m0   = blockIdx.y * 256;
    const int n0   = blockIdx.x * 128;

    float c[4][4][4];
    gemm_core(Ah, Al, BTh, BTl, NE, m0, n0, sb, tid, c);

    const int region = (n0 >= NE + KVDIM) ? 2 : (n0 >= NE ? 1 : 0);

    #pragma unroll
    for (int im = 0; im < 4; im++) {
        const int r0 = m0 + wm * 64 + im * 16 + (lane >> 2);
        const int b  = r0 >> 11;
        const int t  = r0 & 2047;
        #pragma unroll
        for (int in = 0; in < 4; in++) {
            const int cc = n0 + wn * 32 + in * 8 + ((lane & 3) << 1);
            float b0, b1;
            if (region == 0)      { b0 = bq[cc];          b1 = bq[cc + 1]; }
            else if (region == 1) { b0 = bk[cc - NE];     b1 = bk[cc - NE + 1]; }
            else                  { b0 = bv[cc - NE - KVDIM]; b1 = bv[cc - NE - KVDIM + 1]; }
            float v0 = c[im][in][0] + b0, v1 = c[im][in][1] + b1;   // row t
            float v2 = c[im][in][2] + b0, v3 = c[im][in][3] + b1;   // row t+8
            const int dloc = cc & 127;
            if (region <= 1) {
                const int i  = dloc >> 1;
                float c0 = ct[t * 64 + i],       s0 = st[t * 64 + i];
                float c2 = ct[(t + 8) * 64 + i], s2 = st[(t + 8) * 64 + i];
                uint32_t p0 = cvtpack(v0 * c0 - v1 * s0, v0 * s0 + v1 * c0);
                uint32_t p2 = cvtpack(v2 * c2 - v3 * s2, v2 * s2 + v3 * c2);
                if (region == 0) {
                    const int h = cc >> 7;
                    size_t dst = ((size_t)((b * NH + h) * TT + t)) * HD + dloc;
                    *(uint32_t*)(qr + dst)          = p0;
                    *(uint32_t*)(qr + dst + 8 * HD) = p2;
                } else {
                    const int h = (cc - NE) >> 7;
                    size_t dst = ((size_t)((b * NKV + h) * TT + t)) * HD + dloc;
                    *(uint32_t*)(kr + dst)          = p0;
                    *(uint32_t*)(kr + dst + 8 * HD) = p2;
                }
            } else {
                const int h = (cc - NE - KVDIM) >> 7;
                size_t dst = ((size_t)((b * NKV + h) * TT + t)) * HD + dloc;
                uint32_t h01 = cvtpack(v0, v1);
                uint32_t h23 = cvtpack(v2, v3);
                *(uint32_t*)(vh + dst)          = h01;
                *(uint32_t*)(vl + dst)          = cvtpack(v0 - lo_f(h01), v1 - hi_f(h01));
                *(uint32_t*)(vh + dst + 8 * HD) = h23;
                *(uint32_t*)(vl + dst + 8 * HD) = cvtpack(v2 - lo_f(h23), v3 - hi_f(h23));
            }
        }
    }
}

// ---------------------------------------------------------------------------
// Output projection GEMM: plain bias epilogue -> fp32 out
// ---------------------------------------------------------------------------
__global__ void __launch_bounds__(512, 1)
gemm_out_kernel(const __nv_bfloat16* __restrict__ Ah, const __nv_bfloat16* __restrict__ Al,
                const __nv_bfloat16* __restrict__ BTh, const __nv_bfloat16* __restrict__ BTl,
                const float* __restrict__ bias, float* __restrict__ C)
{
    extern __shared__ char dsm[];
    char* smbase = (char*)(((uintptr_t)dsm + 1023) & ~(uintptr_t)1023);
    const uint32_t sb = smem_u32(smbase);
    const int tid  = threadIdx.x;
    const int lane = tid & 31;
    const int wm   = (tid >> 5) >> 2;
    const int wn   = (tid >> 5) & 3;
    const int m0   = blockIdx.y * 256;
    const int n0   = blockIdx.x * 128;

    float c[4][4][4];
    gemm_core(Ah, Al, BTh, BTl, NE, m0, n0, sb, tid, c);

    #pragma unroll
    for (int im = 0; im < 4; im++) {
        const int r0 = m0 + wm * 64 + im * 16 + (lane >> 2);
        #pragma unroll
        for (int in = 0; in < 4; in++) {
            const int cc = n0 + wn * 32 + in * 8 + ((lane & 3) << 1);
            float2 bb = *(const float2*)&bias[cc];
            float2 o0, o1;
            o0.x = c[im][in][0] + bb.x;  o0.y = c[im][in][1] + bb.y;
            o1.x = c[im][in][2] + bb.x;  o1.y = c[im][in][3] + bb.y;
            *(float2*)&C[(size_t)r0 * NE + cc]       = o0;
            *(float2*)&C[(size_t)(r0 + 8) * NE + cc] = o1;
        }
    }
}

// ---------------------------------------------------------------------------
// Flash attention (causal, GQA) on mma.sync. BM=64, BN=64, 128 threads/4 warps,
// 2 CTAs/SM (smem ~103KB). Ring-2 K/Vh/Vl buffers, ONE sync per tile,
// prefetch AFTER the sync (race-free with ring-2). Q borrows buf1's K slot
// for the first tile (extracted to regs before tile-1 prefetch).
// Epilogue writes split-bf16 oh/ol directly.
// ---------------------------------------------------------------------------
#define AT_RS 272
#define AT_T64 (64 * AT_RS)
#define ATT_SMEM (6 * AT_T64 + 1024)

__global__ void __launch_bounds__(128, 2)
attn_mma_kernel(const __nv_bfloat16* __restrict__ qr, const __nv_bfloat16* __restrict__ kr,
                const __nv_bfloat16* __restrict__ vh, const __nv_bfloat16* __restrict__ vl,
                __nv_bfloat16* __restrict__ oh, __nv_bfloat16* __restrict__ ol)
{
    extern __shared__ char dsm2[];
    char* smb = (char*)(((uintptr_t)dsm2 + 1023) & ~(uintptr_t)1023);
    const uint32_t sb = smem_u32(smb);

    const int tid  = threadIdx.x;
    const int lane = tid & 31;
    const int w    = tid >> 5;                              // 0..3
    const int mtb  = (int)gridDim.x - 1 - (int)blockIdx.x;  // heavy blocks first
    const int h    = blockIdx.y, b = blockIdx.z;
    const int m0   = mtb * 64;
    const int kv   = h >> 2;
    const int ntile = mtb + 1;

    const __nv_bfloat16* qg  = qr + ((size_t)(b * NH + h) * TT + m0) * HD;
    const __nv_bfloat16* kg  = kr + ((size_t)(b * NKV + kv) * TT) * HD;
    const __nv_bfloat16* vhg = vh + ((size_t)(b * NKV + kv) * TT) * HD;
    const __nv_bfloat16* vlg = vl + ((size_t)(b * NKV + kv) * TT) * HD;

    auto toff = [&](int buf, int which) -> uint32_t {
        return sb + (uint32_t)AT_T64 * (buf * 3 + which);
    };
    const uint32_t Q0 = toff(1, 0);   // Q borrows buf1's K slot initially
    auto load64 = [&](uint32_t dst, const __nv_bfloat16* src) {
        #pragma unroll
        for (int i = 0; i < 8; i++) {
            int idx = tid + i * 128;
            int row = idx >> 4, cq = idx & 15;
            cp16(dst + (uint32_t)(row * AT_RS + cq * 16), src + (size_t)row * HD + cq * 8);
        }
    };

    load64(Q0, qg);
    load64(toff(0, 0), kg);
    load64(toff(0, 1), vhg);
    load64(toff(0, 2), vlg);
    asm volatile("cp.async.commit_group;" ::: "memory");

    uint32_t qf[8][4];
    float ov[16][4];
    #pragma unroll
    for (int n = 0; n < 16; n++) { ov[n][0] = ov[n][1] = ov[n][2] = ov[n][3] = 0.f; }
    float m_lo = -1e30f, m_hi = -1e30f, l_lo = 0.f, l_hi = 0.f;

    const int aRow = lane & 15;
    const int aK   = (lane >> 4) << 4;
    const int bRow = (lane & 7) + ((lane >> 4) << 3);
    const int bK   = ((lane >> 3) & 1) << 4;
    const int vRow = (lane & 7) + (((lane >> 3) & 1) << 3);
    const int vC   = (lane >> 4) << 4;

    for (int jt = 0; jt < ntile; jt++) {
        asm volatile("cp.async.wait_group 0;" ::: "memory");
        __syncthreads();
        if (jt == 0) {
            // extract Q fragments from buf1's K slot, then release it
            #pragma unroll
            for (int kt = 0; kt < 8; kt++)
                ldsm4(qf[kt], Q0 + (uint32_t)((w * 16 + aRow) * AT_RS + kt * 32 + aK));
            __syncthreads();
        }
        if (jt + 1 < ntile) {
            int nb = (jt + 1) & 1;
            load64(toff(nb, 0), kg  + (size_t)(jt + 1) * 64 * HD);
            load64(toff(nb, 1), vhg + (size_t)(jt + 1) * 64 * HD);
            load64(toff(nb, 2), vlg + (size_t)(jt + 1) * 64 * HD);
            asm volatile("cp.async.commit_group;" ::: "memory");
        }

        const int cbuf = jt & 1;
        const uint32_t kb  = toff(cbuf, 0);
        const uint32_t vhb = toff(cbuf, 1);
        const uint32_t vlb = toff(cbuf, 2);

        // ---- S = Q @ K^T ----
        float sc[8][4];
        #pragma unroll
        for (int j = 0; j < 8; j++) { sc[j][0] = sc[j][1] = sc[j][2] = sc[j][3] = 0.f; }

        #pragma unroll
        for (int kt = 0; kt < 8; kt++) {
            #pragma unroll
            for (int ib = 0; ib < 4; ib++) {
                uint32_t bf[4];
                ldsm4(bf, kb + (uint32_t)((ib * 16 + bRow) * AT_RS + kt * 32 + bK));
                mma16816(sc[2 * ib],     qf[kt], bf);
                mma16816(sc[2 * ib + 1], qf[kt], bf + 2);
            }
        }

        // ---- causal mask (diagonal tile only) ----
        if (jt == ntile - 1) {
            const int rl = w * 16 + (lane >> 2);   // row within block
            #pragma unroll
            for (int j = 0; j < 8; j++) {
                int gn = j * 8 + ((lane & 3) << 1);
                if (gn     > rl)     sc[j][0] = -1e30f;
                if (gn + 1 > rl)     sc[j][1] = -1e30f;
                if (gn     > rl + 8) sc[j][2] = -1e30f;
                if (gn + 1 > rl + 8) sc[j][3] = -1e30f;
            }
        }

        // ---- online softmax ----
        float vlo = -1e30f, vhi = -1e30f;
        #pragma unroll
        for (int j = 0; j < 8; j++) {
            vlo = fmaxf(vlo, fmaxf(sc[j][0], sc[j][1]));
            vhi = fmaxf(vhi, fmaxf(sc[j][2], sc[j][3]));
        }
        vlo = fmaxf(vlo, __shfl_xor_sync(0xffffffffu, vlo, 1));
        vlo = fmaxf(vlo, __shfl_xor_sync(0xffffffffu, vlo, 2));
        vhi = fmaxf(vhi, __shfl_xor_sync(0xffffffffu, vhi, 1));
        vhi = fmaxf(vhi, __shfl_xor_sync(0xffffffffu, vhi, 2));
        float mn_lo = fmaxf(m_lo, vlo), mn_hi = fmaxf(m_hi, vhi);
        float al_lo = __expf(m_lo - mn_lo), al_hi = __expf(m_hi - mn_hi);
        m_lo = mn_lo; m_hi = mn_hi;
        l_lo *= al_lo; l_hi *= al_hi;
        #pragma unroll
        for (int n = 0; n < 16; n++) {
            ov[n][0] *= al_lo; ov[n][1] *= al_lo;
            ov[n][2] *= al_hi; ov[n][3] *= al_hi;
        }

        uint32_t ph[8][2], pl[8][2];
        #pragma unroll
        for (int j = 0; j < 8; j++) {
            float p0 = __expf(sc[j][0] - m_lo), p1 = __expf(sc[j][1] - m_lo);
            float p2 = __expf(sc[j][2] - m_hi), p3 = __expf(sc[j][3] - m_hi);
            l_lo += p0 + p1;  l_hi += p2 + p3;
            uint32_t h01 = cvtpack(p0, p1);
            uint32_t h23 = cvtpack(p2, p3);
            ph[j][0] = h01;
            ph[j][1] = h23;
            pl[j][0] = cvtpack(p0 - lo_f(h01), p1 - hi_f(h01));
            pl[j][1] = cvtpack(p2 - lo_f(h23), p3 - hi_f(h23));
        }

        // ---- O += P @ V  (3-term split) ----
        #pragma unroll
        for (int kt = 0; kt < 4; kt++) {
            uint32_t ah[4] = { ph[2*kt][0], ph[2*kt][1], ph[2*kt+1][0], ph[2*kt+1][1] };
            uint32_t am[4] = { pl[2*kt][0], pl[2*kt][1], pl[2*kt+1][0], pl[2*kt+1][1] };
            #pragma unroll
            for (int np = 0; np < 4; np++) {
                uint32_t base = (uint32_t)((kt * 16 + vRow) * AT_RS + np * 64 + vC);
                uint32_t bh0[4], bh1[4], bl0[4], bl1[4];
                ldsm4t(bh0, vhb + base);
                ldsm4t(bh1, vhb + base + 32);
                ldsm4t(bl0, vlb + base);
                ldsm4t(bl1, vlb + base + 32);
                mma16816(ov[np*4+0], ah, bh0);
                mma16816(ov[np*4+1], ah, bh0 + 2);
                mma16816(ov[np*4+2], ah, bh1);
                mma16816(ov[np*4+3], ah, bh1 + 2);
                mma16816(ov[np*4+0], am, bh0);
                mma16816(ov[np*4+1], am, bh0 + 2);
                mma16816(ov[np*4+2], am, bh1);
                mma16816(ov[np*4+3], am, bh1 + 2);
                mma16816(ov[np*4+0], ah, bl0);
                mma16816(ov[np*4+1], ah, bl0 + 2);
                mma16816(ov[np*4+2], ah, bl1);
                mma16816(ov[np*4+3], ah, bl1 + 2);
            }
        }
    }

    // ---- epilogue: normalize, split-bf16, write oh/ol ----
    l_lo += __shfl_xor_sync(0xffffffffu, l_lo, 1);
    l_lo += __shfl_xor_sync(0xffffffffu, l_lo, 2);
    l_hi += __shfl_xor_sync(0xffffffffu, l_hi, 1);
    l_hi += __shfl_xor_sync(0xffffffffu, l_hi, 2);
    const float inv_lo = 0.022097086912079608f / l_lo;
    const float inv_hi = 0.022097086912079608f / l_hi;
    const int rlo = m0 + w * 16 + (lane >> 2);
    size_t base = ((size_t)(b * TT) + rlo) * NE + h * HD;
    #pragma unroll
    for (int n = 0; n < 16; n++) {
        int d = n * 8 + ((lane & 3) << 1);
        float o0 = ov[n][0] * inv_lo, o1 = ov[n][1] * inv_lo;
        float o2 = ov[n][2] * inv_hi, o3 = ov[n][3] * inv_hi;
        uint32_t h01 = cvtpack(o0, o1);
        uint32_t h23 = cvtpack(o2, o3);
        *(uint32_t*)(oh + base + d)          = h01;
        *(uint32_t*)(ol + base + d)          = cvtpack(o0 - lo_f(h01), o1 - hi_f(h01));
        *(uint32_t*)(oh + base + 8 * NE + d) = h23;
        *(uint32_t*)(ol + base + 8 * NE + d) = cvtpack(o2 - lo_f(h23), o3 - hi_f(h23));
    }
}

// ---------------------------------------------------------------------------
// launch
// ---------------------------------------------------------------------------
extern "C" void kernel_launch(void* const* d_in, const int* in_sizes, int n_in,
                              void* d_out, int out_size)
{
    const float* x  = (const float*)d_in[0];
    const float* Wq = (const float*)d_in[1];
    const float* bq = (const float*)d_in[2];
    const float* Wk = (const float*)d_in[3];
    const float* bk = (const float*)d_in[4];
    const float* Wv = (const float*)d_in[5];
    const float* bv = (const float*)d_in[6];
    const float* Wo = (const float*)d_in[7];
    const float* bo = (const float*)d_in[8];
    float* out = (float*)d_out;

    float *ct, *st;
    __nv_bfloat16 *qr, *kr, *vhp, *vlp;
    __nv_bfloat16 *xh, *xl, *oh, *ol;
    __nv_bfloat16 *wqkvh, *wqkvl, *woh, *wol;
    cudaGetSymbolAddress((void**)&ct, g_cos);
    cudaGetSymbolAddress((void**)&st, g_sin);
    cudaGetSymbolAddress((void**)&qr, g_qr);
    cudaGetSymbolAddress((void**)&kr, g_kr);
    cudaGetSymbolAddress((void**)&vhp, g_vh);
    cudaGetSymbolAddress((void**)&vlp, g_vl);
    cudaGetSymbolAddress((void**)&xh, g_xh);
    cudaGetSymbolAddress((void**)&xl, g_xl);
    cudaGetSymbolAddress((void**)&oh, g_oh);
    cudaGetSymbolAddress((void**)&ol, g_ol);
    cudaGetSymbolAddress((void**)&wqkvh, g_wqkvh);
    cudaGetSymbolAddress((void**)&wqkvl, g_wqkvl);
    cudaGetSymbolAddress((void**)&woh, g_woh);
    cudaGetSymbolAddress((void**)&wol, g_wol);

    cudaFuncSetAttribute(gemm_qkv_kernel, cudaFuncAttributeMaxDynamicSharedMemorySize, GEMM_SMEM);
    cudaFuncSetAttribute(gemm_out_kernel, cudaFuncAttributeMaxDynamicSharedMemorySize, GEMM_SMEM);
    cudaFuncSetAttribute(attn_mma_kernel, cudaFuncAttributeMaxDynamicSharedMemorySize, ATT_SMEM);

    // fused prep (1 launch)
    prep_kernel<<<14848, 256>>>(Wq, Wk, Wv, Wo, x, wqkvh, wqkvl, woh, wol, xh, xl, ct, st);

    // fused QKV projection (rope + v-split epilogue)
    gemm_qkv_kernel<<<dim3(NQKV / 128, MROWS / 256), 512, GEMM_SMEM>>>(
        xh, xl, wqkvh, wqkvl, bq, bk, bv, ct, st, qr, kr, vhp, vlp);

    // attention (writes split-bf16 oh/ol); 2 CTAs/SM
    {
        dim3 grid(TT / 64, NH, BB);
        attn_mma_kernel<<<grid, 128, ATT_SMEM>>>(qr, kr, vhp, vlp, oh, ol);
    }

    // output projection
    gemm_out_kernel<<<dim3(NE / 128, MROWS / 256), 512, GEMM_SMEM>>>(
        oh, ol, woh, wol, bo, out);
}

// round 13
// speedup vs baseline: 1.7706x; 1.0795x over previous
#include <cuda_runtime.h>
#include <cuda_bf16.h>
#include <cuda_fp16.h>
#include <cstdint>
#include <cmath>

// ---------------------------------------------------------------------------
// Problem constants (fixed shapes)
// ---------------------------------------------------------------------------
#define BB 2
#define TT 2048
#define NE 2048          // N_EMBED
#define NH 16            // N_HEAD
#define NKV 4            // N_KV_HEAD
#define HD 128           // HEAD_DIM
#define MROWS (BB*TT)    // 4096
#define KVDIM (NKV*HD)   // 512
#define NQKV (NE + 2*KVDIM)   // 3072

// ---------------------------------------------------------------------------
// Scratch (static device globals; no allocations allowed)
// ---------------------------------------------------------------------------
__device__ __nv_bfloat16 g_qr[(size_t)BB * NH * TT * HD];   // rope(q) bf16 [B,H,T,D]
__device__ __nv_bfloat16 g_kr[(size_t)BB * NKV * TT * HD];  // rope(k) bf16 [B,KV,T,D]
__device__ __half        g_v16[(size_t)BB * NKV * TT * HD]; // v fp16 [B,KV,T,D]
__device__ float g_cos[TT * (HD/2)];
__device__ float g_sin[TT * (HD/2)];

// split-bf16 operands for tensor-core GEMMs
__device__ __nv_bfloat16 g_xh[(size_t)MROWS * NE];
__device__ __nv_bfloat16 g_xl[(size_t)MROWS * NE];
__device__ __nv_bfloat16 g_oh[(size_t)MROWS * NE];   // attn out hi
__device__ __nv_bfloat16 g_ol[(size_t)MROWS * NE];   // attn out lo
// packed transposed weights [N][K] hi/lo: rows 0..2047 Wq^T, 2048..2559 Wk^T, 2560..3071 Wv^T
__device__ __nv_bfloat16 g_wqkvh[(size_t)NQKV * NE];
__device__ __nv_bfloat16 g_wqkvl[(size_t)NQKV * NE];
__device__ __nv_bfloat16 g_woh[(size_t)NE * NE];
__device__ __nv_bfloat16 g_wol[(size_t)NE * NE];

// ---------------------------------------------------------------------------
// Helpers (baseline PTX only — no sm_103a-suffixed features)
// ---------------------------------------------------------------------------
__device__ __forceinline__ uint32_t smem_u32(const void* p) {
    uint32_t a;
    asm("{ .reg .u64 t; cvta.to.shared.u64 t, %1; cvt.u32.u64 %0, t; }" : "=r"(a) : "l"(p));
    return a;
}
__device__ __forceinline__ uint32_t sw128(uint32_t off) {
    return off ^ ((off >> 3) & 0x70);
}
__device__ __forceinline__ void cp16(uint32_t dst, const void* src) {
    asm volatile("cp.async.cg.shared.global [%0], [%1], 16;" :: "r"(dst), "l"(src) : "memory");
}
__device__ __forceinline__ void ldsm4(uint32_t* r, uint32_t addr) {
    asm volatile("ldmatrix.sync.aligned.m8n8.x4.shared.b16 {%0,%1,%2,%3}, [%4];"
                 : "=r"(r[0]), "=r"(r[1]), "=r"(r[2]), "=r"(r[3]) : "r"(addr));
}
__device__ __forceinline__ void ldsm4t(uint32_t* r, uint32_t addr) {
    asm volatile("ldmatrix.sync.aligned.m8n8.x4.trans.shared.b16 {%0,%1,%2,%3}, [%4];"
                 : "=r"(r[0]), "=r"(r[1]), "=r"(r[2]), "=r"(r[3]) : "r"(addr));
}
__device__ __forceinline__ void mma16816(float* c, const uint32_t* a, const uint32_t* b) {
    asm volatile(
        "mma.sync.aligned.m16n8k16.row.col.f32.bf16.bf16.f32 "
        "{%0,%1,%2,%3}, {%4,%5,%6,%7}, {%8,%9}, {%0,%1,%2,%3};"
        : "+f"(c[0]), "+f"(c[1]), "+f"(c[2]), "+f"(c[3])
        : "r"(a[0]), "r"(a[1]), "r"(a[2]), "r"(a[3]), "r"(b[0]), "r"(b[1]));
}
__device__ __forceinline__ void mma16816h(float* c, const uint32_t* a, const uint32_t* b) {
    asm volatile(
        "mma.sync.aligned.m16n8k16.row.col.f32.f16.f16.f32 "
        "{%0,%1,%2,%3}, {%4,%5,%6,%7}, {%8,%9}, {%0,%1,%2,%3};"
        : "+f"(c[0]), "+f"(c[1]), "+f"(c[2]), "+f"(c[3])
        : "r"(a[0]), "r"(a[1]), "r"(a[2]), "r"(a[3]), "r"(b[0]), "r"(b[1]));
}
// pack two f32 -> bf16x2 (lo -> low half), round-to-nearest-even
__device__ __forceinline__ uint32_t cvtpack(float lo, float hi) {
    uint32_t r;
    asm("cvt.rn.bf16x2.f32 %0, %1, %2;" : "=r"(r) : "f"(hi), "f"(lo));
    return r;
}
// pack two f32 -> f16x2 (lo -> low half)
__device__ __forceinline__ uint32_t cvtpackh(float lo, float hi) {
    uint32_t r;
    asm("cvt.rn.f16x2.f32 %0, %1, %2;" : "=r"(r) : "f"(hi), "f"(lo));
    return r;
}
__device__ __forceinline__ float lo_f(uint32_t p) { return __uint_as_float(p << 16); }
__device__ __forceinline__ float hi_f(uint32_t p) { return __uint_as_float(p & 0xffff0000u); }

// ---------------------------------------------------------------------------
// Fused prep kernel: weight transposes+split | x split | rope table
// blocks [0,10240) tsplit, [10240,14336) xsplit, [14336,14848) rope table
// ---------------------------------------------------------------------------
__global__ void __launch_bounds__(256)
prep_kernel(const float* __restrict__ Wq, const float* __restrict__ Wk,
            const float* __restrict__ Wv, const float* __restrict__ Wo,
            const float* __restrict__ x,
            __nv_bfloat16* __restrict__ wqkvh, __nv_bfloat16* __restrict__ wqkvl,
            __nv_bfloat16* __restrict__ woh, __nv_bfloat16* __restrict__ wol,
            __nv_bfloat16* __restrict__ xh, __nv_bfloat16* __restrict__ xl,
            float* __restrict__ ct, float* __restrict__ st)
{
    int bid = blockIdx.x;
    if (bid < 10240) {
        __shared__ float t[32][33];
        int id = bid;
        const float* W;
        __nv_bfloat16 *Th, *Tl;
        int N;
        if (id < 4096)      { W = Wq; Th = wqkvh;                             Tl = wqkvl;                             N = NE;    }
        else if (id < 5120) { W = Wk; Th = wqkvh + (size_t)NE * NE;           Tl = wqkvl + (size_t)NE * NE;           N = KVDIM; id -= 4096; }
        else if (id < 6144) { W = Wv; Th = wqkvh + (size_t)(NE + KVDIM) * NE; Tl = wqkvl + (size_t)(NE + KVDIM) * NE; N = KVDIM; id -= 5120; }
        else                { W = Wo; Th = woh;                               Tl = wol;                               N = NE;    id -= 6144; }
        const int ntiles = N / 32;
        const int n0 = (id % ntiles) * 32;
        const int k0 = (id / ntiles) * 32;
        const int tx = threadIdx.x & 31, ty = threadIdx.x >> 5;
        #pragma unroll
        for (int i = 0; i < 4; i++)
            t[ty + i * 8][tx] = W[(size_t)(k0 + ty + i * 8) * N + n0 + tx];
        __syncthreads();
        #pragma unroll
        for (int i = 0; i < 4; i++) {
            int n = n0 + ty + i * 8, k = k0 + tx;
            float v = t[tx][ty + i * 8];
            __nv_bfloat16 h = __float2bfloat16(v);
            Th[(size_t)n * NE + k] = h;
            Tl[(size_t)n * NE + k] = __float2bfloat16(v - __bfloat162float(h));
        }
    } else if (bid < 14336) {
        int i = (bid - 10240) * 256 + threadIdx.x;
        size_t base = (size_t)i * 8;
        float4 v0 = *(const float4*)(x + base);
        float4 v1 = *(const float4*)(x + base + 4);
        float vv[8] = {v0.x, v0.y, v0.z, v0.w, v1.x, v1.y, v1.z, v1.w};
        uint4 uh, ul;
        uint32_t* ph = (uint32_t*)&uh;
        uint32_t* pl = (uint32_t*)&ul;
        #pragma unroll
        for (int j = 0; j < 4; j++) {
            uint32_t h = cvtpack(vv[2*j], vv[2*j+1]);
            ph[j] = h;
            pl[j] = cvtpack(vv[2*j] - lo_f(h), vv[2*j+1] - hi_f(h));
        }
        *(uint4*)(xh + base) = uh;
        *(uint4*)(xl + base) = ul;
    } else {
        int idx = (bid - 14336) * 256 + threadIdx.x;
        int t = idx >> 6;
        int i = idx & 63;
        double fr = exp(-((double)(2 * i) / (double)NE) * log(10000.0));
        float ff = (float)fr;
        float ang = __fmul_rn((float)t, ff);
        float s, c;
        sincosf(ang, &s, &c);
        ct[idx] = c;
        st[idx] = s;
    }
}

// ---------------------------------------------------------------------------
// GEMM core: split-bf16 C = Ah@Bh^T + Ah@Bl^T + Al@Bh^T
// BM=256, BN=128, BK=64, 512 threads (4m x 4n warps, warp tile 64x32),
// 2-stage cp.async pipeline, ONE __syncthreads per stage. (R11-proven)
// ---------------------------------------------------------------------------
#define STG_BYTES 98304
#define GEMM_SMEM (2*STG_BYTES + 1024)

__device__ __forceinline__ void gemm_core(
    const __nv_bfloat16* __restrict__ Ah, const __nv_bfloat16* __restrict__ Al,
    const __nv_bfloat16* __restrict__ BTh, const __nv_bfloat16* __restrict__ BTl,
    int K, int m0, int n0, uint32_t sb, int tid, float c[4][4][4])
{
    const int lane = tid & 31;
    const int wm   = (tid >> 5) >> 2;
    const int wn   = (tid >> 5) & 3;
    const int nstage = K / 64;

    #pragma unroll
    for (int im = 0; im < 4; im++)
        #pragma unroll
        for (int in = 0; in < 4; in++)
            #pragma unroll
            for (int j = 0; j < 4; j++) c[im][in][j] = 0.f;

    auto load_stage = [&](int s) {
        const int k0 = s * 64;
        const uint32_t stg = sb + (uint32_t)(s & 1) * STG_BYTES;
        #pragma unroll
        for (int i = 0; i < 12; i++) {
            int idx = tid + (i << 9);
            if (idx < 4096) {
                int mat = idx >> 11;
                int row = (idx >> 3) & 255;
                int q   = idx & 7;
                const __nv_bfloat16* src =
                    (mat ? Al : Ah) + (size_t)(m0 + row) * K + k0 + q * 8;
                cp16(stg + mat * 32768 + sw128((uint32_t)(row * 128 + q * 16)), src);
            } else {
                int rel = idx - 4096;
                int mat = rel >> 10;
                int row = (rel >> 3) & 127;
                int q   = rel & 7;
                const __nv_bfloat16* src =
                    (mat ? BTl : BTh) + (size_t)(n0 + row) * K + k0 + q * 8;
                cp16(stg + 65536 + mat * 16384 + sw128((uint32_t)(row * 128 + q * 16)), src);
            }
        }
    };

    load_stage(0);
    asm volatile("cp.async.commit_group;" ::: "memory");

    const int aRow  = (lane & 15);
    const int aKoff = (lane >> 4) << 4;
    const int bRow  = (lane & 7) + ((lane >> 4) << 3);
    const int bKoff = ((lane >> 3) & 1) << 4;

    for (int s = 0; s < nstage; s++) {
        asm volatile("cp.async.wait_group 0;" ::: "memory");
        __syncthreads();
        if (s + 1 < nstage) {
            load_stage(s + 1);
            asm volatile("cp.async.commit_group;" ::: "memory");
        }

        const uint32_t ab = sb + (uint32_t)(s & 1) * STG_BYTES;

        #pragma unroll
        for (int kk = 0; kk < 4; kk++) {
            const int kb = kk * 32;
            uint32_t b_h[8], b_l[8];
            #pragma unroll
            for (int ib = 0; ib < 2; ib++) {
                uint32_t off = sw128((uint32_t)((wn * 32 + ib * 16 + bRow) * 128 + kb + bKoff));
                ldsm4(&b_h[ib * 4], ab + 65536 + off);
                ldsm4(&b_l[ib * 4], ab + 81920 + off);
            }
            #pragma unroll
            for (int im = 0; im < 4; im++) {
                uint32_t a_h[4], a_l[4];
                uint32_t off = sw128((uint32_t)((wm * 64 + im * 16 + aRow) * 128 + kb + aKoff));
                ldsm4(a_h, ab + off);
                ldsm4(a_l, ab + 32768 + off);
                #pragma unroll
                for (int in = 0; in < 4; in++) {
                    const uint32_t* bh = &b_h[(in >> 1) * 4 + (in & 1) * 2];
                    const uint32_t* bl = &b_l[(in >> 1) * 4 + (in & 1) * 2];
                    mma16816(c[im][in], a_h, bh);
                    mma16816(c[im][in], a_l, bh);
                    mma16816(c[im][in], a_h, bl);
                }
            }
        }
    }
    __syncthreads();
}

// ---------------------------------------------------------------------------
// QKV GEMM: fused projections with RoPE epilogue; V written as fp16.
// ---------------------------------------------------------------------------
__global__ void __launch_bounds__(512, 1)
gemm_qkv_kernel(const __nv_bfloat16* __restrict__ Ah, const __nv_bfloat16* __restrict__ Al,
                const __nv_bfloat16* __restrict__ BTh, const __nv_bfloat16* __restrict__ BTl,
                const float* __restrict__ bq, const float* __restrict__ bk,
                const float* __restrict__ bv,
                const float* __restrict__ ct, const float* __restrict__ st,
                __nv_bfloat16* __restrict__ qr, __nv_bfloat16* __restrict__ kr,
                __half* __restrict__ v16)
{
    extern __shared__ char dsm[];
    char* smbase = (char*)(((uintptr_t)dsm + 1023) & ~(uintptr_t)1023);
    const uint32_t sb = smem_u32(smbase);
    const int tid  = threadIdx.x;
    const int lane = tid & 31;
    const int wm   = (tid >> 5) >> 2;
    const int wn   = (tid >> 5) & 3;
    const int m0   = blockIdx.y * 256;
    const int n0   = blockIdx.x * 128;

    float c[4][4][4];
    gemm_core(Ah, Al, BTh, BTl, NE, m0, n0, sb, tid, c);

    const int region = (n0 >= NE + KVDIM) ? 2 : (n0 >= NE ? 1 : 0);

    #pragma unroll
    for (int im = 0; im < 4; im++) {
        const int r0 = m0 + wm * 64 + im * 16 + (lane >> 2);
        const int b  = r0 >> 11;
        const int t  = r0 & 2047;
        #pragma unroll
        for (int in = 0; in < 4; in++) {
            const int cc = n0 + wn * 32 + in * 8 + ((lane & 3) << 1);
            float b0, b1;
            if (region == 0)      { b0 = bq[cc];          b1 = bq[cc + 1]; }
            else if (region == 1) { b0 = bk[cc - NE];     b1 = bk[cc - NE + 1]; }
            else                  { b0 = bv[cc - NE - KVDIM]; b1 = bv[cc - NE - KVDIM + 1]; }
            float v0 = c[im][in][0] + b0, v1 = c[im][in][1] + b1;   // row t
            float v2 = c[im][in][2] + b0, v3 = c[im][in][3] + b1;   // row t+8
            const int dloc = cc & 127;
            if (region <= 1) {
                const int i  = dloc >> 1;
                float c0 = ct[t * 64 + i],       s0 = st[t * 64 + i];
                float c2 = ct[(t + 8) * 64 + i], s2 = st[(t + 8) * 64 + i];
                uint32_t p0 = cvtpack(v0 * c0 - v1 * s0, v0 * s0 + v1 * c0);
                uint32_t p2 = cvtpack(v2 * c2 - v3 * s2, v2 * s2 + v3 * c2);
                if (region == 0) {
                    const int h = cc >> 7;
                    size_t dst = ((size_t)((b * NH + h) * TT + t)) * HD + dloc;
                    *(uint32_t*)(qr + dst)          = p0;
                    *(uint32_t*)(qr + dst + 8 * HD) = p2;
                } else {
                    const int h = (cc - NE) >> 7;
                    size_t dst = ((size_t)((b * NKV + h) * TT + t)) * HD + dloc;
                    *(uint32_t*)(kr + dst)          = p0;
                    *(uint32_t*)(kr + dst + 8 * HD) = p2;
                }
            } else {
                const int h = (cc - NE - KVDIM) >> 7;
                size_t dst = ((size_t)((b * NKV + h) * TT + t)) * HD + dloc;
                *(uint32_t*)(v16 + dst)          = cvtpackh(v0, v1);
                *(uint32_t*)(v16 + dst + 8 * HD) = cvtpackh(v2, v3);
            }
        }
    }
}

// ---------------------------------------------------------------------------
// Output projection GEMM: plain bias epilogue -> fp32 out
// ---------------------------------------------------------------------------
__global__ void __launch_bounds__(512, 1)
gemm_out_kernel(const __nv_bfloat16* __restrict__ Ah, const __nv_bfloat16* __restrict__ Al,
                const __nv_bfloat16* __restrict__ BTh, const __nv_bfloat16* __restrict__ BTl,
                const float* __restrict__ bias, float* __restrict__ C)
{
    extern __shared__ char dsm[];
    char* smbase = (char*)(((uintptr_t)dsm + 1023) & ~(uintptr_t)1023);
    const uint32_t sb = smem_u32(smbase);
    const int tid  = threadIdx.x;
    const int lane = tid & 31;
    const int wm   = (tid >> 5) >> 2;
    const int wn   = (tid >> 5) & 3;
    const int m0   = blockIdx.y * 256;
    const int n0   = blockIdx.x * 128;

    float c[4][4][4];
    gemm_core(Ah, Al, BTh, BTl, NE, m0, n0, sb, tid, c);

    #pragma unroll
    for (int im = 0; im < 4; im++) {
        const int r0 = m0 + wm * 64 + im * 16 + (lane >> 2);
        #pragma unroll
        for (int in = 0; in < 4; in++) {
            const int cc = n0 + wn * 32 + in * 8 + ((lane & 3) << 1);
            float2 bb = *(const float2*)&bias[cc];
            float2 o0, o1;
            o0.x = c[im][in][0] + bb.x;  o0.y = c[im][in][1] + bb.y;
            o1.x = c[im][in][2] + bb.x;  o1.y = c[im][in][3] + bb.y;
            *(float2*)&C[(size_t)r0 * NE + cc]       = o0;
            *(float2*)&C[(size_t)(r0 + 8) * NE + cc] = o1;
        }
    }
}

// ---------------------------------------------------------------------------
// Flash attention (causal, GQA). S=QK^T on bf16 mma (reference-exact);
// AV on fp16 P x fp16 V single term. BM=64, BN=64, 128 threads/4 warps,
// 3 CTAs/SM (smem ~70KB). Ring-2 {K,V} buffers, ONE sync per tile,
// prefetch AFTER the sync. Q borrows buf1's K slot for tile 0.
// Epilogue writes split-bf16 oh/ol (feeds O-projection).
// ---------------------------------------------------------------------------
#define AT_RS 272
#define AT_T64 (64 * AT_RS)
#define ATT_SMEM (4 * AT_T64 + 1024)

__global__ void __launch_bounds__(128, 3)
attn_mma_kernel(const __nv_bfloat16* __restrict__ qr, const __nv_bfloat16* __restrict__ kr,
                const __half* __restrict__ v16,
                __nv_bfloat16* __restrict__ oh, __nv_bfloat16* __restrict__ ol)
{
    extern __shared__ char dsm2[];
    char* smb = (char*)(((uintptr_t)dsm2 + 1023) & ~(uintptr_t)1023);
    const uint32_t sb = smem_u32(smb);

    const int tid  = threadIdx.x;
    const int lane = tid & 31;
    const int w    = tid >> 5;                              // 0..3
    const int mtb  = (int)gridDim.x - 1 - (int)blockIdx.x;  // heavy blocks first
    const int h    = blockIdx.y, b = blockIdx.z;
    const int m0   = mtb * 64;
    const int kv   = h >> 2;
    const int ntile = mtb + 1;

    const __nv_bfloat16* qg = qr  + ((size_t)(b * NH + h) * TT + m0) * HD;
    const __nv_bfloat16* kg = kr  + ((size_t)(b * NKV + kv) * TT) * HD;
    const __half*        vg = v16 + ((size_t)(b * NKV + kv) * TT) * HD;

    // buffers: buf0 {K@0, V@1}, buf1 {K@2, V@3}; Q borrows slot 2 initially
    auto toff = [&](int buf, int which) -> uint32_t {
        return sb + (uint32_t)AT_T64 * (buf * 2 + which);
    };
    const uint32_t Q0 = toff(1, 0);
    auto load64 = [&](uint32_t dst, const void* srcbase, int tile) {
        const char* src = (const char*)srcbase + (size_t)tile * 64 * HD * 2;
        #pragma unroll
        for (int i = 0; i < 8; i++) {
            int idx = tid + i * 128;
            int row = idx >> 4, cq = idx & 15;
            cp16(dst + (uint32_t)(row * AT_RS + cq * 16), src + (size_t)row * HD * 2 + cq * 16);
        }
    };

    load64(Q0, qg, 0);
    load64(toff(0, 0), kg, 0);
    load64(toff(0, 1), vg, 0);
    asm volatile("cp.async.commit_group;" ::: "memory");

    uint32_t qf[8][4];
    float ov[16][4];
    #pragma unroll
    for (int n = 0; n < 16; n++) { ov[n][0] = ov[n][1] = ov[n][2] = ov[n][3] = 0.f; }
    float m_lo = -1e30f, m_hi = -1e30f, l_lo = 0.f, l_hi = 0.f;

    const int aRow = lane & 15;
    const int aK   = (lane >> 4) << 4;
    const int bRow = (lane & 7) + ((lane >> 4) << 3);
    const int bK   = ((lane >> 3) & 1) << 4;
    const int vRow = (lane & 7) + (((lane >> 3) & 1) << 3);
    const int vC   = (lane >> 4) << 4;

    for (int jt = 0; jt < ntile; jt++) {
        asm volatile("cp.async.wait_group 0;" ::: "memory");
        __syncthreads();
        if (jt == 0) {
            // extract Q fragments from buf1's K slot, then release it
            #pragma unroll
            for (int kt = 0; kt < 8; kt++)
                ldsm4(qf[kt], Q0 + (uint32_t)((w * 16 + aRow) * AT_RS + kt * 32 + aK));
            __syncthreads();
        }
        if (jt + 1 < ntile) {
            int nb = (jt + 1) & 1;
            load64(toff(nb, 0), kg, jt + 1);
            load64(toff(nb, 1), vg, jt + 1);
            asm volatile("cp.async.commit_group;" ::: "memory");
        }

        const int cbuf = jt & 1;
        const uint32_t kb = toff(cbuf, 0);
        const uint32_t vb = toff(cbuf, 1);

        // ---- S = Q @ K^T (bf16, reference-exact inputs) ----
        float sc[8][4];
        #pragma unroll
        for (int j = 0; j < 8; j++) { sc[j][0] = sc[j][1] = sc[j][2] = sc[j][3] = 0.f; }

        #pragma unroll
        for (int kt = 0; kt < 8; kt++) {
            #pragma unroll
            for (int ib = 0; ib < 4; ib++) {
                uint32_t bf[4];
                ldsm4(bf, kb + (uint32_t)((ib * 16 + bRow) * AT_RS + kt * 32 + bK));
                mma16816(sc[2 * ib],     qf[kt], bf);
                mma16816(sc[2 * ib + 1], qf[kt], bf + 2);
            }
        }

        // ---- causal mask (diagonal tile only) ----
        if (jt == ntile - 1) {
            const int rl = w * 16 + (lane >> 2);
            #pragma unroll
            for (int j = 0; j < 8; j++) {
                int gn = j * 8 + ((lane & 3) << 1);
                if (gn     > rl)     sc[j][0] = -1e30f;
                if (gn + 1 > rl)     sc[j][1] = -1e30f;
                if (gn     > rl + 8) sc[j][2] = -1e30f;
                if (gn + 1 > rl + 8) sc[j][3] = -1e30f;
            }
        }

        // ---- online softmax ----
        float vlo = -1e30f, vhi = -1e30f;
        #pragma unroll
        for (int j = 0; j < 8; j++) {
            vlo = fmaxf(vlo, fmaxf(sc[j][0], sc[j][1]));
            vhi = fmaxf(vhi, fmaxf(sc[j][2], sc[j][3]));
        }
        vlo = fmaxf(vlo, __shfl_xor_sync(0xffffffffu, vlo, 1));
        vlo = fmaxf(vlo, __shfl_xor_sync(0xffffffffu, vlo, 2));
        vhi = fmaxf(vhi, __shfl_xor_sync(0xffffffffu, vhi, 1));
        vhi = fmaxf(vhi, __shfl_xor_sync(0xffffffffu, vhi, 2));
        float mn_lo = fmaxf(m_lo, vlo), mn_hi = fmaxf(m_hi, vhi);
        float al_lo = __expf(m_lo - mn_lo), al_hi = __expf(m_hi - mn_hi);
        m_lo = mn_lo; m_hi = mn_hi;
        l_lo *= al_lo; l_hi *= al_hi;
        #pragma unroll
        for (int n = 0; n < 16; n++) {
            ov[n][0] *= al_lo; ov[n][1] *= al_lo;
            ov[n][2] *= al_hi; ov[n][3] *= al_hi;
        }

        uint32_t ph[8][2];
        #pragma unroll
        for (int j = 0; j < 8; j++) {
            float p0 = __expf(sc[j][0] - m_lo), p1 = __expf(sc[j][1] - m_lo);
            float p2 = __expf(sc[j][2] - m_hi), p3 = __expf(sc[j][3] - m_hi);
            l_lo += p0 + p1;  l_hi += p2 + p3;
            ph[j][0] = cvtpackh(p0, p1);
            ph[j][1] = cvtpackh(p2, p3);
        }

        // ---- O += P @ V  (fp16 x fp16, single term) ----
        #pragma unroll
        for (int kt = 0; kt < 4; kt++) {
            uint32_t ah[4] = { ph[2*kt][0], ph[2*kt][1], ph[2*kt+1][0], ph[2*kt+1][1] };
            #pragma unroll
            for (int np = 0; np < 4; np++) {
                uint32_t base = (uint32_t)((kt * 16 + vRow) * AT_RS + np * 64 + vC);
                uint32_t bh0[4], bh1[4];
                ldsm4t(bh0, vb + base);
                ldsm4t(bh1, vb + base + 32);
                mma16816h(ov[np*4+0], ah, bh0);
                mma16816h(ov[np*4+1], ah, bh0 + 2);
                mma16816h(ov[np*4+2], ah, bh1);
                mma16816h(ov[np*4+3], ah, bh1 + 2);
            }
        }
    }

    // ---- epilogue: normalize, split-bf16, write oh/ol ----
    l_lo += __shfl_xor_sync(0xffffffffu, l_lo, 1);
    l_lo += __shfl_xor_sync(0xffffffffu, l_lo, 2);
    l_hi += __shfl_xor_sync(0xffffffffu, l_hi, 1);
    l_hi += __shfl_xor_sync(0xffffffffu, l_hi, 2);
    const float inv_lo = 0.022097086912079608f / l_lo;
    const float inv_hi = 0.022097086912079608f / l_hi;
    const int rlo = m0 + w * 16 + (lane >> 2);
    size_t base = ((size_t)(b * TT) + rlo) * NE + h * HD;
    #pragma unroll
    for (int n = 0; n < 16; n++) {
        int d = n * 8 + ((lane & 3) << 1);
        float o0 = ov[n][0] * inv_lo, o1 = ov[n][1] * inv_lo;
        float o2 = ov[n][2] * inv_hi, o3 = ov[n][3] * inv_hi;
        uint32_t h01 = cvtpack(o0, o1);
        uint32_t h23 = cvtpack(o2, o3);
        *(uint32_t*)(oh + base + d)          = h01;
        *(uint32_t*)(ol + base + d)          = cvtpack(o0 - lo_f(h01), o1 - hi_f(h01));
        *(uint32_t*)(oh + base + 8 * NE + d) = h23;
        *(uint32_t*)(ol + base + 8 * NE + d) = cvtpack(o2 - lo_f(h23), o3 - hi_f(h23));
    }
}

// ---------------------------------------------------------------------------
// launch
// ---------------------------------------------------------------------------
extern "C" void kernel_launch(void* const* d_in, const int* in_sizes, int n_in,
                              void* d_out, int out_size)
{
    const float* x  = (const float*)d_in[0];
    const float* Wq = (const float*)d_in[1];
    const float* bq = (const float*)d_in[2];
    const float* Wk = (const float*)d_in[3];
    const float* bk = (const float*)d_in[4];
    const float* Wv = (const float*)d_in[5];
    const float* bv = (const float*)d_in[6];
    const float* Wo = (const float*)d_in[7];
    const float* bo = (const float*)d_in[8];
    float* out = (float*)d_out;

    float *ct, *st;
    __nv_bfloat16 *qr, *kr;
    __half *v16;
    __nv_bfloat16 *xh, *xl, *oh, *ol;
    __nv_bfloat16 *wqkvh, *wqkvl, *woh, *wol;
    cudaGetSymbolAddress((void**)&ct, g_cos);
    cudaGetSymbolAddress((void**)&st, g_sin);
    cudaGetSymbolAddress((void**)&qr, g_qr);
    cudaGetSymbolAddress((void**)&kr, g_kr);
    cudaGetSymbolAddress((void**)&v16, g_v16);
    cudaGetSymbolAddress((void**)&xh, g_xh);
    cudaGetSymbolAddress((void**)&xl, g_xl);
    cudaGetSymbolAddress((void**)&oh, g_oh);
    cudaGetSymbolAddress((void**)&ol, g_ol);
    cudaGetSymbolAddress((void**)&wqkvh, g_wqkvh);
    cudaGetSymbolAddress((void**)&wqkvl, g_wqkvl);
    cudaGetSymbolAddress((void**)&woh, g_woh);
    cudaGetSymbolAddress((void**)&wol, g_wol);

    cudaFuncSetAttribute(gemm_qkv_kernel, cudaFuncAttributeMaxDynamicSharedMemorySize, GEMM_SMEM);
    cudaFuncSetAttribute(gemm_out_kernel, cudaFuncAttributeMaxDynamicSharedMemorySize, GEMM_SMEM);
    cudaFuncSetAttribute(attn_mma_kernel, cudaFuncAttributeMaxDynamicSharedMemorySize, ATT_SMEM);

    // fused prep (1 launch)
    prep_kernel<<<14848, 256>>>(Wq, Wk, Wv, Wo, x, wqkvh, wqkvl, woh, wol, xh, xl, ct, st);

    // fused QKV projection (rope epilogue; V -> fp16)
    gemm_qkv_kernel<<<dim3(NQKV / 128, MROWS / 256), 512, GEMM_SMEM>>>(
        xh, xl, wqkvh, wqkvl, bq, bk, bv, ct, st, qr, kr, v16);

    // attention (writes split-bf16 oh/ol); 3 CTAs/SM
    {
        dim3 grid(TT / 64, NH, BB);
        attn_mma_kernel<<<grid, 128, ATT_SMEM>>>(qr, kr, v16, oh, ol);
    }

    // output projection
    gemm_out_kernel<<<dim3(NE / 128, MROWS / 256), 512, GEMM_SMEM>>>(
        oh, ol, woh, wol, bo, out);
}

// round 14
// speedup vs baseline: 2.1846x; 1.2338x over previous
#include <cuda_runtime.h>
#include <cuda_bf16.h>
#include <cuda_fp16.h>
#include <cstdint>
#include <cmath>

// ---------------------------------------------------------------------------
// Problem constants (fixed shapes)
// ---------------------------------------------------------------------------
#define BB 2
#define TT 2048
#define NE 2048          // N_EMBED
#define NH 16            // N_HEAD
#define NKV 4            // N_KV_HEAD
#define HD 128           // HEAD_DIM
#define MROWS (BB*TT)    // 4096
#define KVDIM (NKV*HD)   // 512
#define NQKV (NE + 2*KVDIM)   // 3072

// ---------------------------------------------------------------------------
// Scratch (static device globals; no allocations allowed)
// ---------------------------------------------------------------------------
__device__ __nv_bfloat16 g_qr[(size_t)BB * NH * TT * HD];   // rope(q) bf16 [B,H,T,D]
__device__ __nv_bfloat16 g_kr[(size_t)BB * NKV * TT * HD];  // rope(k) bf16 [B,KV,T,D]
__device__ __half        g_v16[(size_t)BB * NKV * TT * HD]; // v fp16 [B,KV,T,D]
__device__ __half        g_o16[(size_t)MROWS * NE];         // attn out fp16
__device__ float g_cos[TT * (HD/2)];
__device__ float g_sin[TT * (HD/2)];

// split-bf16 operands for QKV tensor-core GEMM
__device__ __nv_bfloat16 g_xh[(size_t)MROWS * NE];
__device__ __nv_bfloat16 g_xl[(size_t)MROWS * NE];
// packed transposed weights [N][K] hi/lo: rows 0..2047 Wq^T, 2048..2559 Wk^T, 2560..3071 Wv^T
__device__ __nv_bfloat16 g_wqkvh[(size_t)NQKV * NE];
__device__ __nv_bfloat16 g_wqkvl[(size_t)NQKV * NE];
__device__ __half        g_wo16[(size_t)NE * NE];           // Wo^T fp16 [N][K]

// ---------------------------------------------------------------------------
// Helpers (baseline PTX only — no sm_103a-suffixed features)
// ---------------------------------------------------------------------------
__device__ __forceinline__ uint32_t smem_u32(const void* p) {
    uint32_t a;
    asm("{ .reg .u64 t; cvta.to.shared.u64 t, %1; cvt.u32.u64 %0, t; }" : "=r"(a) : "l"(p));
    return a;
}
__device__ __forceinline__ uint32_t sw128(uint32_t off) {
    return off ^ ((off >> 3) & 0x70);
}
__device__ __forceinline__ void cp16(uint32_t dst, const void* src) {
    asm volatile("cp.async.cg.shared.global [%0], [%1], 16;" :: "r"(dst), "l"(src) : "memory");
}
__device__ __forceinline__ void ldsm4(uint32_t* r, uint32_t addr) {
    asm volatile("ldmatrix.sync.aligned.m8n8.x4.shared.b16 {%0,%1,%2,%3}, [%4];"
                 : "=r"(r[0]), "=r"(r[1]), "=r"(r[2]), "=r"(r[3]) : "r"(addr));
}
__device__ __forceinline__ void ldsm4t(uint32_t* r, uint32_t addr) {
    asm volatile("ldmatrix.sync.aligned.m8n8.x4.trans.shared.b16 {%0,%1,%2,%3}, [%4];"
                 : "=r"(r[0]), "=r"(r[1]), "=r"(r[2]), "=r"(r[3]) : "r"(addr));
}
__device__ __forceinline__ void mma16816(float* c, const uint32_t* a, const uint32_t* b) {
    asm volatile(
        "mma.sync.aligned.m16n8k16.row.col.f32.bf16.bf16.f32 "
        "{%0,%1,%2,%3}, {%4,%5,%6,%7}, {%8,%9}, {%0,%1,%2,%3};"
        : "+f"(c[0]), "+f"(c[1]), "+f"(c[2]), "+f"(c[3])
        : "r"(a[0]), "r"(a[1]), "r"(a[2]), "r"(a[3]), "r"(b[0]), "r"(b[1]));
}
__device__ __forceinline__ void mma16816h(float* c, const uint32_t* a, const uint32_t* b) {
    asm volatile(
        "mma.sync.aligned.m16n8k16.row.col.f32.f16.f16.f32 "
        "{%0,%1,%2,%3}, {%4,%5,%6,%7}, {%8,%9}, {%0,%1,%2,%3};"
        : "+f"(c[0]), "+f"(c[1]), "+f"(c[2]), "+f"(c[3])
        : "r"(a[0]), "r"(a[1]), "r"(a[2]), "r"(a[3]), "r"(b[0]), "r"(b[1]));
}
// pack two f32 -> bf16x2 (lo -> low half), round-to-nearest-even
__device__ __forceinline__ uint32_t cvtpack(float lo, float hi) {
    uint32_t r;
    asm("cvt.rn.bf16x2.f32 %0, %1, %2;" : "=r"(r) : "f"(hi), "f"(lo));
    return r;
}
// pack two f32 -> f16x2 (lo -> low half)
__device__ __forceinline__ uint32_t cvtpackh(float lo, float hi) {
    uint32_t r;
    asm("cvt.rn.f16x2.f32 %0, %1, %2;" : "=r"(r) : "f"(hi), "f"(lo));
    return r;
}
__device__ __forceinline__ float lo_f(uint32_t p) { return __uint_as_float(p << 16); }
__device__ __forceinline__ float hi_f(uint32_t p) { return __uint_as_float(p & 0xffff0000u); }

// ---------------------------------------------------------------------------
// Fused prep kernel:
// blocks [0,6144)      QKV weight transposes + bf16 hi/lo split
//        [6144,10240)  Wo transpose -> fp16
//        [10240,14336) x split
//        [14336,14848) rope table
// ---------------------------------------------------------------------------
__global__ void __launch_bounds__(256)
prep_kernel(const float* __restrict__ Wq, const float* __restrict__ Wk,
            const float* __restrict__ Wv, const float* __restrict__ Wo,
            const float* __restrict__ x,
            __nv_bfloat16* __restrict__ wqkvh, __nv_bfloat16* __restrict__ wqkvl,
            __half* __restrict__ wo16,
            __nv_bfloat16* __restrict__ xh, __nv_bfloat16* __restrict__ xl,
            float* __restrict__ ct, float* __restrict__ st)
{
    int bid = blockIdx.x;
    if (bid < 6144) {
        __shared__ float t[32][33];
        int id = bid;
        const float* W;
        __nv_bfloat16 *Th, *Tl;
        int N;
        if (id < 4096)      { W = Wq; Th = wqkvh;                             Tl = wqkvl;                             N = NE;    }
        else if (id < 5120) { W = Wk; Th = wqkvh + (size_t)NE * NE;           Tl = wqkvl + (size_t)NE * NE;           N = KVDIM; id -= 4096; }
        else                { W = Wv; Th = wqkvh + (size_t)(NE + KVDIM) * NE; Tl = wqkvl + (size_t)(NE + KVDIM) * NE; N = KVDIM; id -= 5120; }
        const int ntiles = N / 32;
        const int n0 = (id % ntiles) * 32;
        const int k0 = (id / ntiles) * 32;
        const int tx = threadIdx.x & 31, ty = threadIdx.x >> 5;
        #pragma unroll
        for (int i = 0; i < 4; i++)
            t[ty + i * 8][tx] = W[(size_t)(k0 + ty + i * 8) * N + n0 + tx];
        __syncthreads();
        #pragma unroll
        for (int i = 0; i < 4; i++) {
            int n = n0 + ty + i * 8, k = k0 + tx;
            float v = t[tx][ty + i * 8];
            __nv_bfloat16 h = __float2bfloat16(v);
            Th[(size_t)n * NE + k] = h;
            Tl[(size_t)n * NE + k] = __float2bfloat16(v - __bfloat162float(h));
        }
    } else if (bid < 10240) {
        // Wo transpose -> fp16
        __shared__ float t[32][33];
        int id = bid - 6144;
        const int n0 = (id & 63) * 32;      // 2048/32 = 64 tiles per row
        const int k0 = (id >> 6) * 32;
        const int tx = threadIdx.x & 31, ty = threadIdx.x >> 5;
        #pragma unroll
        for (int i = 0; i < 4; i++)
            t[ty + i * 8][tx] = Wo[(size_t)(k0 + ty + i * 8) * NE + n0 + tx];
        __syncthreads();
        #pragma unroll
        for (int i = 0; i < 4; i++) {
            int n = n0 + ty + i * 8, k = k0 + tx;
            wo16[(size_t)n * NE + k] = __float2half(t[tx][ty + i * 8]);
        }
    } else if (bid < 14336) {
        int i = (bid - 10240) * 256 + threadIdx.x;
        size_t base = (size_t)i * 8;
        float4 v0 = *(const float4*)(x + base);
        float4 v1 = *(const float4*)(x + base + 4);
        float vv[8] = {v0.x, v0.y, v0.z, v0.w, v1.x, v1.y, v1.z, v1.w};
        uint4 uh, ul;
        uint32_t* ph = (uint32_t*)&uh;
        uint32_t* pl = (uint32_t*)&ul;
        #pragma unroll
        for (int j = 0; j < 4; j++) {
            uint32_t h = cvtpack(vv[2*j], vv[2*j+1]);
            ph[j] = h;
            pl[j] = cvtpack(vv[2*j] - lo_f(h), vv[2*j+1] - hi_f(h));
        }
        *(uint4*)(xh + base) = uh;
        *(uint4*)(xl + base) = ul;
    } else {
        int idx = (bid - 14336) * 256 + threadIdx.x;
        int t = idx >> 6;
        int i = idx & 63;
        double fr = exp(-((double)(2 * i) / (double)NE) * log(10000.0));
        float ff = (float)fr;
        float ang = __fmul_rn((float)t, ff);
        float s, c;
        sincosf(ang, &s, &c);
        ct[idx] = c;
        st[idx] = s;
    }
}

// ---------------------------------------------------------------------------
// QKV GEMM core: split-bf16 C = Ah@Bh^T + Ah@Bl^T + Al@Bh^T
// BM=256, BN=128, BK=64, 512 threads (4m x 4n warps, warp tile 64x32),
// 2-stage cp.async pipeline, ONE __syncthreads per stage. (R11-proven)
// ---------------------------------------------------------------------------
#define STG_BYTES 98304
#define GEMM_SMEM (2*STG_BYTES + 1024)

__device__ __forceinline__ void gemm_core(
    const __nv_bfloat16* __restrict__ Ah, const __nv_bfloat16* __restrict__ Al,
    const __nv_bfloat16* __restrict__ BTh, const __nv_bfloat16* __restrict__ BTl,
    int K, int m0, int n0, uint32_t sb, int tid, float c[4][4][4])
{
    const int lane = tid & 31;
    const int wm   = (tid >> 5) >> 2;
    const int wn   = (tid >> 5) & 3;
    const int nstage = K / 64;

    #pragma unroll
    for (int im = 0; im < 4; im++)
        #pragma unroll
        for (int in = 0; in < 4; in++)
            #pragma unroll
            for (int j = 0; j < 4; j++) c[im][in][j] = 0.f;

    auto load_stage = [&](int s) {
        const int k0 = s * 64;
        const uint32_t stg = sb + (uint32_t)(s & 1) * STG_BYTES;
        #pragma unroll
        for (int i = 0; i < 12; i++) {
            int idx = tid + (i << 9);
            if (idx < 4096) {
                int mat = idx >> 11;
                int row = (idx >> 3) & 255;
                int q   = idx & 7;
                const __nv_bfloat16* src =
                    (mat ? Al : Ah) + (size_t)(m0 + row) * K + k0 + q * 8;
                cp16(stg + mat * 32768 + sw128((uint32_t)(row * 128 + q * 16)), src);
            } else {
                int rel = idx - 4096;
                int mat = rel >> 10;
                int row = (rel >> 3) & 127;
                int q   = rel & 7;
                const __nv_bfloat16* src =
                    (mat ? BTl : BTh) + (size_t)(n0 + row) * K + k0 + q * 8;
                cp16(stg + 65536 + mat * 16384 + sw128((uint32_t)(row * 128 + q * 16)), src);
            }
        }
    };

    load_stage(0);
    asm volatile("cp.async.commit_group;" ::: "memory");

    const int aRow  = (lane & 15);
    const int aKoff = (lane >> 4) << 4;
    const int bRow  = (lane & 7) + ((lane >> 4) << 3);
    const int bKoff = ((lane >> 3) & 1) << 4;

    for (int s = 0; s < nstage; s++) {
        asm volatile("cp.async.wait_group 0;" ::: "memory");
        __syncthreads();
        if (s + 1 < nstage) {
            load_stage(s + 1);
            asm volatile("cp.async.commit_group;" ::: "memory");
        }

        const uint32_t ab = sb + (uint32_t)(s & 1) * STG_BYTES;

        #pragma unroll
        for (int kk = 0; kk < 4; kk++) {
            const int kb = kk * 32;
            uint32_t b_h[8], b_l[8];
            #pragma unroll
            for (int ib = 0; ib < 2; ib++) {
                uint32_t off = sw128((uint32_t)((wn * 32 + ib * 16 + bRow) * 128 + kb + bKoff));
                ldsm4(&b_h[ib * 4], ab + 65536 + off);
                ldsm4(&b_l[ib * 4], ab + 81920 + off);
            }
            #pragma unroll
            for (int im = 0; im < 4; im++) {
                uint32_t a_h[4], a_l[4];
                uint32_t off = sw128((uint32_t)((wm * 64 + im * 16 + aRow) * 128 + kb + aKoff));
                ldsm4(a_h, ab + off);
                ldsm4(a_l, ab + 32768 + off);
                #pragma unroll
                for (int in = 0; in < 4; in++) {
                    const uint32_t* bh = &b_h[(in >> 1) * 4 + (in & 1) * 2];
                    const uint32_t* bl = &b_l[(in >> 1) * 4 + (in & 1) * 2];
                    mma16816(c[im][in], a_h, bh);
                    mma16816(c[im][in], a_l, bh);
                    mma16816(c[im][in], a_h, bl);
                }
            }
        }
    }
    __syncthreads();
}

// ---------------------------------------------------------------------------
// QKV GEMM: fused projections with RoPE epilogue; V written as fp16.
// ---------------------------------------------------------------------------
__global__ void __launch_bounds__(512, 1)
gemm_qkv_kernel(const __nv_bfloat16* __restrict__ Ah, const __nv_bfloat16* __restrict__ Al,
                const __nv_bfloat16* __restrict__ BTh, const __nv_bfloat16* __restrict__ BTl,
                const float* __restrict__ bq, const float* __restrict__ bk,
                const float* __restrict__ bv,
                const float* __restrict__ ct, const float* __restrict__ st,
                __nv_bfloat16* __restrict__ qr, __nv_bfloat16* __restrict__ kr,
                __half* __restrict__ v16)
{
    extern __shared__ char dsm[];
    char* smbase = (char*)(((uintptr_t)dsm + 1023) & ~(uintptr_t)1023);
    const uint32_t sb = smem_u32(smbase);
    const int tid  = threadIdx.x;
    const int lane = tid & 31;
    const int wm   = (tid >> 5) >> 2;
    const int wn   = (tid >> 5) & 3;
    const int m0   = blockIdx.y * 256;
    const int n0   = blockIdx.x * 128;

    float c[4][4][4];
    gemm_core(Ah, Al, BTh, BTl, NE, m0, n0, sb, tid, c);

    const int region = (n0 >= NE + KVDIM) ? 2 : (n0 >= NE ? 1 : 0);

    #pragma unroll
    for (int im = 0; im < 4; im++) {
        const int r0 = m0 + wm * 64 + im * 16 + (lane >> 2);
        const int b  = r0 >> 11;
        const int t  = r0 & 2047;
        #pragma unroll
        for (int in = 0; in < 4; in++) {
            const int cc = n0 + wn * 32 + in * 8 + ((lane & 3) << 1);
            float b0, b1;
            if (region == 0)      { b0 = bq[cc];          b1 = bq[cc + 1]; }
            else if (region == 1) { b0 = bk[cc - NE];     b1 = bk[cc - NE + 1]; }
            else                  { b0 = bv[cc - NE - KVDIM]; b1 = bv[cc - NE - KVDIM + 1]; }
            float v0 = c[im][in][0] + b0, v1 = c[im][in][1] + b1;   // row t
            float v2 = c[im][in][2] + b0, v3 = c[im][in][3] + b1;   // row t+8
            const int dloc = cc & 127;
            if (region <= 1) {
                const int i  = dloc >> 1;
                float c0 = ct[t * 64 + i],       s0 = st[t * 64 + i];
                float c2 = ct[(t + 8) * 64 + i], s2 = st[(t + 8) * 64 + i];
                uint32_t p0 = cvtpack(v0 * c0 - v1 * s0, v0 * s0 + v1 * c0);
                uint32_t p2 = cvtpack(v2 * c2 - v3 * s2, v2 * s2 + v3 * c2);
                if (region == 0) {
                    const int h = cc >> 7;
                    size_t dst = ((size_t)((b * NH + h) * TT + t)) * HD + dloc;
                    *(uint32_t*)(qr + dst)          = p0;
                    *(uint32_t*)(qr + dst + 8 * HD) = p2;
                } else {
                    const int h = (cc - NE) >> 7;
                    size_t dst = ((size_t)((b * NKV + h) * TT + t)) * HD + dloc;
                    *(uint32_t*)(kr + dst)          = p0;
                    *(uint32_t*)(kr + dst + 8 * HD) = p2;
                }
            } else {
                const int h = (cc - NE - KVDIM) >> 7;
                size_t dst = ((size_t)((b * NKV + h) * TT + t)) * HD + dloc;
                *(uint32_t*)(v16 + dst)          = cvtpackh(v0, v1);
                *(uint32_t*)(v16 + dst + 8 * HD) = cvtpackh(v2, v3);
            }
        }
    }
}

// ---------------------------------------------------------------------------
// Output projection GEMM: fp16 x fp16 single-term (+bias) -> fp32 out
// BM=256, BN=128, BK=64, 512 threads, warp tile 64x32, 2-stage cp.async.
// Stage: A 32KB @0 | B 16KB @32K  (rows 128B, SW128)
// ---------------------------------------------------------------------------
#define OSTG_BYTES 49152
#define GEMMO_SMEM (2*OSTG_BYTES + 1024)

__global__ void __launch_bounds__(512, 1)
gemm_out_kernel(const __half* __restrict__ A, const __half* __restrict__ BT,
                const float* __restrict__ bias, float* __restrict__ C)
{
    extern __shared__ char dsm[];
    char* smbase = (char*)(((uintptr_t)dsm + 1023) & ~(uintptr_t)1023);
    const uint32_t sb = smem_u32(smbase);
    const int tid  = threadIdx.x;
    const int lane = tid & 31;
    const int wm   = (tid >> 5) >> 2;
    const int wn   = (tid >> 5) & 3;
    const int m0   = blockIdx.y * 256;
    const int n0   = blockIdx.x * 128;
    const int nstage = NE / 64;

    float c[4][4][4];
    #pragma unroll
    for (int im = 0; im < 4; im++)
        #pragma unroll
        for (int in = 0; in < 4; in++)
            #pragma unroll
            for (int j = 0; j < 4; j++) c[im][in][j] = 0.f;

    auto load_stage = [&](int s) {
        const int k0 = s * 64;
        const uint32_t stg = sb + (uint32_t)(s & 1) * OSTG_BYTES;
        #pragma unroll
        for (int i = 0; i < 6; i++) {
            int idx = tid + (i << 9);           // 0..3071
            if (idx < 2048) {
                int row = idx >> 3;
                int q   = idx & 7;
                cp16(stg + sw128((uint32_t)(row * 128 + q * 16)),
                     A + (size_t)(m0 + row) * NE + k0 + q * 8);
            } else {
                int rel = idx - 2048;
                int row = rel >> 3;
                int q   = rel & 7;
                cp16(stg + 32768 + sw128((uint32_t)(row * 128 + q * 16)),
                     BT + (size_t)(n0 + row) * NE + k0 + q * 8);
            }
        }
    };

    load_stage(0);
    asm volatile("cp.async.commit_group;" ::: "memory");

    const int aRow  = (lane & 15);
    const int aKoff = (lane >> 4) << 4;
    const int bRow  = (lane & 7) + ((lane >> 4) << 3);
    const int bKoff = ((lane >> 3) & 1) << 4;

    for (int s = 0; s < nstage; s++) {
        asm volatile("cp.async.wait_group 0;" ::: "memory");
        __syncthreads();
        if (s + 1 < nstage) {
            load_stage(s + 1);
            asm volatile("cp.async.commit_group;" ::: "memory");
        }

        const uint32_t ab = sb + (uint32_t)(s & 1) * OSTG_BYTES;

        #pragma unroll
        for (int kk = 0; kk < 4; kk++) {
            const int kb = kk * 32;
            uint32_t b_f[8];
            #pragma unroll
            for (int ib = 0; ib < 2; ib++) {
                uint32_t off = sw128((uint32_t)((wn * 32 + ib * 16 + bRow) * 128 + kb + bKoff));
                ldsm4(&b_f[ib * 4], ab + 32768 + off);
            }
            #pragma unroll
            for (int im = 0; im < 4; im++) {
                uint32_t a_f[4];
                uint32_t off = sw128((uint32_t)((wm * 64 + im * 16 + aRow) * 128 + kb + aKoff));
                ldsm4(a_f, ab + off);
                #pragma unroll
                for (int in = 0; in < 4; in++)
                    mma16816h(c[im][in], a_f, &b_f[(in >> 1) * 4 + (in & 1) * 2]);
            }
        }
    }

    #pragma unroll
    for (int im = 0; im < 4; im++) {
        const int r0 = m0 + wm * 64 + im * 16 + (lane >> 2);
        #pragma unroll
        for (int in = 0; in < 4; in++) {
            const int cc = n0 + wn * 32 + in * 8 + ((lane & 3) << 1);
            float2 bb = *(const float2*)&bias[cc];
            float2 o0, o1;
            o0.x = c[im][in][0] + bb.x;  o0.y = c[im][in][1] + bb.y;
            o1.x = c[im][in][2] + bb.x;  o1.y = c[im][in][3] + bb.y;
            *(float2*)&C[(size_t)r0 * NE + cc]       = o0;
            *(float2*)&C[(size_t)(r0 + 8) * NE + cc] = o1;
        }
    }
}

// ---------------------------------------------------------------------------
// Flash attention (causal, GQA). S=QK^T on bf16 mma (reference-exact);
// AV on fp16 P x fp16 V single term. BM=64, BN=64, 128 threads/4 warps,
// 3 CTAs/SM. Ring-2 {K,V} buffers, ONE sync per tile, prefetch AFTER sync.
// Q borrows buf1's K slot for tile 0. Epilogue writes fp16 o16.
// ---------------------------------------------------------------------------
#define AT_RS 272
#define AT_T64 (64 * AT_RS)
#define ATT_SMEM (4 * AT_T64 + 1024)

__global__ void __launch_bounds__(128, 3)
attn_mma_kernel(const __nv_bfloat16* __restrict__ qr, const __nv_bfloat16* __restrict__ kr,
                const __half* __restrict__ v16, __half* __restrict__ o16)
{
    extern __shared__ char dsm2[];
    char* smb = (char*)(((uintptr_t)dsm2 + 1023) & ~(uintptr_t)1023);
    const uint32_t sb = smem_u32(smb);

    const int tid  = threadIdx.x;
    const int lane = tid & 31;
    const int w    = tid >> 5;                              // 0..3
    const int mtb  = (int)gridDim.x - 1 - (int)blockIdx.x;  // heavy blocks first
    const int h    = blockIdx.y, b = blockIdx.z;
    const int m0   = mtb * 64;
    const int kv   = h >> 2;
    const int ntile = mtb + 1;

    const __nv_bfloat16* qg = qr  + ((size_t)(b * NH + h) * TT + m0) * HD;
    const __nv_bfloat16* kg = kr  + ((size_t)(b * NKV + kv) * TT) * HD;
    const __half*        vg = v16 + ((size_t)(b * NKV + kv) * TT) * HD;

    auto toff = [&](int buf, int which) -> uint32_t {
        return sb + (uint32_t)AT_T64 * (buf * 2 + which);
    };
    const uint32_t Q0 = toff(1, 0);
    auto load64 = [&](uint32_t dst, const void* srcbase, int tile) {
        const char* src = (const char*)srcbase + (size_t)tile * 64 * HD * 2;
        #pragma unroll
        for (int i = 0; i < 8; i++) {
            int idx = tid + i * 128;
            int row = idx >> 4, cq = idx & 15;
            cp16(dst + (uint32_t)(row * AT_RS + cq * 16), src + (size_t)row * HD * 2 + cq * 16);
        }
    };

    load64(Q0, qg, 0);
    load64(toff(0, 0), kg, 0);
    load64(toff(0, 1), vg, 0);
    asm volatile("cp.async.commit_group;" ::: "memory");

    uint32_t qf[8][4];
    float ov[16][4];
    #pragma unroll
    for (int n = 0; n < 16; n++) { ov[n][0] = ov[n][1] = ov[n][2] = ov[n][3] = 0.f; }
    float m_lo = -1e30f, m_hi = -1e30f, l_lo = 0.f, l_hi = 0.f;

    const int aRow = lane & 15;
    const int aK   = (lane >> 4) << 4;
    const int bRow = (lane & 7) + ((lane >> 4) << 3);
    const int bK   = ((lane >> 3) & 1) << 4;
    const int vRow = (lane & 7) + (((lane >> 3) & 1) << 3);
    const int vC   = (lane >> 4) << 4;

    for (int jt = 0; jt < ntile; jt++) {
        asm volatile("cp.async.wait_group 0;" ::: "memory");
        __syncthreads();
        if (jt == 0) {
            #pragma unroll
            for (int kt = 0; kt < 8; kt++)
                ldsm4(qf[kt], Q0 + (uint32_t)((w * 16 + aRow) * AT_RS + kt * 32 + aK));
            __syncthreads();
        }
        if (jt + 1 < ntile) {
            int nb = (jt + 1) & 1;
            load64(toff(nb, 0), kg, jt + 1);
            load64(toff(nb, 1), vg, jt + 1);
            asm volatile("cp.async.commit_group;" ::: "memory");
        }

        const int cbuf = jt & 1;
        const uint32_t kb = toff(cbuf, 0);
        const uint32_t vb = toff(cbuf, 1);

        // ---- S = Q @ K^T (bf16, reference-exact inputs) ----
        float sc[8][4];
        #pragma unroll
        for (int j = 0; j < 8; j++) { sc[j][0] = sc[j][1] = sc[j][2] = sc[j][3] = 0.f; }

        #pragma unroll
        for (int kt = 0; kt < 8; kt++) {
            #pragma unroll
            for (int ib = 0; ib < 4; ib++) {
                uint32_t bf[4];
                ldsm4(bf, kb + (uint32_t)((ib * 16 + bRow) * AT_RS + kt * 32 + bK));
                mma16816(sc[2 * ib],     qf[kt], bf);
                mma16816(sc[2 * ib + 1], qf[kt], bf + 2);
            }
        }

        // ---- causal mask (diagonal tile only) ----
        if (jt == ntile - 1) {
            const int rl = w * 16 + (lane >> 2);
            #pragma unroll
            for (int j = 0; j < 8; j++) {
                int gn = j * 8 + ((lane & 3) << 1);
                if (gn     > rl)     sc[j][0] = -1e30f;
                if (gn + 1 > rl)     sc[j][1] = -1e30f;
                if (gn     > rl + 8) sc[j][2] = -1e30f;
                if (gn + 1 > rl + 8) sc[j][3] = -1e30f;
            }
        }

        // ---- online softmax ----
        float vlo = -1e30f, vhi = -1e30f;
        #pragma unroll
        for (int j = 0; j < 8; j++) {
            vlo = fmaxf(vlo, fmaxf(sc[j][0], sc[j][1]));
            vhi = fmaxf(vhi, fmaxf(sc[j][2], sc[j][3]));
        }
        vlo = fmaxf(vlo, __shfl_xor_sync(0xffffffffu, vlo, 1));
        vlo = fmaxf(vlo, __shfl_xor_sync(0xffffffffu, vlo, 2));
        vhi = fmaxf(vhi, __shfl_xor_sync(0xffffffffu, vhi, 1));
        vhi = fmaxf(vhi, __shfl_xor_sync(0xffffffffu, vhi, 2));
        float mn_lo = fmaxf(m_lo, vlo), mn_hi = fmaxf(m_hi, vhi);
        float al_lo = __expf(m_lo - mn_lo), al_hi = __expf(m_hi - mn_hi);
        m_lo = mn_lo; m_hi = mn_hi;
        l_lo *= al_lo; l_hi *= al_hi;
        #pragma unroll
        for (int n = 0; n < 16; n++) {
            ov[n][0] *= al_lo; ov[n][1] *= al_lo;
            ov[n][2] *= al_hi; ov[n][3] *= al_hi;
        }

        uint32_t ph[8][2];
        #pragma unroll
        for (int j = 0; j < 8; j++) {
            float p0 = __expf(sc[j][0] - m_lo), p1 = __expf(sc[j][1] - m_lo);
            float p2 = __expf(sc[j][2] - m_hi), p3 = __expf(sc[j][3] - m_hi);
            l_lo += p0 + p1;  l_hi += p2 + p3;
            ph[j][0] = cvtpackh(p0, p1);
            ph[j][1] = cvtpackh(p2, p3);
        }

        // ---- O += P @ V  (fp16 x fp16, single term) ----
        #pragma unroll
        for (int kt = 0; kt < 4; kt++) {
            uint32_t ah[4] = { ph[2*kt][0], ph[2*kt][1], ph[2*kt+1][0], ph[2*kt+1][1] };
            #pragma unroll
            for (int np = 0; np < 4; np++) {
                uint32_t base = (uint32_t)((kt * 16 + vRow) * AT_RS + np * 64 + vC);
                uint32_t bh0[4], bh1[4];
                ldsm4t(bh0, vb + base);
                ldsm4t(bh1, vb + base + 32);
                mma16816h(ov[np*4+0], ah, bh0);
                mma16816h(ov[np*4+1], ah, bh0 + 2);
                mma16816h(ov[np*4+2], ah, bh1);
                mma16816h(ov[np*4+3], ah, bh1 + 2);
            }
        }
    }

    // ---- epilogue: normalize, write fp16 o16 ----
    l_lo += __shfl_xor_sync(0xffffffffu, l_lo, 1);
    l_lo += __shfl_xor_sync(0xffffffffu, l_lo, 2);
    l_hi += __shfl_xor_sync(0xffffffffu, l_hi, 1);
    l_hi += __shfl_xor_sync(0xffffffffu, l_hi, 2);
    const float inv_lo = 0.022097086912079608f / l_lo;
    const float inv_hi = 0.022097086912079608f / l_hi;
    const int rlo = m0 + w * 16 + (lane >> 2);
    size_t base = ((size_t)(b * TT) + rlo) * NE + h * HD;
    #pragma unroll
    for (int n = 0; n < 16; n++) {
        int d = n * 8 + ((lane & 3) << 1);
        *(uint32_t*)(o16 + base + d)          = cvtpackh(ov[n][0] * inv_lo, ov[n][1] * inv_lo);
        *(uint32_t*)(o16 + base + 8 * NE + d) = cvtpackh(ov[n][2] * inv_hi, ov[n][3] * inv_hi);
    }
}

// ---------------------------------------------------------------------------
// launch
// ---------------------------------------------------------------------------
extern "C" void kernel_launch(void* const* d_in, const int* in_sizes, int n_in,
                              void* d_out, int out_size)
{
    const float* x  = (const float*)d_in[0];
    const float* Wq = (const float*)d_in[1];
    const float* bq = (const float*)d_in[2];
    const float* Wk = (const float*)d_in[3];
    const float* bk = (const float*)d_in[4];
    const float* Wv = (const float*)d_in[5];
    const float* bv = (const float*)d_in[6];
    const float* Wo = (const float*)d_in[7];
    const float* bo = (const float*)d_in[8];
    float* out = (float*)d_out;

    float *ct, *st;
    __nv_bfloat16 *qr, *kr;
    __half *v16, *o16, *wo16;
    __nv_bfloat16 *xh, *xl;
    __nv_bfloat16 *wqkvh, *wqkvl;
    cudaGetSymbolAddress((void**)&ct, g_cos);
    cudaGetSymbolAddress((void**)&st, g_sin);
    cudaGetSymbolAddress((void**)&qr, g_qr);
    cudaGetSymbolAddress((void**)&kr, g_kr);
    cudaGetSymbolAddress((void**)&v16, g_v16);
    cudaGetSymbolAddress((void**)&o16, g_o16);
    cudaGetSymbolAddress((void**)&xh, g_xh);
    cudaGetSymbolAddress((void**)&xl, g_xl);
    cudaGetSymbolAddress((void**)&wqkvh, g_wqkvh);
    cudaGetSymbolAddress((void**)&wqkvl, g_wqkvl);
    cudaGetSymbolAddress((void**)&wo16, g_wo16);

    cudaFuncSetAttribute(gemm_qkv_kernel, cudaFuncAttributeMaxDynamicSharedMemorySize, GEMM_SMEM);
    cudaFuncSetAttribute(gemm_out_kernel, cudaFuncAttributeMaxDynamicSharedMemorySize, GEMMO_SMEM);
    cudaFuncSetAttribute(attn_mma_kernel, cudaFuncAttributeMaxDynamicSharedMemorySize, ATT_SMEM);

    // fused prep (1 launch)
    prep_kernel<<<14848, 256>>>(Wq, Wk, Wv, Wo, x, wqkvh, wqkvl, wo16, xh, xl, ct, st);

    // fused QKV projection (rope epilogue; V -> fp16)
    gemm_qkv_kernel<<<dim3(NQKV / 128, MROWS / 256), 512, GEMM_SMEM>>>(
        xh, xl, wqkvh, wqkvl, bq, bk, bv, ct, st, qr, kr, v16);

    // attention (writes fp16 o16); 3 CTAs/SM
    {
        dim3 grid(TT / 64, NH, BB);
        attn_mma_kernel<<<grid, 128, ATT_SMEM>>>(qr, kr, v16, o16);
    }

    // output projection: fp16 single-term
    gemm_out_kernel<<<dim3(NE / 128, MROWS / 256), 512, GEMMO_SMEM>>>(
        o16, wo16, bo, out);
}